// round 4
// baseline (speedup 1.0000x reference)
#include <cuda_runtime.h>
#include <math.h>

#define BB 16
#define CC 128
#define HW 16384
#define KS1 8
#define KSEG (HW / KS1)   // 2048
#define CHK 32
#define NCH (KSEG / CHK)  // 64

__device__ float g_energy[BB * CC * CC];
__device__ float g_epart[BB * KS1 * CC * CC];
__device__ float g_attn[BB * CC * CC];
__device__ float g_rowsum[BB * CC];
__device__ float g_scale[CC];
__device__ float g_shift[CC];

typedef unsigned long long u64;

__device__ __forceinline__ u64 fma2(u64 a, u64 b, u64 c) {
    u64 d;
    asm("fma.rn.f32x2 %0, %1, %2, %3;" : "=l"(d) : "l"(a), "l"(b), "l"(c));
    return d;
}
__device__ __forceinline__ u64 pack2(float x, float y) {
    u64 d;
    asm("mov.b64 %0, {%1, %2};" : "=l"(d) : "f"(x), "f"(y));
    return d;
}
__device__ __forceinline__ float2 unpack2(u64 v) {
    float2 r;
    asm("mov.b64 {%0, %1}, %2;" : "=f"(r.x), "=f"(r.y) : "l"(v));
    return r;
}

// ---- 1. rowsum_q[b][j] = sum_n q[b][j][n] ----
__global__ void k_rowsum(const float* __restrict__ x) {
    int j = blockIdx.x, b = blockIdx.y, t = threadIdx.x;
    const float4* p = (const float4*)(x + ((size_t)(b * CC + j)) * HW);
    float s = 0.f;
    #pragma unroll 4
    for (int i = t; i < HW / 4; i += 256) {
        float4 v = p[i];
        s += (v.x + v.y) + (v.z + v.w);
    }
    __shared__ float red[256];
    red[t] = s;
    __syncthreads();
    for (int w = 128; w > 0; w >>= 1) {
        if (t < w) red[t] += red[t + w];
        __syncthreads();
    }
    if (t == 0) g_rowsum[b * CC + j] = red[0];
}

// ---- 2. energy partials: 64x64 tile, K-segment of 2048, f32x2 over k ----
__global__ void __launch_bounds__(128) k_energy(const float* __restrict__ x) {
    int ks = blockIdx.x;
    int it = blockIdx.y >> 1, jt = blockIdx.y & 1;
    int b = blockIdx.z;
    int t = threadIdx.x;
    int tx = t & 15, ty = t >> 4;  // 16 x 8 threads; per-thread tile 8(m) x 4(n)

    __shared__ __align__(16) float2 sA[CHK / 2][64];
    __shared__ __align__(16) float2 sB[CHK / 2][64];

    const float* qb = x + (size_t)b * CC * HW;
    const float* Abase = qb + (size_t)(it * 64) * HW + ks * KSEG;
    const float* Bbase = qb + (size_t)(jt * 64) * HW + ks * KSEG;

    u64 acc[8][4];
    #pragma unroll
    for (int m = 0; m < 8; m++)
        #pragma unroll
        for (int n = 0; n < 4; n++) acc[m][n] = 0ULL;

    for (int ch = 0; ch < NCH; ch++) {
        int k0 = ch * CHK;
        #pragma unroll
        for (int i = 0; i < 4; i++) {
            int idx = t + 128 * i;
            int row = idx >> 3, kq = idx & 7;
            float4 va = *(const float4*)(Abase + (size_t)row * HW + k0 + kq * 4);
            sA[kq * 2][row] = make_float2(va.x, va.y);
            sA[kq * 2 + 1][row] = make_float2(va.z, va.w);
            float4 vb = *(const float4*)(Bbase + (size_t)row * HW + k0 + kq * 4);
            sB[kq * 2][row] = make_float2(vb.x, vb.y);
            sB[kq * 2 + 1][row] = make_float2(vb.z, vb.w);
        }
        __syncthreads();
        #pragma unroll
        for (int kp = 0; kp < CHK / 2; kp++) {
            const ulonglong2* ap = (const ulonglong2*)&sA[kp][ty * 8];
            ulonglong2 a01 = ap[0], a23 = ap[1], a45 = ap[2], a67 = ap[3];
            u64 A[8] = {a01.x, a01.y, a23.x, a23.y, a45.x, a45.y, a67.x, a67.y};
            const ulonglong2* bp = (const ulonglong2*)&sB[kp][tx * 4];
            ulonglong2 b01 = bp[0], b23 = bp[1];
            u64 Bv[4] = {b01.x, b01.y, b23.x, b23.y};
            #pragma unroll
            for (int m = 0; m < 8; m++)
                #pragma unroll
                for (int n = 0; n < 4; n++) acc[m][n] = fma2(A[m], Bv[n], acc[m][n]);
        }
        __syncthreads();
    }
    float* op = g_epart + ((size_t)(b * KS1 + ks)) * CC * CC;
    #pragma unroll
    for (int m = 0; m < 8; m++) {
        int i = it * 64 + ty * 8 + m;
        float2 f0 = unpack2(acc[m][0]), f1 = unpack2(acc[m][1]);
        float2 f2 = unpack2(acc[m][2]), f3 = unpack2(acc[m][3]);
        float4 o = make_float4(f0.x + f0.y, f1.x + f1.y, f2.x + f2.y, f3.x + f3.y);
        *(float4*)(op + (size_t)i * CC + jt * 64 + tx * 4) = o;
    }
}

// ---- 3. reduce K-split partials (fixed order) ----
__global__ void k_reduce() {
    int idx = blockIdx.x * 256 + threadIdx.x;  // 65536 float4s
    int b = idx >> 12;
    int off = idx & 4095;
    const float4* p = (const float4*)g_epart + (size_t)b * KS1 * 4096 + off;
    float4 s = p[0];
    #pragma unroll
    for (int ks = 1; ks < KS1; ks++) {
        float4 v = p[(size_t)ks * 4096];
        s.x += v.x; s.y += v.y; s.z += v.z; s.w += v.w;
    }
    ((float4*)g_energy)[idx] = s;
}

// ---- 4. softmax per row, replicating reference rounding order ----
__global__ void k_softmax() {
    int w = threadIdx.x >> 5, l = threadIdx.x & 31;
    int r = blockIdx.x * 8 + w;  // 2048 rows
    float4 v = ((const float4*)(g_energy + (size_t)r * CC))[l];
    float mx = fmaxf(fmaxf(v.x, v.y), fmaxf(v.z, v.w));
    #pragma unroll
    for (int o = 16; o; o >>= 1) mx = fmaxf(mx, __shfl_xor_sync(0xffffffffu, mx, o));
    float e0 = mx - v.x, e1 = mx - v.y, e2 = mx - v.z, e3 = mx - v.w;
    float m2 = fmaxf(fmaxf(e0, e1), fmaxf(e2, e3));
    #pragma unroll
    for (int o = 16; o; o >>= 1) m2 = fmaxf(m2, __shfl_xor_sync(0xffffffffu, m2, o));
    float p0 = expf(e0 - m2), p1 = expf(e1 - m2);
    float p2 = expf(e2 - m2), p3 = expf(e3 - m2);
    float s = (p0 + p1) + (p2 + p3);
    #pragma unroll
    for (int o = 16; o; o >>= 1) s += __shfl_xor_sync(0xffffffffu, s, o);
    float inv = 1.f / s;
    float4 out = make_float4(p0 * inv, p1 * inv, p2 * inv, p3 * inv);
    ((float4*)(g_attn + (size_t)r * CC))[l] = out;
}

// ---- 5. analytic BN stats -> scale/shift per channel ----
__global__ void k_stats(const float* __restrict__ gamma,
                        const float* __restrict__ bn_w,
                        const float* __restrict__ bn_b) {
    int c = blockIdx.x, t = threadIdx.x;  // 128 threads
    __shared__ float s_a[128];
    __shared__ float red[128];
    float acc1 = 0.f, acc2 = 0.f;
    for (int b = 0; b < BB; b++) {
        s_a[t] = g_attn[((size_t)(b * CC + c)) * CC + t];
        __syncthreads();
        const float* E = g_energy + (size_t)b * CC * CC + (size_t)t * CC;
        float v = 0.f;
        #pragma unroll 8
        for (int k = 0; k < CC; k++) v += E[k] * s_a[k];
        float p1 = s_a[t] * g_rowsum[b * CC + t];
        float p2 = s_a[t] * v;
        red[t] = p1; __syncthreads();
        for (int w = 64; w; w >>= 1) { if (t < w) red[t] += red[t + w]; __syncthreads(); }
        if (t == 0) acc1 += red[0];
        __syncthreads();
        red[t] = p2; __syncthreads();
        for (int w = 64; w; w >>= 1) { if (t < w) red[t] += red[t + w]; __syncthreads(); }
        if (t == 0) acc2 += red[0];
        __syncthreads();
    }
    if (t == 0) {
        float g = gamma[0];
        float invN = 1.f / (float)((size_t)BB * HW);
        float mean = g * acc1 * invN;
        float ey2 = g * g * acc2 * invN;
        float var = ey2 - mean * mean;
        float rstd = rsqrtf(var + 1e-5f);
        float w = bn_w[c];
        g_scale[c] = g * rstd * w;
        g_shift[c] = bn_b[c] - mean * rstd * w;
    }
}

// ---- 6. out = (scale_i * attn_i) . q + shift_i + x ;  f32x2 over i-pairs ----
__global__ void __launch_bounds__(256) k_out(const float* __restrict__ x,
                                             float* __restrict__ out) {
    int nb = blockIdx.x;  // 16 chunks of 1024 along n
    int ib = blockIdx.y;  // 8 chunks of 16 along i
    int b = blockIdx.z;
    int t = threadIdx.x;
    __shared__ __align__(16) float s_a[128][16];
    __shared__ float s_sh[16];
    for (int v = t; v < 128 * 16; v += 256) {
        int j = v >> 4, ii = v & 15;
        int i = ib * 16 + ii;
        s_a[j][ii] = g_attn[((size_t)(b * CC + i)) * CC + j] * g_scale[i];
    }
    if (t < 16) s_sh[t] = g_shift[ib * 16 + t];
    __syncthreads();

    const float* qb = x + (size_t)b * CC * HW + nb * 1024 + t * 4;
    u64 acc[8][4];  // [i-pair][n]
    #pragma unroll
    for (int p = 0; p < 8; p++)
        #pragma unroll
        for (int n = 0; n < 4; n++) acc[p][n] = 0ULL;

    #pragma unroll 4
    for (int j = 0; j < 128; j++) {
        float4 qv = *(const float4*)(qb + (size_t)j * HW);
        u64 qq0 = pack2(qv.x, qv.x), qq1 = pack2(qv.y, qv.y);
        u64 qq2 = pack2(qv.z, qv.z), qq3 = pack2(qv.w, qv.w);
        const ulonglong2* ap = (const ulonglong2*)s_a[j];  // broadcast reads
        ulonglong2 a01 = ap[0], a23 = ap[1], a45 = ap[2], a67 = ap[3];
        u64 A[8] = {a01.x, a01.y, a23.x, a23.y, a45.x, a45.y, a67.x, a67.y};
        #pragma unroll
        for (int p = 0; p < 8; p++) {
            acc[p][0] = fma2(A[p], qq0, acc[p][0]);
            acc[p][1] = fma2(A[p], qq1, acc[p][1]);
            acc[p][2] = fma2(A[p], qq2, acc[p][2]);
            acc[p][3] = fma2(A[p], qq3, acc[p][3]);
        }
    }
    #pragma unroll
    for (int p = 0; p < 8; p++) {
        float2 f0 = unpack2(acc[p][0]), f1 = unpack2(acc[p][1]);
        float2 f2 = unpack2(acc[p][2]), f3 = unpack2(acc[p][3]);
        #pragma unroll
        for (int h = 0; h < 2; h++) {
            int ii = p * 2 + h;
            int i = ib * 16 + ii;
            size_t base = ((size_t)(b * CC + i)) * HW + nb * 1024 + t * 4;
            float4 xv = *(const float4*)(x + base);
            float sh = s_sh[ii];
            float4 o;
            if (h == 0) o = make_float4(f0.x + sh + xv.x, f1.x + sh + xv.y,
                                        f2.x + sh + xv.z, f3.x + sh + xv.w);
            else        o = make_float4(f0.y + sh + xv.x, f1.y + sh + xv.y,
                                        f2.y + sh + xv.z, f3.y + sh + xv.w);
            *(float4*)(out + base) = o;
        }
    }
}

extern "C" void kernel_launch(void* const* d_in, const int* in_sizes, int n_in,
                              void* d_out, int out_size) {
    const float* x = (const float*)d_in[0];
    const float* gamma = (const float*)d_in[1];
    const float* bn_w = (const float*)d_in[2];
    const float* bn_b = (const float*)d_in[3];
    float* out = (float*)d_out;

    k_rowsum<<<dim3(CC, BB), 256>>>(x);
    k_energy<<<dim3(KS1, 4, BB), 128>>>(x);
    k_reduce<<<256, 256>>>();
    k_softmax<<<256, 256>>>();
    k_stats<<<CC, 128>>>(gamma, bn_w, bn_b);
    k_out<<<dim3(16, 8, BB), 256>>>(x, out);
}

// round 6
// speedup vs baseline: 1.5191x; 1.5191x over previous
#include <cuda_runtime.h>
#include <cuda_bf16.h>
#include <math.h>

#define BB 16
#define CC 128
#define HW 16384
#define KS1 8
#define KSEG (HW / KS1)  // 2048

__device__ float g_energy[BB * CC * CC];
__device__ float g_epart[BB * KS1 * CC * CC];
__device__ float g_attn[BB * CC * CC];
__device__ float g_rowsum[BB * CC];
__device__ float g_scale[CC];
__device__ float g_shift[CC];
__device__ __nv_bfloat16 g_q0[(size_t)BB * CC * HW];
__device__ __nv_bfloat16 g_q1[(size_t)BB * CC * HW];
// attn limbs (scale folded), layout [b][limb][jhalf][i][64]
__device__ __nv_bfloat16 g_al[(size_t)BB * 2 * 2 * CC * 64];

__device__ __forceinline__ unsigned smem_u32(const void* p) {
    unsigned a;
    asm("{ .reg .u64 t; cvta.to.shared.u64 t, %1; cvt.u32.u64 %0, t; }" : "=r"(a) : "l"(p));
    return a;
}
__device__ __forceinline__ unsigned swz(unsigned o) { return o ^ ((o >> 3) & 0x70); }

#define CPA(dst, src) asm volatile("cp.async.ca.shared.global [%0], [%1], 16;" :: "r"(dst), "l"(src))
#define CPA_COMMIT()  asm volatile("cp.async.commit_group;" ::: "memory")
#define CPA_WAIT0()   asm volatile("cp.async.wait_group 0;" ::: "memory")
#define CPA_WAIT1()   asm volatile("cp.async.wait_group 1;" ::: "memory")

__device__ __forceinline__ void ldsm4(unsigned a, unsigned r[4]) {
    asm volatile("ldmatrix.sync.aligned.m8n8.x4.shared.b16 {%0,%1,%2,%3}, [%4];"
                 : "=r"(r[0]), "=r"(r[1]), "=r"(r[2]), "=r"(r[3]) : "r"(a));
}
__device__ __forceinline__ void ldsm4t(unsigned a, unsigned r[4]) {
    asm volatile("ldmatrix.sync.aligned.m8n8.x4.trans.shared.b16 {%0,%1,%2,%3}, [%4];"
                 : "=r"(r[0]), "=r"(r[1]), "=r"(r[2]), "=r"(r[3]) : "r"(a));
}
__device__ __forceinline__ void mma16816(float c[4], const unsigned a[4], unsigned b0, unsigned b1) {
    asm volatile("mma.sync.aligned.m16n8k16.row.col.f32.bf16.bf16.f32 "
                 "{%0,%1,%2,%3}, {%4,%5,%6,%7}, {%8,%9}, {%0,%1,%2,%3};"
                 : "+f"(c[0]), "+f"(c[1]), "+f"(c[2]), "+f"(c[3])
                 : "r"(a[0]), "r"(a[1]), "r"(a[2]), "r"(a[3]), "r"(b0), "r"(b1));
}

// ---------------- kernel 0: bf16 2-limb decomposition of x ----------------
__global__ void k_limbs(const float* __restrict__ x) {
    size_t idx = (size_t)blockIdx.x * 256 + threadIdx.x;
    float4 v = ((const float4*)x)[idx];
    float f[4] = {v.x, v.y, v.z, v.w};
    __nv_bfloat16 l0[4], l1[4];
    #pragma unroll
    for (int c = 0; c < 4; c++) {
        l0[c] = __float2bfloat16_rn(f[c]);
        l1[c] = __float2bfloat16_rn(f[c] - __bfloat162float(l0[c]));
    }
    ((__nv_bfloat162*)g_q0)[idx * 2]     = __nv_bfloat162(l0[0], l0[1]);
    ((__nv_bfloat162*)g_q0)[idx * 2 + 1] = __nv_bfloat162(l0[2], l0[3]);
    ((__nv_bfloat162*)g_q1)[idx * 2]     = __nv_bfloat162(l1[0], l1[1]);
    ((__nv_bfloat162*)g_q1)[idx * 2 + 1] = __nv_bfloat162(l1[2], l1[3]);
}

// ---------------- kernel 1: rowsum ----------------
__global__ void k_rowsum(const float* __restrict__ x) {
    int j = blockIdx.x, b = blockIdx.y, t = threadIdx.x;
    const float4* p = (const float4*)(x + ((size_t)(b * CC + j)) * HW);
    float s = 0.f;
    #pragma unroll 4
    for (int i = t; i < HW / 4; i += 256) {
        float4 v = p[i];
        s += (v.x + v.y) + (v.z + v.w);
    }
    __shared__ float red[256];
    red[t] = s;
    __syncthreads();
    for (int w = 128; w > 0; w >>= 1) {
        if (t < w) red[t] += red[t + w];
        __syncthreads();
    }
    if (t == 0) g_rowsum[b * CC + j] = red[0];
}

// ---------------- kernel 2: energy via mma.sync bf16, 3 limb products -------
__global__ void __launch_bounds__(256) k_energy_mma() {
    extern __shared__ char smraw[];
    char* sm = (char*)(((unsigned long long)smraw + 1023) & ~1023ULL);
    unsigned sb = smem_u32(sm);
    int t = threadIdx.x, lane = t & 31, wid = t >> 5;
    int ks = blockIdx.x, b = blockIdx.y;
    size_t rowbase = (size_t)b * CC * HW + (size_t)ks * KSEG;
    int wm = (wid >> 2) * 64, wn = (wid & 3) * 32;

    float acc[4][4][4];
    #pragma unroll
    for (int mt = 0; mt < 4; mt++)
        #pragma unroll
        for (int nt = 0; nt < 4; nt++)
            #pragma unroll
            for (int c = 0; c < 4; c++) acc[mt][nt][c] = 0.f;

    // chunk load: 2 limbs x 128 rows x 64 k (bf16) = 32 KB per buffer
    #define E_LOAD(ch) do { \
        int _buf = (ch) & 1; \
        unsigned _db = sb + _buf * 32768; \
        _Pragma("unroll") \
        for (int _i = 0; _i < 8; _i++) { \
            int _idx = t + 256 * _i; \
            int _limb = _idx >> 10, _rem = _idx & 1023, _row = _rem >> 3, _part = _rem & 7; \
            const __nv_bfloat16* _L = _limb ? g_q1 : g_q0; \
            const void* _src = _L + rowbase + (size_t)_row * HW + (ch) * 64 + _part * 8; \
            CPA(_db + _limb * 16384 + swz(_row * 128 + _part * 16), _src); \
        } \
        CPA_COMMIT(); \
    } while (0)

    E_LOAD(0);
    for (int ch = 0; ch < 32; ch++) {
        if (ch < 31) { E_LOAD(ch + 1); CPA_WAIT1(); }
        else CPA_WAIT0();
        __syncthreads();
        unsigned b0t = sb + (ch & 1) * 32768;
        unsigned b1t = b0t + 16384;
        #pragma unroll
        for (int kk = 0; kk < 4; kk++) {
            int kbyte = kk * 32;
            unsigned A0[4][4], A1[4][4];
            #pragma unroll
            for (int mt = 0; mt < 4; mt++) {
                unsigned off = swz((unsigned)((wm + mt * 16 + (lane & 15)) * 128 + kbyte + (lane >> 4) * 16));
                ldsm4(b0t + off, A0[mt]);
                ldsm4(b1t + off, A1[mt]);
            }
            unsigned B0[2][4], B1[2][4];
            #pragma unroll
            for (int nt = 0; nt < 2; nt++) {
                int row = wn + nt * 16 + ((lane >> 4) & 1) * 8 + (lane & 7);
                int kb = kbyte + ((lane >> 3) & 1) * 16;
                unsigned off = swz((unsigned)(row * 128 + kb));
                ldsm4(b0t + off, B0[nt]);
                ldsm4(b1t + off, B1[nt]);
            }
            #pragma unroll
            for (int mt = 0; mt < 4; mt++)
                #pragma unroll
                for (int nt = 0; nt < 2; nt++)
                    #pragma unroll
                    for (int s = 0; s < 2; s++) {
                        float* c = acc[mt][nt * 2 + s];
                        mma16816(c, A0[mt], B0[nt][s * 2], B0[nt][s * 2 + 1]);  // 00
                        mma16816(c, A0[mt], B1[nt][s * 2], B1[nt][s * 2 + 1]);  // 01
                        mma16816(c, A1[mt], B0[nt][s * 2], B0[nt][s * 2 + 1]);  // 10
                    }
        }
        __syncthreads();
    }

    float* op = g_epart + ((size_t)(b * KS1 + ks)) * CC * CC;
    int g = lane >> 2, tg = lane & 3;
    #pragma unroll
    for (int mt = 0; mt < 4; mt++)
        #pragma unroll
        for (int nt = 0; nt < 4; nt++) {
            int i0 = wm + mt * 16 + g, j = wn + nt * 8 + tg * 2;
            *(float2*)(op + (size_t)i0 * CC + j) = make_float2(acc[mt][nt][0], acc[mt][nt][1]);
            *(float2*)(op + (size_t)(i0 + 8) * CC + j) = make_float2(acc[mt][nt][2], acc[mt][nt][3]);
        }
}

// ---------------- kernel 3: reduce K-split partials ----------------
__global__ void k_reduce() {
    int idx = blockIdx.x * 256 + threadIdx.x;
    int b = idx >> 12, off = idx & 4095;
    const float4* p = (const float4*)g_epart + (size_t)b * KS1 * 4096 + off;
    float4 s = p[0];
    #pragma unroll
    for (int ks = 1; ks < KS1; ks++) {
        float4 v = p[(size_t)ks * 4096];
        s.x += v.x; s.y += v.y; s.z += v.z; s.w += v.w;
    }
    ((float4*)g_energy)[idx] = s;
}

// ---------------- kernel 4: softmax (reference rounding order) ----------------
__global__ void k_softmax() {
    int w = threadIdx.x >> 5, l = threadIdx.x & 31;
    int r = blockIdx.x * 8 + w;
    float4 v = ((const float4*)(g_energy + (size_t)r * CC))[l];
    float mx = fmaxf(fmaxf(v.x, v.y), fmaxf(v.z, v.w));
    #pragma unroll
    for (int o = 16; o; o >>= 1) mx = fmaxf(mx, __shfl_xor_sync(0xffffffffu, mx, o));
    float e0 = mx - v.x, e1 = mx - v.y, e2 = mx - v.z, e3 = mx - v.w;
    float m2 = fmaxf(fmaxf(e0, e1), fmaxf(e2, e3));
    #pragma unroll
    for (int o = 16; o; o >>= 1) m2 = fmaxf(m2, __shfl_xor_sync(0xffffffffu, m2, o));
    float p0 = expf(e0 - m2), p1 = expf(e1 - m2), p2 = expf(e2 - m2), p3 = expf(e3 - m2);
    float s = (p0 + p1) + (p2 + p3);
    #pragma unroll
    for (int o = 16; o; o >>= 1) s += __shfl_xor_sync(0xffffffffu, s, o);
    float inv = 1.f / s;
    ((float4*)(g_attn + (size_t)r * CC))[l] = make_float4(p0 * inv, p1 * inv, p2 * inv, p3 * inv);
}

// ---------------- kernel 5: analytic BN stats ----------------
__global__ void k_stats(const float* __restrict__ gamma,
                        const float* __restrict__ bn_w,
                        const float* __restrict__ bn_b) {
    int c = blockIdx.x, t = threadIdx.x;
    __shared__ float s_a[128], red[128];
    float acc1 = 0.f, acc2 = 0.f;
    for (int b = 0; b < BB; b++) {
        s_a[t] = g_attn[((size_t)(b * CC + c)) * CC + t];
        __syncthreads();
        const float* E = g_energy + (size_t)b * CC * CC + (size_t)t * CC;
        float v = 0.f;
        #pragma unroll 8
        for (int k = 0; k < CC; k++) v += E[k] * s_a[k];
        float p1 = s_a[t] * g_rowsum[b * CC + t];
        float p2 = s_a[t] * v;
        red[t] = p1; __syncthreads();
        for (int w = 64; w; w >>= 1) { if (t < w) red[t] += red[t + w]; __syncthreads(); }
        if (t == 0) acc1 += red[0];
        __syncthreads();
        red[t] = p2; __syncthreads();
        for (int w = 64; w; w >>= 1) { if (t < w) red[t] += red[t + w]; __syncthreads(); }
        if (t == 0) acc2 += red[0];
        __syncthreads();
    }
    if (t == 0) {
        float g = gamma[0];
        float invN = 1.f / (float)((size_t)BB * HW);
        float mean = g * acc1 * invN;
        float ey2 = g * g * acc2 * invN;
        float rstd = rsqrtf(ey2 - mean * mean + 1e-5f);
        float w = bn_w[c];
        g_scale[c] = g * rstd * w;
        g_shift[c] = bn_b[c] - mean * rstd * w;
    }
}

// ---------------- kernel 5b: attn limbs with scale folded ----------------
__global__ void k_alimb() {
    int b = blockIdx.x, j = threadIdx.x;  // 128 threads
    int half = j >> 6, jl = j & 63;
    for (int i = 0; i < 128; i++) {
        float v = g_attn[((size_t)(b * CC + i)) * CC + j] * g_scale[i];
        __nv_bfloat16 a0 = __float2bfloat16_rn(v);
        __nv_bfloat16 a1 = __float2bfloat16_rn(v - __bfloat162float(a0));
        g_al[(((size_t)(b * 2 + 0) * 2 + half) * CC + i) * 64 + jl] = a0;
        g_al[(((size_t)(b * 2 + 1) * 2 + half) * CC + i) * 64 + jl] = a1;
    }
}

// ---------------- kernel 6: out GEMM via mma.sync (3 limb products) ----------
__global__ void __launch_bounds__(256) k_out_mma(const float* __restrict__ x,
                                                 float* __restrict__ out) {
    extern __shared__ char smraw[];
    char* sm = (char*)(((unsigned long long)smraw + 1023) & ~1023ULL);
    unsigned sb = smem_u32(sm);
    float* stage = (float*)(sm + 131072);  // 128 rows x 68 floats (padded)
    int t = threadIdx.x, lane = t & 31, wid = t >> 5;
    int nb = blockIdx.x, b = blockIdx.y;   // nb: 64 chunks of 256 cols
    int wm = (wid >> 2) * 64, wn = (wid & 3) * 16;

    // load A limbs once: [limb][jhalf][row 128][64] -> 4 x 16KB tiles at sb
    #pragma unroll
    for (int i = 0; i < 16; i++) {
        int idx = t + 256 * i;
        int limb = idx >> 11, rem = idx & 2047, half = rem >> 10, r2 = rem & 1023;
        int row = r2 >> 3, part = r2 & 7;
        const void* src = g_al + (((size_t)(b * 2 + limb) * 2 + half) * CC + row) * 64 + part * 8;
        CPA(sb + (limb * 2 + half) * 16384 + swz((unsigned)(row * 128 + part * 16)), src);
    }

    // B load: q n-subchunk of 64: [limb][j row 128][64] -> 2 x 16KB at sb+65536+buf*32768
    #define O_LOAD(it) do { \
        int _buf = (it) & 1; \
        size_t _nbase = (size_t)nb * 256 + (it) * 64; \
        _Pragma("unroll") \
        for (int _i = 0; _i < 8; _i++) { \
            int _idx = t + 256 * _i; \
            int _limb = _idx >> 10, _rem = _idx & 1023, _row = _rem >> 3, _part = _rem & 7; \
            const __nv_bfloat16* _L = _limb ? g_q1 : g_q0; \
            const void* _src = _L + ((size_t)(b * CC + _row)) * HW + _nbase + _part * 8; \
            CPA(sb + 65536 + _buf * 32768 + _limb * 16384 + swz((unsigned)(_row * 128 + _part * 16)), _src); \
        } \
        CPA_COMMIT(); \
    } while (0)

    O_LOAD(0);  // group includes A loads
    for (int it = 0; it < 4; it++) {
        if (it < 3) { O_LOAD(it + 1); CPA_WAIT1(); }
        else CPA_WAIT0();
        __syncthreads();

        float acc[4][2][4];
        #pragma unroll
        for (int mt = 0; mt < 4; mt++)
            #pragma unroll
            for (int s = 0; s < 2; s++)
                #pragma unroll
                for (int c = 0; c < 4; c++) acc[mt][s][c] = 0.f;

        unsigned Bt0 = sb + 65536 + (it & 1) * 32768;
        unsigned Bt1 = Bt0 + 16384;
        #pragma unroll
        for (int ksp = 0; ksp < 8; ksp++) {
            int jhalf = ksp >> 2, kloc = (ksp & 3) * 32;
            unsigned A0[4][4], A1[4][4];
            #pragma unroll
            for (int mt = 0; mt < 4; mt++) {
                unsigned off = swz((unsigned)((wm + mt * 16 + (lane & 15)) * 128 + kloc + (lane >> 4) * 16));
                ldsm4(sb + (0 * 2 + jhalf) * 16384 + off, A0[mt]);
                ldsm4(sb + (1 * 2 + jhalf) * 16384 + off, A1[mt]);
            }
            int jrow = ksp * 16 + ((lane >> 3) & 1) * 8 + (lane & 7);
            int ncol = wn + ((lane >> 4) & 1) * 8;
            unsigned offb = swz((unsigned)(jrow * 128 + ncol * 2));
            unsigned B0f[4], B1f[4];
            ldsm4t(Bt0 + offb, B0f);
            ldsm4t(Bt1 + offb, B1f);
            #pragma unroll
            for (int mt = 0; mt < 4; mt++)
                #pragma unroll
                for (int s = 0; s < 2; s++) {
                    float* c = acc[mt][s];
                    mma16816(c, A0[mt], B0f[s * 2], B0f[s * 2 + 1]);  // a0*q0
                    mma16816(c, A0[mt], B1f[s * 2], B1f[s * 2 + 1]);  // a0*q1
                    mma16816(c, A1[mt], B0f[s * 2], B0f[s * 2 + 1]);  // a1*q0
                }
        }
        __syncthreads();

        // stage accum -> padded smem
        int g = lane >> 2, tg = lane & 3;
        #pragma unroll
        for (int mt = 0; mt < 4; mt++)
            #pragma unroll
            for (int s = 0; s < 2; s++) {
                int i0 = wm + mt * 16 + g, col = wn + s * 8 + tg * 2;
                *(float2*)&stage[i0 * 68 + col] = make_float2(acc[mt][s][0], acc[mt][s][1]);
                *(float2*)&stage[(i0 + 8) * 68 + col] = make_float2(acc[mt][s][2], acc[mt][s][3]);
            }
        __syncthreads();

        // coalesced epilogue: + shift + x
        size_t gbase = (size_t)b * CC * HW + (size_t)nb * 256 + it * 64;
        #pragma unroll
        for (int r = 0; r < 8; r++) {
            int idx = t + 256 * r;  // 2048 float4s
            int i = idx >> 4, n4 = (idx & 15) * 4;
            float4 v = *(float4*)&stage[i * 68 + n4];
            float sh = g_shift[i];
            size_t o = gbase + (size_t)i * HW + n4;
            float4 xv = *(const float4*)(x + o);
            *(float4*)(out + o) = make_float4(v.x + sh + xv.x, v.y + sh + xv.y,
                                              v.z + sh + xv.z, v.w + sh + xv.w);
        }
        __syncthreads();
    }
}

extern "C" void kernel_launch(void* const* d_in, const int* in_sizes, int n_in,
                              void* d_out, int out_size) {
    const float* x = (const float*)d_in[0];
    const float* gamma = (const float*)d_in[1];
    const float* bn_w = (const float*)d_in[2];
    const float* bn_b = (const float*)d_in[3];
    float* out = (float*)d_out;

    int smE = 1024 + 2 * 32768;                       // 66.5 KB
    int smO = 1024 + 65536 + 65536 + 128 * 68 * 4;    // ~167 KB
    cudaFuncSetAttribute(k_energy_mma, cudaFuncAttributeMaxDynamicSharedMemorySize, smE);
    cudaFuncSetAttribute(k_out_mma, cudaFuncAttributeMaxDynamicSharedMemorySize, smO);

    k_limbs<<<(BB * CC * HW) / 4 / 256, 256>>>(x);
    k_rowsum<<<dim3(CC, BB), 256>>>(x);
    k_energy_mma<<<dim3(KS1, BB), 256, smE>>>();
    k_reduce<<<256, 256>>>();
    k_softmax<<<256, 256>>>();
    k_stats<<<CC, 128>>>(gamma, bn_w, bn_b);
    k_alimb<<<BB, 128>>>();
    k_out_mma<<<dim3(64, BB), 256, smO>>>(x, out);
}

// round 7
// speedup vs baseline: 1.5700x; 1.0335x over previous
#include <cuda_runtime.h>
#include <cuda_bf16.h>
#include <math.h>

#define BB 16
#define CC 128
#define HW 16384
#define KS1 8
#define KSEG (HW / KS1)  // 2048

__device__ float g_energy[BB * CC * CC];
__device__ float g_epF[BB * KS1 * CC * CC];
__device__ float g_epG[BB * KS1 * CC * CC];
__device__ float g_attn[BB * CC * CC];
__device__ float g_rowsum[BB * CC];
__device__ float g_scale[CC];
__device__ float g_shift[CC];
__device__ __nv_bfloat16 g_q0[(size_t)BB * CC * HW];
__device__ __nv_bfloat16 g_q1[(size_t)BB * CC * HW];
// attn limbs (scale folded), layout [b][limb][jhalf][i][64]
__device__ __nv_bfloat16 g_al[(size_t)BB * 2 * 2 * CC * 64];

__device__ __forceinline__ unsigned smem_u32(const void* p) {
    unsigned a;
    asm("{ .reg .u64 t; cvta.to.shared.u64 t, %1; cvt.u32.u64 %0, t; }" : "=r"(a) : "l"(p));
    return a;
}
__device__ __forceinline__ unsigned swz(unsigned o) { return o ^ ((o >> 3) & 0x70); }

#define CPA(dst, src) asm volatile("cp.async.ca.shared.global [%0], [%1], 16;" :: "r"(dst), "l"(src))
#define CPA_COMMIT()  asm volatile("cp.async.commit_group;" ::: "memory")
#define CPA_WAIT0()   asm volatile("cp.async.wait_group 0;" ::: "memory")
#define CPA_WAIT1()   asm volatile("cp.async.wait_group 1;" ::: "memory")

__device__ __forceinline__ void ldsm4(unsigned a, unsigned r[4]) {
    asm volatile("ldmatrix.sync.aligned.m8n8.x4.shared.b16 {%0,%1,%2,%3}, [%4];"
                 : "=r"(r[0]), "=r"(r[1]), "=r"(r[2]), "=r"(r[3]) : "r"(a));
}
__device__ __forceinline__ void ldsm4t(unsigned a, unsigned r[4]) {
    asm volatile("ldmatrix.sync.aligned.m8n8.x4.trans.shared.b16 {%0,%1,%2,%3}, [%4];"
                 : "=r"(r[0]), "=r"(r[1]), "=r"(r[2]), "=r"(r[3]) : "r"(a));
}
__device__ __forceinline__ void mma16816(float c[4], const unsigned a[4], unsigned b0, unsigned b1) {
    asm volatile("mma.sync.aligned.m16n8k16.row.col.f32.bf16.bf16.f32 "
                 "{%0,%1,%2,%3}, {%4,%5,%6,%7}, {%8,%9}, {%0,%1,%2,%3};"
                 : "+f"(c[0]), "+f"(c[1]), "+f"(c[2]), "+f"(c[3])
                 : "r"(a[0]), "r"(a[1]), "r"(a[2]), "r"(a[3]), "r"(b0), "r"(b1));
}

// ---- kernel 0: fused bf16 2-limb decomposition + rowsum (one row per block) --
__global__ void k_limbs_rs(const float* __restrict__ x, int b0) {
    int j = blockIdx.x, b = b0 + blockIdx.y, t = threadIdx.x;
    size_t rb = ((size_t)(b * CC + j)) * HW;
    const float4* p = (const float4*)(x + rb);
    __nv_bfloat162* o0 = (__nv_bfloat162*)(g_q0 + rb);
    __nv_bfloat162* o1 = (__nv_bfloat162*)(g_q1 + rb);
    float s = 0.f;
    #pragma unroll 4
    for (int i = t; i < HW / 4; i += 256) {
        float4 v = p[i];
        s += (v.x + v.y) + (v.z + v.w);
        float f[4] = {v.x, v.y, v.z, v.w};
        __nv_bfloat16 l0[4], l1[4];
        #pragma unroll
        for (int c = 0; c < 4; c++) {
            l0[c] = __float2bfloat16_rn(f[c]);
            l1[c] = __float2bfloat16_rn(f[c] - __bfloat162float(l0[c]));
        }
        o0[i * 2] = __nv_bfloat162(l0[0], l0[1]);
        o0[i * 2 + 1] = __nv_bfloat162(l0[2], l0[3]);
        o1[i * 2] = __nv_bfloat162(l1[0], l1[1]);
        o1[i * 2 + 1] = __nv_bfloat162(l1[2], l1[3]);
    }
    __shared__ float red[256];
    red[t] = s;
    __syncthreads();
    for (int w = 128; w > 0; w >>= 1) {
        if (t < w) red[t] += red[t + w];
        __syncthreads();
    }
    if (t == 0) g_rowsum[b * CC + j] = red[0];
}

__global__ void k_nop() {}

// ---- kernel 2: energy via mma.sync: F = q0 q0^T, G = q0 q1^T ----------------
__global__ void __launch_bounds__(256) k_energy_mma() {
    extern __shared__ char smraw[];
    char* sm = (char*)(((unsigned long long)smraw + 1023) & ~1023ULL);
    unsigned sb = smem_u32(sm);
    int t = threadIdx.x, lane = t & 31, wid = t >> 5;
    int ks = blockIdx.x, b = blockIdx.y;
    size_t rowbase = (size_t)b * CC * HW + (size_t)ks * KSEG;
    int wm = (wid >> 2) * 64, wn = (wid & 3) * 32;

    float accF[4][4][4], accG[4][4][4];
    #pragma unroll
    for (int mt = 0; mt < 4; mt++)
        #pragma unroll
        for (int nt = 0; nt < 4; nt++)
            #pragma unroll
            for (int c = 0; c < 4; c++) { accF[mt][nt][c] = 0.f; accG[mt][nt][c] = 0.f; }

    #define E_LOAD(ch) do { \
        int _buf = (ch) & 1; \
        unsigned _db = sb + _buf * 32768; \
        _Pragma("unroll") \
        for (int _i = 0; _i < 8; _i++) { \
            int _idx = t + 256 * _i; \
            int _limb = _idx >> 10, _rem = _idx & 1023, _row = _rem >> 3, _part = _rem & 7; \
            const __nv_bfloat16* _L = _limb ? g_q1 : g_q0; \
            const void* _src = _L + rowbase + (size_t)_row * HW + (ch) * 64 + _part * 8; \
            CPA(_db + _limb * 16384 + swz(_row * 128 + _part * 16), _src); \
        } \
        CPA_COMMIT(); \
    } while (0)

    E_LOAD(0);
    for (int ch = 0; ch < 32; ch++) {
        if (ch < 31) { E_LOAD(ch + 1); CPA_WAIT1(); }
        else CPA_WAIT0();
        __syncthreads();
        unsigned b0t = sb + (ch & 1) * 32768;
        unsigned b1t = b0t + 16384;
        #pragma unroll
        for (int kk = 0; kk < 4; kk++) {
            int kbyte = kk * 32;
            unsigned A[4][4];
            #pragma unroll
            for (int mt = 0; mt < 4; mt++) {
                unsigned off = swz((unsigned)((wm + mt * 16 + (lane & 15)) * 128 + kbyte + (lane >> 4) * 16));
                ldsm4(b0t + off, A[mt]);
            }
            unsigned B0[2][4], B1[2][4];
            #pragma unroll
            for (int nt = 0; nt < 2; nt++) {
                int row = wn + nt * 16 + ((lane >> 4) & 1) * 8 + (lane & 7);
                int kb = kbyte + ((lane >> 3) & 1) * 16;
                unsigned off = swz((unsigned)(row * 128 + kb));
                ldsm4(b0t + off, B0[nt]);
                ldsm4(b1t + off, B1[nt]);
            }
            #pragma unroll
            for (int mt = 0; mt < 4; mt++)
                #pragma unroll
                for (int nt = 0; nt < 2; nt++)
                    #pragma unroll
                    for (int s = 0; s < 2; s++) {
                        mma16816(accF[mt][nt * 2 + s], A[mt], B0[nt][s * 2], B0[nt][s * 2 + 1]);
                        mma16816(accG[mt][nt * 2 + s], A[mt], B1[nt][s * 2], B1[nt][s * 2 + 1]);
                    }
        }
        __syncthreads();
    }

    size_t pbase = ((size_t)(b * KS1 + ks)) * CC * CC;
    int g = lane >> 2, tg = lane & 3;
    #pragma unroll
    for (int mt = 0; mt < 4; mt++)
        #pragma unroll
        for (int nt = 0; nt < 4; nt++) {
            int i0 = wm + mt * 16 + g, j = wn + nt * 8 + tg * 2;
            *(float2*)(g_epF + pbase + (size_t)i0 * CC + j) = make_float2(accF[mt][nt][0], accF[mt][nt][1]);
            *(float2*)(g_epF + pbase + (size_t)(i0 + 8) * CC + j) = make_float2(accF[mt][nt][2], accF[mt][nt][3]);
            *(float2*)(g_epG + pbase + (size_t)i0 * CC + j) = make_float2(accG[mt][nt][0], accG[mt][nt][1]);
            *(float2*)(g_epG + pbase + (size_t)(i0 + 8) * CC + j) = make_float2(accG[mt][nt][2], accG[mt][nt][3]);
        }
}

// ---- kernel 3: E = sum_ks F + sum_ks G + (sum_ks G)^T ----------------------
__global__ void k_reduce_sym() {  // grid (4, BB), block 256
    int islab = blockIdx.x, b = blockIdx.y, t = threadIdx.x;
    __shared__ float sGT[32][132];  // sGT[i_local][j] = Gsum[j][islab*32+i_local]
    // phase A: sum G column-slab, store transposed
    #pragma unroll
    for (int r = 0; r < 4; r++) {
        int idx = t + 256 * r;
        int j = idx >> 3, c4 = idx & 7;
        float4 s = make_float4(0.f, 0.f, 0.f, 0.f);
        #pragma unroll
        for (int ks = 0; ks < KS1; ks++) {
            float4 v = *(const float4*)(g_epG + (((size_t)(b * KS1 + ks) * CC + j)) * CC + islab * 32 + c4 * 4);
            s.x += v.x; s.y += v.y; s.z += v.z; s.w += v.w;
        }
        sGT[c4 * 4 + 0][j] = s.x;
        sGT[c4 * 4 + 1][j] = s.y;
        sGT[c4 * 4 + 2][j] = s.z;
        sGT[c4 * 4 + 3][j] = s.w;
    }
    __syncthreads();
    // phase B: row-slab F+G sums + transposed add
    #pragma unroll
    for (int r = 0; r < 4; r++) {
        int idx = t + 256 * r;
        int il = idx >> 5, j4 = idx & 31;
        int i = islab * 32 + il;
        float4 f = make_float4(0.f, 0.f, 0.f, 0.f);
        #pragma unroll
        for (int ks = 0; ks < KS1; ks++) {
            size_t o = (((size_t)(b * KS1 + ks) * CC + i)) * CC + j4 * 4;
            float4 vf = *(const float4*)(g_epF + o);
            float4 vg = *(const float4*)(g_epG + o);
            f.x += vf.x + vg.x; f.y += vf.y + vg.y; f.z += vf.z + vg.z; f.w += vf.w + vg.w;
        }
        float4 gt = *(const float4*)&sGT[il][j4 * 4];
        *(float4*)(g_energy + ((size_t)(b * CC + i)) * CC + j4 * 4) =
            make_float4(f.x + gt.x, f.y + gt.y, f.z + gt.z, f.w + gt.w);
    }
}

// ---- kernel 4: softmax (reference rounding order) ---------------------------
__global__ void k_softmax() {
    int w = threadIdx.x >> 5, l = threadIdx.x & 31;
    int r = blockIdx.x * 8 + w;
    float4 v = ((const float4*)(g_energy + (size_t)r * CC))[l];
    float mx = fmaxf(fmaxf(v.x, v.y), fmaxf(v.z, v.w));
    #pragma unroll
    for (int o = 16; o; o >>= 1) mx = fmaxf(mx, __shfl_xor_sync(0xffffffffu, mx, o));
    float e0 = mx - v.x, e1 = mx - v.y, e2 = mx - v.z, e3 = mx - v.w;
    float m2 = fmaxf(fmaxf(e0, e1), fmaxf(e2, e3));
    #pragma unroll
    for (int o = 16; o; o >>= 1) m2 = fmaxf(m2, __shfl_xor_sync(0xffffffffu, m2, o));
    float p0 = expf(e0 - m2), p1 = expf(e1 - m2), p2 = expf(e2 - m2), p3 = expf(e3 - m2);
    float s = (p0 + p1) + (p2 + p3);
    #pragma unroll
    for (int o = 16; o; o >>= 1) s += __shfl_xor_sync(0xffffffffu, s, o);
    float inv = 1.f / s;
    ((float4*)(g_attn + (size_t)r * CC))[l] = make_float4(p0 * inv, p1 * inv, p2 * inv, p3 * inv);
}

// ---- kernel 5: analytic BN stats -------------------------------------------
__global__ void k_stats(const float* __restrict__ gamma,
                        const float* __restrict__ bn_w,
                        const float* __restrict__ bn_b) {
    int c = blockIdx.x, t = threadIdx.x;
    __shared__ float s_a[128], red[128];
    float acc1 = 0.f, acc2 = 0.f;
    for (int b = 0; b < BB; b++) {
        s_a[t] = g_attn[((size_t)(b * CC + c)) * CC + t];
        __syncthreads();
        const float* E = g_energy + (size_t)b * CC * CC + (size_t)t * CC;
        float v = 0.f;
        #pragma unroll 8
        for (int k = 0; k < CC; k++) v += E[k] * s_a[k];
        float p1 = s_a[t] * g_rowsum[b * CC + t];
        float p2 = s_a[t] * v;
        red[t] = p1; __syncthreads();
        for (int w = 64; w; w >>= 1) { if (t < w) red[t] += red[t + w]; __syncthreads(); }
        if (t == 0) acc1 += red[0];
        __syncthreads();
        red[t] = p2; __syncthreads();
        for (int w = 64; w; w >>= 1) { if (t < w) red[t] += red[t + w]; __syncthreads(); }
        if (t == 0) acc2 += red[0];
        __syncthreads();
    }
    if (t == 0) {
        float g = gamma[0];
        float invN = 1.f / (float)((size_t)BB * HW);
        float mean = g * acc1 * invN;
        float ey2 = g * g * acc2 * invN;
        float rstd = rsqrtf(ey2 - mean * mean + 1e-5f);
        float w = bn_w[c];
        g_scale[c] = g * rstd * w;
        g_shift[c] = bn_b[c] - mean * rstd * w;
    }
}

// ---- kernel 5b: attn limbs with scale folded --------------------------------
__global__ void k_alimb() {
    int b = blockIdx.x, j = threadIdx.x;
    int half = j >> 6, jl = j & 63;
    for (int i = 0; i < 128; i++) {
        float v = g_attn[((size_t)(b * CC + i)) * CC + j] * g_scale[i];
        __nv_bfloat16 a0 = __float2bfloat16_rn(v);
        __nv_bfloat16 a1 = __float2bfloat16_rn(v - __bfloat162float(a0));
        g_al[(((size_t)(b * 2 + 0) * 2 + half) * CC + i) * 64 + jl] = a0;
        g_al[(((size_t)(b * 2 + 1) * 2 + half) * CC + i) * 64 + jl] = a1;
    }
}

// ---- kernel 6: out GEMM via mma.sync (3 limb products) ----------------------
__global__ void __launch_bounds__(256) k_out_mma(const float* __restrict__ x,
                                                 float* __restrict__ out) {
    extern __shared__ char smraw[];
    char* sm = (char*)(((unsigned long long)smraw + 1023) & ~1023ULL);
    unsigned sb = smem_u32(sm);
    float* stage = (float*)(sm + 131072);
    int t = threadIdx.x, lane = t & 31, wid = t >> 5;
    int nb = blockIdx.x, b = blockIdx.y;
    int wm = (wid >> 2) * 64, wn = (wid & 3) * 16;

    #pragma unroll
    for (int i = 0; i < 16; i++) {
        int idx = t + 256 * i;
        int limb = idx >> 11, rem = idx & 2047, half = rem >> 10, r2 = rem & 1023;
        int row = r2 >> 3, part = r2 & 7;
        const void* src = g_al + (((size_t)(b * 2 + limb) * 2 + half) * CC + row) * 64 + part * 8;
        CPA(sb + (limb * 2 + half) * 16384 + swz((unsigned)(row * 128 + part * 16)), src);
    }

    #define O_LOAD(it) do { \
        int _buf = (it) & 1; \
        size_t _nbase = (size_t)nb * 256 + (it) * 64; \
        _Pragma("unroll") \
        for (int _i = 0; _i < 8; _i++) { \
            int _idx = t + 256 * _i; \
            int _limb = _idx >> 10, _rem = _idx & 1023, _row = _rem >> 3, _part = _rem & 7; \
            const __nv_bfloat16* _L = _limb ? g_q1 : g_q0; \
            const void* _src = _L + ((size_t)(b * CC + _row)) * HW + _nbase + _part * 8; \
            CPA(sb + 65536 + _buf * 32768 + _limb * 16384 + swz((unsigned)(_row * 128 + _part * 16)), _src); \
        } \
        CPA_COMMIT(); \
    } while (0)

    O_LOAD(0);
    for (int it = 0; it < 4; it++) {
        if (it < 3) { O_LOAD(it + 1); CPA_WAIT1(); }
        else CPA_WAIT0();
        __syncthreads();

        float acc[4][2][4];
        #pragma unroll
        for (int mt = 0; mt < 4; mt++)
            #pragma unroll
            for (int s = 0; s < 2; s++)
                #pragma unroll
                for (int c = 0; c < 4; c++) acc[mt][s][c] = 0.f;

        unsigned Bt0 = sb + 65536 + (it & 1) * 32768;
        unsigned Bt1 = Bt0 + 16384;
        #pragma unroll
        for (int ksp = 0; ksp < 8; ksp++) {
            int jhalf = ksp >> 2, kloc = (ksp & 3) * 32;
            unsigned A0[4][4], A1[4][4];
            #pragma unroll
            for (int mt = 0; mt < 4; mt++) {
                unsigned off = swz((unsigned)((wm + mt * 16 + (lane & 15)) * 128 + kloc + (lane >> 4) * 16));
                ldsm4(sb + (0 * 2 + jhalf) * 16384 + off, A0[mt]);
                ldsm4(sb + (1 * 2 + jhalf) * 16384 + off, A1[mt]);
            }
            int jrow = ksp * 16 + ((lane >> 3) & 1) * 8 + (lane & 7);
            int ncol = wn + ((lane >> 4) & 1) * 8;
            unsigned offb = swz((unsigned)(jrow * 128 + ncol * 2));
            unsigned B0f[4], B1f[4];
            ldsm4t(Bt0 + offb, B0f);
            ldsm4t(Bt1 + offb, B1f);
            #pragma unroll
            for (int mt = 0; mt < 4; mt++)
                #pragma unroll
                for (int s = 0; s < 2; s++) {
                    float* c = acc[mt][s];
                    mma16816(c, A0[mt], B0f[s * 2], B0f[s * 2 + 1]);
                    mma16816(c, A0[mt], B1f[s * 2], B1f[s * 2 + 1]);
                    mma16816(c, A1[mt], B0f[s * 2], B0f[s * 2 + 1]);
                }
        }
        __syncthreads();

        int g = lane >> 2, tg = lane & 3;
        #pragma unroll
        for (int mt = 0; mt < 4; mt++)
            #pragma unroll
            for (int s = 0; s < 2; s++) {
                int i0 = wm + mt * 16 + g, col = wn + s * 8 + tg * 2;
                *(float2*)&stage[i0 * 68 + col] = make_float2(acc[mt][s][0], acc[mt][s][1]);
                *(float2*)&stage[(i0 + 8) * 68 + col] = make_float2(acc[mt][s][2], acc[mt][s][3]);
            }
        __syncthreads();

        size_t gbase = (size_t)b * CC * HW + (size_t)nb * 256 + it * 64;
        #pragma unroll
        for (int r = 0; r < 8; r++) {
            int idx = t + 256 * r;
            int i = idx >> 4, n4 = (idx & 15) * 4;
            float4 v = *(float4*)&stage[i * 68 + n4];
            float sh = g_shift[i];
            size_t o = gbase + (size_t)i * HW + n4;
            float4 xv = *(const float4*)(x + o);
            *(float4*)(out + o) = make_float4(v.x + sh + xv.x, v.y + sh + xv.y,
                                              v.z + sh + xv.z, v.w + sh + xv.w);
        }
        __syncthreads();
    }
}

extern "C" void kernel_launch(void* const* d_in, const int* in_sizes, int n_in,
                              void* d_out, int out_size) {
    const float* x = (const float*)d_in[0];
    const float* gamma = (const float*)d_in[1];
    const float* bn_w = (const float*)d_in[2];
    const float* bn_b = (const float*)d_in[3];
    float* out = (float*)d_out;

    int smE = 1024 + 2 * 32768;
    int smO = 1024 + 65536 + 65536 + 128 * 68 * 4;
    cudaFuncSetAttribute(k_energy_mma, cudaFuncAttributeMaxDynamicSharedMemorySize, smE);
    cudaFuncSetAttribute(k_out_mma, cudaFuncAttributeMaxDynamicSharedMemorySize, smO);

    k_limbs_rs<<<dim3(CC, BB / 2), 256>>>(x, 0);       // launch 0
    k_limbs_rs<<<dim3(CC, BB / 2), 256>>>(x, BB / 2);  // launch 1
    k_nop<<<1, 1>>>();                                  // launch 2
    k_energy_mma<<<dim3(KS1, BB), 256, smE>>>();        // launch 3 (ncu capture slot)
    k_reduce_sym<<<dim3(4, BB), 256>>>();
    k_softmax<<<256, 256>>>();
    k_stats<<<CC, 128>>>(gamma, bn_w, bn_b);
    k_alimb<<<BB, 128>>>();
    k_out_mma<<<dim3(64, BB), 256, smO>>>(x, out);
}

// round 8
// speedup vs baseline: 2.0693x; 1.3180x over previous
#include <cuda_runtime.h>
#include <cuda_bf16.h>
#include <math.h>

#define BB 16
#define CC 128
#define HW 16384
#define KS1 8
#define KSEG (HW / KS1)  // 2048

__device__ float g_energy[BB * CC * CC];
__device__ float g_epF[BB * KS1 * CC * CC];
__device__ float g_epG[BB * KS1 * CC * CC];
__device__ float g_attn[BB * CC * CC];
__device__ float g_rowsum[BB * CC];
__device__ float g_part1[BB * CC];
__device__ float g_part2[BB * CC];
__device__ float g_scale[CC];
__device__ float g_shift[CC];
__device__ __nv_bfloat16 g_q0[(size_t)BB * CC * HW];
__device__ __nv_bfloat16 g_q1[(size_t)BB * CC * HW];
// attn limbs (scale folded), layout [b][limb][jhalf][i][64]
__device__ __nv_bfloat16 g_al[(size_t)BB * 2 * 2 * CC * 64];

__device__ __forceinline__ unsigned smem_u32(const void* p) {
    unsigned a;
    asm("{ .reg .u64 t; cvta.to.shared.u64 t, %1; cvt.u32.u64 %0, t; }" : "=r"(a) : "l"(p));
    return a;
}
__device__ __forceinline__ unsigned swz(unsigned o) { return o ^ ((o >> 3) & 0x70); }

#define CPA(dst, src) asm volatile("cp.async.ca.shared.global [%0], [%1], 16;" :: "r"(dst), "l"(src))
#define CPA_COMMIT()  asm volatile("cp.async.commit_group;" ::: "memory")
#define CPA_WAIT0()   asm volatile("cp.async.wait_group 0;" ::: "memory")
#define CPA_WAIT1()   asm volatile("cp.async.wait_group 1;" ::: "memory")

__device__ __forceinline__ void ldsm4(unsigned a, unsigned r[4]) {
    asm volatile("ldmatrix.sync.aligned.m8n8.x4.shared.b16 {%0,%1,%2,%3}, [%4];"
                 : "=r"(r[0]), "=r"(r[1]), "=r"(r[2]), "=r"(r[3]) : "r"(a));
}
__device__ __forceinline__ void ldsm4t(unsigned a, unsigned r[4]) {
    asm volatile("ldmatrix.sync.aligned.m8n8.x4.trans.shared.b16 {%0,%1,%2,%3}, [%4];"
                 : "=r"(r[0]), "=r"(r[1]), "=r"(r[2]), "=r"(r[3]) : "r"(a));
}
__device__ __forceinline__ void mma16816(float c[4], const unsigned a[4], unsigned b0, unsigned b1) {
    asm volatile("mma.sync.aligned.m16n8k16.row.col.f32.bf16.bf16.f32 "
                 "{%0,%1,%2,%3}, {%4,%5,%6,%7}, {%8,%9}, {%0,%1,%2,%3};"
                 : "+f"(c[0]), "+f"(c[1]), "+f"(c[2]), "+f"(c[3])
                 : "r"(a[0]), "r"(a[1]), "r"(a[2]), "r"(a[3]), "r"(b0), "r"(b1));
}

// ---- kernel 0: fused bf16 2-limb decomposition + rowsum ---------------------
__global__ void k_limbs_rs(const float* __restrict__ x) {
    int j = blockIdx.x, b = blockIdx.y, t = threadIdx.x;
    size_t rb = ((size_t)(b * CC + j)) * HW;
    const float4* p = (const float4*)(x + rb);
    __nv_bfloat162* o0 = (__nv_bfloat162*)(g_q0 + rb);
    __nv_bfloat162* o1 = (__nv_bfloat162*)(g_q1 + rb);
    float s = 0.f;
    #pragma unroll 4
    for (int i = t; i < HW / 4; i += 256) {
        float4 v = p[i];
        s += (v.x + v.y) + (v.z + v.w);
        float f[4] = {v.x, v.y, v.z, v.w};
        __nv_bfloat16 l0[4], l1[4];
        #pragma unroll
        for (int c = 0; c < 4; c++) {
            l0[c] = __float2bfloat16_rn(f[c]);
            l1[c] = __float2bfloat16_rn(f[c] - __bfloat162float(l0[c]));
        }
        o0[i * 2] = __nv_bfloat162(l0[0], l0[1]);
        o0[i * 2 + 1] = __nv_bfloat162(l0[2], l0[3]);
        o1[i * 2] = __nv_bfloat162(l1[0], l1[1]);
        o1[i * 2 + 1] = __nv_bfloat162(l1[2], l1[3]);
    }
    __shared__ float red[256];
    red[t] = s;
    __syncthreads();
    for (int w = 128; w > 0; w >>= 1) {
        if (t < w) red[t] += red[t + w];
        __syncthreads();
    }
    if (t == 0) g_rowsum[b * CC + j] = red[0];
}

// ---- kernel 1: energy via mma.sync: F = q0 q0^T, G = q0 q1^T ----------------
__global__ void __launch_bounds__(256) k_energy_mma() {
    extern __shared__ char smraw[];
    char* sm = (char*)(((unsigned long long)smraw + 1023) & ~1023ULL);
    unsigned sb = smem_u32(sm);
    int t = threadIdx.x, lane = t & 31, wid = t >> 5;
    int ks = blockIdx.x, b = blockIdx.y;
    size_t rowbase = (size_t)b * CC * HW + (size_t)ks * KSEG;
    int wm = (wid >> 2) * 64, wn = (wid & 3) * 32;

    float accF[4][4][4], accG[4][4][4];
    #pragma unroll
    for (int mt = 0; mt < 4; mt++)
        #pragma unroll
        for (int nt = 0; nt < 4; nt++)
            #pragma unroll
            for (int c = 0; c < 4; c++) { accF[mt][nt][c] = 0.f; accG[mt][nt][c] = 0.f; }

    #define E_LOAD(ch) do { \
        int _buf = (ch) & 1; \
        unsigned _db = sb + _buf * 32768; \
        _Pragma("unroll") \
        for (int _i = 0; _i < 8; _i++) { \
            int _idx = t + 256 * _i; \
            int _limb = _idx >> 10, _rem = _idx & 1023, _row = _rem >> 3, _part = _rem & 7; \
            const __nv_bfloat16* _L = _limb ? g_q1 : g_q0; \
            const void* _src = _L + rowbase + (size_t)_row * HW + (ch) * 64 + _part * 8; \
            CPA(_db + _limb * 16384 + swz(_row * 128 + _part * 16), _src); \
        } \
        CPA_COMMIT(); \
    } while (0)

    E_LOAD(0);
    for (int ch = 0; ch < 32; ch++) {
        if (ch < 31) { E_LOAD(ch + 1); CPA_WAIT1(); }
        else CPA_WAIT0();
        __syncthreads();
        unsigned b0t = sb + (ch & 1) * 32768;
        unsigned b1t = b0t + 16384;
        #pragma unroll
        for (int kk = 0; kk < 4; kk++) {
            int kbyte = kk * 32;
            unsigned A[4][4];
            #pragma unroll
            for (int mt = 0; mt < 4; mt++) {
                unsigned off = swz((unsigned)((wm + mt * 16 + (lane & 15)) * 128 + kbyte + (lane >> 4) * 16));
                ldsm4(b0t + off, A[mt]);
            }
            unsigned B0[2][4], B1[2][4];
            #pragma unroll
            for (int nt = 0; nt < 2; nt++) {
                int row = wn + nt * 16 + ((lane >> 4) & 1) * 8 + (lane & 7);
                int kb = kbyte + ((lane >> 3) & 1) * 16;
                unsigned off = swz((unsigned)(row * 128 + kb));
                ldsm4(b0t + off, B0[nt]);
                ldsm4(b1t + off, B1[nt]);
            }
            #pragma unroll
            for (int mt = 0; mt < 4; mt++)
                #pragma unroll
                for (int nt = 0; nt < 2; nt++)
                    #pragma unroll
                    for (int s = 0; s < 2; s++) {
                        mma16816(accF[mt][nt * 2 + s], A[mt], B0[nt][s * 2], B0[nt][s * 2 + 1]);
                        mma16816(accG[mt][nt * 2 + s], A[mt], B1[nt][s * 2], B1[nt][s * 2 + 1]);
                    }
        }
        __syncthreads();
    }
    #undef E_LOAD

    size_t pbase = ((size_t)(b * KS1 + ks)) * CC * CC;
    int g = lane >> 2, tg = lane & 3;
    #pragma unroll
    for (int mt = 0; mt < 4; mt++)
        #pragma unroll
        for (int nt = 0; nt < 4; nt++) {
            int i0 = wm + mt * 16 + g, j = wn + nt * 8 + tg * 2;
            *(float2*)(g_epF + pbase + (size_t)i0 * CC + j) = make_float2(accF[mt][nt][0], accF[mt][nt][1]);
            *(float2*)(g_epF + pbase + (size_t)(i0 + 8) * CC + j) = make_float2(accF[mt][nt][2], accF[mt][nt][3]);
            *(float2*)(g_epG + pbase + (size_t)i0 * CC + j) = make_float2(accG[mt][nt][0], accG[mt][nt][1]);
            *(float2*)(g_epG + pbase + (size_t)(i0 + 8) * CC + j) = make_float2(accG[mt][nt][2], accG[mt][nt][3]);
        }
}

// ---- kernel 2: fused E = F + G + G^T  AND softmax ---------------------------
__global__ void k_redsoft() {  // grid (4, BB), block 256
    int islab = blockIdx.x, b = blockIdx.y, t = threadIdx.x;
    int lane = t & 31;
    __shared__ float sGT[32][132];
    #pragma unroll
    for (int r = 0; r < 4; r++) {
        int idx = t + 256 * r;
        int j = idx >> 3, c4 = idx & 7;
        float4 s = make_float4(0.f, 0.f, 0.f, 0.f);
        #pragma unroll
        for (int ks = 0; ks < KS1; ks++) {
            float4 v = *(const float4*)(g_epG + (((size_t)(b * KS1 + ks) * CC + j)) * CC + islab * 32 + c4 * 4);
            s.x += v.x; s.y += v.y; s.z += v.z; s.w += v.w;
        }
        sGT[c4 * 4 + 0][j] = s.x;
        sGT[c4 * 4 + 1][j] = s.y;
        sGT[c4 * 4 + 2][j] = s.z;
        sGT[c4 * 4 + 3][j] = s.w;
    }
    __syncthreads();
    #pragma unroll
    for (int r = 0; r < 4; r++) {
        int idx = t + 256 * r;
        int il = idx >> 5, j4 = idx & 31;  // warp-aligned: one row per warp
        int i = islab * 32 + il;
        float4 f = make_float4(0.f, 0.f, 0.f, 0.f);
        #pragma unroll
        for (int ks = 0; ks < KS1; ks++) {
            size_t o = (((size_t)(b * KS1 + ks) * CC + i)) * CC + j4 * 4;
            float4 vf = *(const float4*)(g_epF + o);
            float4 vg = *(const float4*)(g_epG + o);
            f.x += vf.x + vg.x; f.y += vf.y + vg.y; f.z += vf.z + vg.z; f.w += vf.w + vg.w;
        }
        float4 gt = *(const float4*)&sGT[il][j4 * 4];
        float4 e = make_float4(f.x + gt.x, f.y + gt.y, f.z + gt.z, f.w + gt.w);
        *(float4*)(g_energy + ((size_t)(b * CC + i)) * CC + j4 * 4) = e;
        // softmax (reference rounding order)
        float mx = fmaxf(fmaxf(e.x, e.y), fmaxf(e.z, e.w));
        #pragma unroll
        for (int o = 16; o; o >>= 1) mx = fmaxf(mx, __shfl_xor_sync(0xffffffffu, mx, o));
        float e0 = mx - e.x, e1 = mx - e.y, e2 = mx - e.z, e3 = mx - e.w;
        float m2 = fmaxf(fmaxf(e0, e1), fmaxf(e2, e3));
        #pragma unroll
        for (int o = 16; o; o >>= 1) m2 = fmaxf(m2, __shfl_xor_sync(0xffffffffu, m2, o));
        float p0 = expf(e0 - m2), p1 = expf(e1 - m2), p2 = expf(e2 - m2), p3 = expf(e3 - m2);
        float s = (p0 + p1) + (p2 + p3);
        #pragma unroll
        for (int o = 16; o; o >>= 1) s += __shfl_xor_sync(0xffffffffu, s, o);
        float inv = 1.f / s;
        *(float4*)(g_attn + ((size_t)(b * CC + i)) * CC + j4 * 4) =
            make_float4(p0 * inv, p1 * inv, p2 * inv, p3 * inv);
        (void)lane;
    }
}

// ---- kernel 3: BN stats partials per batch (T = A.E, a.T.a, a.rowsum) -------
__global__ void __launch_bounds__(256) k_stats1() {
    int b = blockIdx.x, t = threadIdx.x, lane = t & 31, w = t >> 5;
    extern __shared__ float sms[];
    float* sE = sms;           // [k][j] 16384
    float* sA = sms + 16384;   // [c][k] 16384
    float* sR = sms + 32768;   // 128
    const float4* Eg = (const float4*)(g_energy + (size_t)b * CC * CC);
    const float4* Ag = (const float4*)(g_attn + (size_t)b * CC * CC);
    for (int i = t; i < 4096; i += 256) {
        ((float4*)sE)[i] = Eg[i];
        ((float4*)sA)[i] = Ag[i];
    }
    if (t < 32) ((float4*)sR)[t] = ((const float4*)(g_rowsum + b * CC))[t];
    __syncthreads();

    int c0 = w * 16;
    float accT[16][4];
    #pragma unroll
    for (int c = 0; c < 16; c++)
        #pragma unroll
        for (int q = 0; q < 4; q++) accT[c][q] = 0.f;
    for (int k = 0; k < 128; k++) {
        float4 e = *(float4*)&sE[k * 128 + lane * 4];
        #pragma unroll
        for (int c = 0; c < 16; c++) {
            float a = sA[(c0 + c) * 128 + k];  // broadcast
            accT[c][0] += a * e.x; accT[c][1] += a * e.y;
            accT[c][2] += a * e.z; accT[c][3] += a * e.w;
        }
    }
    float4 r4 = *(float4*)&sR[lane * 4];
    #pragma unroll
    for (int c = 0; c < 16; c++) {
        float4 a4 = *(float4*)&sA[(c0 + c) * 128 + lane * 4];
        float l2 = accT[c][0] * a4.x + accT[c][1] * a4.y + accT[c][2] * a4.z + accT[c][3] * a4.w;
        float l1 = r4.x * a4.x + r4.y * a4.y + r4.z * a4.z + r4.w * a4.w;
        #pragma unroll
        for (int o = 16; o; o >>= 1) {
            l1 += __shfl_xor_sync(0xffffffffu, l1, o);
            l2 += __shfl_xor_sync(0xffffffffu, l2, o);
        }
        if (lane == 0) {
            g_part1[b * CC + c0 + c] = l1;
            g_part2[b * CC + c0 + c] = l2;
        }
    }
}

// ---- kernel 4: finalize scale/shift -----------------------------------------
__global__ void k_stats2(const float* __restrict__ gamma,
                         const float* __restrict__ bn_w,
                         const float* __restrict__ bn_b) {
    int c = threadIdx.x;
    float a1 = 0.f, a2 = 0.f;
    #pragma unroll
    for (int b = 0; b < BB; b++) { a1 += g_part1[b * CC + c]; a2 += g_part2[b * CC + c]; }
    float g = gamma[0];
    float invN = 1.f / (float)((size_t)BB * HW);
    float mean = g * a1 * invN;
    float ey2 = g * g * a2 * invN;
    float rstd = rsqrtf(ey2 - mean * mean + 1e-5f);
    float w = bn_w[c];
    g_scale[c] = g * rstd * w;
    g_shift[c] = bn_b[c] - mean * rstd * w;
}

// ---- kernel 5: attn limbs with scale folded ---------------------------------
__global__ void k_alimb() {
    int b = blockIdx.x, j = threadIdx.x;
    int half = j >> 6, jl = j & 63;
    for (int i = 0; i < 128; i++) {
        float v = g_attn[((size_t)(b * CC + i)) * CC + j] * g_scale[i];
        __nv_bfloat16 a0 = __float2bfloat16_rn(v);
        __nv_bfloat16 a1 = __float2bfloat16_rn(v - __bfloat162float(a0));
        g_al[(((size_t)(b * 2 + 0) * 2 + half) * CC + i) * 64 + jl] = a0;
        g_al[(((size_t)(b * 2 + 1) * 2 + half) * CC + i) * 64 + jl] = a1;
    }
}

// ---- kernel 6: out GEMM, persistent 128 CTAs, hoisted A fragments -----------
__global__ void __launch_bounds__(256) k_out_mma(const float* __restrict__ x,
                                                 float* __restrict__ out) {
    extern __shared__ char smraw[];
    char* sm = (char*)(((unsigned long long)smraw + 1023) & ~1023ULL);
    unsigned sb = smem_u32(sm);
    float* stage = (float*)(sm + 163840);  // 128 x 68 floats
    int t = threadIdx.x, lane = t & 31, wid = t >> 5;
    int nb = blockIdx.x, b = blockIdx.y;   // nb: 8 chunks of 2048 cols
    int wm = (wid >> 1) * 32, wn = (wid & 1) * 32;  // 4m x 2n warps

    // A limb tiles (iter-invariant): 4 x 16KB at sb
    #pragma unroll
    for (int i = 0; i < 16; i++) {
        int idx = t + 256 * i;
        int limb = idx >> 11, rem = idx & 2047, half = rem >> 10, r2 = rem & 1023;
        int row = r2 >> 3, part = r2 & 7;
        const void* src = g_al + (((size_t)(b * 2 + limb) * 2 + half) * CC + row) * 64 + part * 8;
        CPA(sb + (limb * 2 + half) * 16384 + swz((unsigned)(row * 128 + part * 16)), src);
    }

    // B ring: 3 stages x 32KB at sb + 65536
    #define O_LOAD(it) do { \
        int _stg = (it) % 3; \
        size_t _nbase = (size_t)nb * 2048 + (it) * 64; \
        _Pragma("unroll") \
        for (int _i = 0; _i < 8; _i++) { \
            int _idx = t + 256 * _i; \
            int _limb = _idx >> 10, _rem = _idx & 1023, _row = _rem >> 3, _part = _rem & 7; \
            const __nv_bfloat16* _L = _limb ? g_q1 : g_q0; \
            const void* _src = _L + ((size_t)(b * CC + _row)) * HW + _nbase + _part * 8; \
            CPA(sb + 65536 + _stg * 32768 + _limb * 16384 + swz((unsigned)(_row * 128 + _part * 16)), _src); \
        } \
        CPA_COMMIT(); \
    } while (0)

    O_LOAD(0);   // group 0: A tiles + B chunk 0
    O_LOAD(1);   // group 1: B chunk 1
    CPA_WAIT1(); // A + chunk 0 ready
    __syncthreads();

    // hoist all A fragments into registers (8 ksp x 2 mt x 2 limbs x 4 regs)
    unsigned A0h[8][2][4], A1h[8][2][4];
    #pragma unroll
    for (int ksp = 0; ksp < 8; ksp++) {
        int jhalf = ksp >> 2;
        unsigned kb = (unsigned)((ksp & 3) * 32 + (lane >> 4) * 16);
        #pragma unroll
        for (int mt = 0; mt < 2; mt++) {
            unsigned off = swz((unsigned)((wm + mt * 16 + (lane & 15)) * 128) + kb);
            ldsm4(sb + (0 * 2 + jhalf) * 16384 + off, A0h[ksp][mt]);
            ldsm4(sb + (1 * 2 + jhalf) * 16384 + off, A1h[ksp][mt]);
        }
    }

    for (int it = 0; it < 32; it++) {
        if (it) {
            if (it < 31) CPA_WAIT1(); else CPA_WAIT0();
            __syncthreads();  // chunk it ready; ring slot (it+2)%3 free; stage free
        }
        if (it + 2 < 32) O_LOAD(it + 2);

        float acc[2][4][4];
        #pragma unroll
        for (int mt = 0; mt < 2; mt++)
            #pragma unroll
            for (int nf = 0; nf < 4; nf++)
                #pragma unroll
                for (int c = 0; c < 4; c++) acc[mt][nf][c] = 0.f;

        unsigned Bt0 = sb + 65536 + (it % 3) * 32768;
        unsigned Bt1 = Bt0 + 16384;
        #pragma unroll
        for (int ksp = 0; ksp < 8; ksp++) {
            int jrow = ksp * 16 + ((lane >> 3) & 1) * 8 + (lane & 7);
            unsigned B0[2][4], B1[2][4];
            #pragma unroll
            for (int nt = 0; nt < 2; nt++) {
                int ncol = wn + nt * 16 + ((lane >> 4) & 1) * 8;
                unsigned offb = swz((unsigned)(jrow * 128 + ncol * 2));
                ldsm4t(Bt0 + offb, B0[nt]);
                ldsm4t(Bt1 + offb, B1[nt]);
            }
            #pragma unroll
            for (int mt = 0; mt < 2; mt++)
                #pragma unroll
                for (int nt = 0; nt < 2; nt++)
                    #pragma unroll
                    for (int s = 0; s < 2; s++) {
                        float* c = acc[mt][nt * 2 + s];
                        mma16816(c, A0h[ksp][mt], B0[nt][s * 2], B0[nt][s * 2 + 1]);
                        mma16816(c, A0h[ksp][mt], B1[nt][s * 2], B1[nt][s * 2 + 1]);
                        mma16816(c, A1h[ksp][mt], B0[nt][s * 2], B0[nt][s * 2 + 1]);
                    }
        }

        int g = lane >> 2, tg = lane & 3;
        #pragma unroll
        for (int mt = 0; mt < 2; mt++)
            #pragma unroll
            for (int nf = 0; nf < 4; nf++) {
                int i0 = wm + mt * 16 + g, col = wn + nf * 8 + tg * 2;
                *(float2*)&stage[i0 * 68 + col] = make_float2(acc[mt][nf][0], acc[mt][nf][1]);
                *(float2*)&stage[(i0 + 8) * 68 + col] = make_float2(acc[mt][nf][2], acc[mt][nf][3]);
            }
        __syncthreads();

        size_t gbase = (size_t)b * CC * HW + (size_t)nb * 2048 + it * 64;
        #pragma unroll
        for (int r = 0; r < 8; r++) {
            int idx = t + 256 * r;
            int i = idx >> 4, n4 = (idx & 15) * 4;
            float4 v = *(float4*)&stage[i * 68 + n4];
            float sh = g_shift[i];
            size_t o = gbase + (size_t)i * HW + n4;
            float4 xv = *(const float4*)(x + o);
            *(float4*)(out + o) = make_float4(v.x + sh + xv.x, v.y + sh + xv.y,
                                              v.z + sh + xv.z, v.w + sh + xv.w);
        }
    }
    #undef O_LOAD
}

extern "C" void kernel_launch(void* const* d_in, const int* in_sizes, int n_in,
                              void* d_out, int out_size) {
    const float* x = (const float*)d_in[0];
    const float* gamma = (const float*)d_in[1];
    const float* bn_w = (const float*)d_in[2];
    const float* bn_b = (const float*)d_in[3];
    float* out = (float*)d_out;

    int smE = 1024 + 2 * 32768;                                  // 66.5 KB
    int smS = (16384 + 16384 + 128) * 4;                          // 128.5 KB
    int smO = 1024 + 65536 + 3 * 32768 + 128 * 68 * 4;            // ~195 KB
    cudaFuncSetAttribute(k_energy_mma, cudaFuncAttributeMaxDynamicSharedMemorySize, smE);
    cudaFuncSetAttribute(k_stats1, cudaFuncAttributeMaxDynamicSharedMemorySize, smS);
    cudaFuncSetAttribute(k_out_mma, cudaFuncAttributeMaxDynamicSharedMemorySize, smO);

    k_limbs_rs<<<dim3(CC, BB), 256>>>(x);            // 0
    k_energy_mma<<<dim3(KS1, BB), 256, smE>>>();     // 1
    k_redsoft<<<dim3(4, BB), 256>>>();               // 2
    k_stats1<<<BB, 256, smS>>>();                    // 3  (ncu capture slot)
    k_stats2<<<1, 128>>>(gamma, bn_w, bn_b);         // 4
    k_alimb<<<BB, 128>>>();                          // 5
    k_out_mma<<<dim3(8, BB), 256, smO>>>(x, out);    // 6
}

// round 9
// speedup vs baseline: 2.3959x; 1.1578x over previous
#include <cuda_runtime.h>
#include <cuda_bf16.h>
#include <math.h>

#define BB 16
#define CC 128
#define HW 16384
#define KS1 8
#define KSEG (HW / KS1)  // 2048

__device__ float g_energy[BB * CC * CC];
__device__ float g_epF[BB * KS1 * CC * CC];
__device__ float g_epG[BB * KS1 * CC * CC];
__device__ float g_attn[BB * CC * CC];
__device__ float g_rowsum[BB * CC];
__device__ float g_part1[BB * CC];
__device__ float g_part2[BB * CC];
__device__ float g_scale[CC];
__device__ float g_shift[CC];
__device__ __nv_bfloat16 g_q0[(size_t)BB * CC * HW];
__device__ __nv_bfloat16 g_q1[(size_t)BB * CC * HW];
// attn limbs (scale folded), layout [b][limb][jhalf][i][64]
__device__ __nv_bfloat16 g_al[(size_t)BB * 2 * 2 * CC * 64];

__device__ __forceinline__ unsigned smem_u32(const void* p) {
    unsigned a;
    asm("{ .reg .u64 t; cvta.to.shared.u64 t, %1; cvt.u32.u64 %0, t; }" : "=r"(a) : "l"(p));
    return a;
}
__device__ __forceinline__ unsigned swz(unsigned o) { return o ^ ((o >> 3) & 0x70); }

#define CPA(dst, src) asm volatile("cp.async.ca.shared.global [%0], [%1], 16;" :: "r"(dst), "l"(src))
#define CPA_COMMIT()  asm volatile("cp.async.commit_group;" ::: "memory")
#define CPA_WAIT0()   asm volatile("cp.async.wait_group 0;" ::: "memory")
#define CPA_WAIT1()   asm volatile("cp.async.wait_group 1;" ::: "memory")

__device__ __forceinline__ void ldsm4(unsigned a, unsigned r[4]) {
    asm volatile("ldmatrix.sync.aligned.m8n8.x4.shared.b16 {%0,%1,%2,%3}, [%4];"
                 : "=r"(r[0]), "=r"(r[1]), "=r"(r[2]), "=r"(r[3]) : "r"(a));
}
__device__ __forceinline__ void ldsm4t(unsigned a, unsigned r[4]) {
    asm volatile("ldmatrix.sync.aligned.m8n8.x4.trans.shared.b16 {%0,%1,%2,%3}, [%4];"
                 : "=r"(r[0]), "=r"(r[1]), "=r"(r[2]), "=r"(r[3]) : "r"(a));
}
__device__ __forceinline__ void mma16816(float c[4], const unsigned a[4], unsigned b0, unsigned b1) {
    asm volatile("mma.sync.aligned.m16n8k16.row.col.f32.bf16.bf16.f32 "
                 "{%0,%1,%2,%3}, {%4,%5,%6,%7}, {%8,%9}, {%0,%1,%2,%3};"
                 : "+f"(c[0]), "+f"(c[1]), "+f"(c[2]), "+f"(c[3])
                 : "r"(a[0]), "r"(a[1]), "r"(a[2]), "r"(a[3]), "r"(b0), "r"(b1));
}

// ---- kernel 0: fused bf16 2-limb decomposition + rowsum ---------------------
__global__ void k_limbs_rs(const float* __restrict__ x) {
    int j = blockIdx.x, b = blockIdx.y, t = threadIdx.x;
    size_t rb = ((size_t)(b * CC + j)) * HW;
    const float4* p = (const float4*)(x + rb);
    __nv_bfloat162* o0 = (__nv_bfloat162*)(g_q0 + rb);
    __nv_bfloat162* o1 = (__nv_bfloat162*)(g_q1 + rb);
    float s = 0.f;
    #pragma unroll 4
    for (int i = t; i < HW / 4; i += 256) {
        float4 v = p[i];
        s += (v.x + v.y) + (v.z + v.w);
        float f[4] = {v.x, v.y, v.z, v.w};
        __nv_bfloat16 l0[4], l1[4];
        #pragma unroll
        for (int c = 0; c < 4; c++) {
            l0[c] = __float2bfloat16_rn(f[c]);
            l1[c] = __float2bfloat16_rn(f[c] - __bfloat162float(l0[c]));
        }
        o0[i * 2] = __nv_bfloat162(l0[0], l0[1]);
        o0[i * 2 + 1] = __nv_bfloat162(l0[2], l0[3]);
        o1[i * 2] = __nv_bfloat162(l1[0], l1[1]);
        o1[i * 2 + 1] = __nv_bfloat162(l1[2], l1[3]);
    }
    __shared__ float red[256];
    red[t] = s;
    __syncthreads();
    for (int w = 128; w > 0; w >>= 1) {
        if (t < w) red[t] += red[t + w];
        __syncthreads();
    }
    if (t == 0) g_rowsum[b * CC + j] = red[0];
}

// ---- kernel 1: energy via mma.sync: F = q0 q0^T, G = q0 q1^T ----------------
__global__ void __launch_bounds__(256) k_energy_mma() {
    extern __shared__ char smraw[];
    char* sm = (char*)(((unsigned long long)smraw + 1023) & ~1023ULL);
    unsigned sb = smem_u32(sm);
    int t = threadIdx.x, lane = t & 31, wid = t >> 5;
    int ks = blockIdx.x, b = blockIdx.y;
    size_t rowbase = (size_t)b * CC * HW + (size_t)ks * KSEG;
    int wm = (wid >> 2) * 64, wn = (wid & 3) * 32;

    float accF[4][4][4], accG[4][4][4];
    #pragma unroll
    for (int mt = 0; mt < 4; mt++)
        #pragma unroll
        for (int nt = 0; nt < 4; nt++)
            #pragma unroll
            for (int c = 0; c < 4; c++) { accF[mt][nt][c] = 0.f; accG[mt][nt][c] = 0.f; }

    #define E_LOAD(ch) do { \
        int _buf = (ch) & 1; \
        unsigned _db = sb + _buf * 32768; \
        _Pragma("unroll") \
        for (int _i = 0; _i < 8; _i++) { \
            int _idx = t + 256 * _i; \
            int _limb = _idx >> 10, _rem = _idx & 1023, _row = _rem >> 3, _part = _rem & 7; \
            const __nv_bfloat16* _L = _limb ? g_q1 : g_q0; \
            const void* _src = _L + rowbase + (size_t)_row * HW + (ch) * 64 + _part * 8; \
            CPA(_db + _limb * 16384 + swz(_row * 128 + _part * 16), _src); \
        } \
        CPA_COMMIT(); \
    } while (0)

    E_LOAD(0);
    for (int ch = 0; ch < 32; ch++) {
        if (ch < 31) { E_LOAD(ch + 1); CPA_WAIT1(); }
        else CPA_WAIT0();
        __syncthreads();
        unsigned b0t = sb + (ch & 1) * 32768;
        unsigned b1t = b0t + 16384;
        #pragma unroll
        for (int kk = 0; kk < 4; kk++) {
            int kbyte = kk * 32;
            unsigned A[4][4];
            #pragma unroll
            for (int mt = 0; mt < 4; mt++) {
                unsigned off = swz((unsigned)((wm + mt * 16 + (lane & 15)) * 128 + kbyte + (lane >> 4) * 16));
                ldsm4(b0t + off, A[mt]);
            }
            unsigned B0[2][4], B1[2][4];
            #pragma unroll
            for (int nt = 0; nt < 2; nt++) {
                int row = wn + nt * 16 + ((lane >> 4) & 1) * 8 + (lane & 7);
                int kb = kbyte + ((lane >> 3) & 1) * 16;
                unsigned off = swz((unsigned)(row * 128 + kb));
                ldsm4(b0t + off, B0[nt]);
                ldsm4(b1t + off, B1[nt]);
            }
            #pragma unroll
            for (int mt = 0; mt < 4; mt++)
                #pragma unroll
                for (int nt = 0; nt < 2; nt++)
                    #pragma unroll
                    for (int s = 0; s < 2; s++) {
                        mma16816(accF[mt][nt * 2 + s], A[mt], B0[nt][s * 2], B0[nt][s * 2 + 1]);
                        mma16816(accG[mt][nt * 2 + s], A[mt], B1[nt][s * 2], B1[nt][s * 2 + 1]);
                    }
        }
        __syncthreads();
    }
    #undef E_LOAD

    size_t pbase = ((size_t)(b * KS1 + ks)) * CC * CC;
    int g = lane >> 2, tg = lane & 3;
    #pragma unroll
    for (int mt = 0; mt < 4; mt++)
        #pragma unroll
        for (int nt = 0; nt < 4; nt++) {
            int i0 = wm + mt * 16 + g, j = wn + nt * 8 + tg * 2;
            *(float2*)(g_epF + pbase + (size_t)i0 * CC + j) = make_float2(accF[mt][nt][0], accF[mt][nt][1]);
            *(float2*)(g_epF + pbase + (size_t)(i0 + 8) * CC + j) = make_float2(accF[mt][nt][2], accF[mt][nt][3]);
            *(float2*)(g_epG + pbase + (size_t)i0 * CC + j) = make_float2(accG[mt][nt][0], accG[mt][nt][1]);
            *(float2*)(g_epG + pbase + (size_t)(i0 + 8) * CC + j) = make_float2(accG[mt][nt][2], accG[mt][nt][3]);
        }
}

// ---- kernel 2: fused E = F + G + G^T  AND softmax ---------------------------
__global__ void k_redsoft() {  // grid (4, BB), block 256
    int islab = blockIdx.x, b = blockIdx.y, t = threadIdx.x;
    __shared__ float sGT[32][132];
    #pragma unroll
    for (int r = 0; r < 4; r++) {
        int idx = t + 256 * r;
        int j = idx >> 3, c4 = idx & 7;
        float4 s = make_float4(0.f, 0.f, 0.f, 0.f);
        #pragma unroll
        for (int ks = 0; ks < KS1; ks++) {
            float4 v = *(const float4*)(g_epG + (((size_t)(b * KS1 + ks) * CC + j)) * CC + islab * 32 + c4 * 4);
            s.x += v.x; s.y += v.y; s.z += v.z; s.w += v.w;
        }
        sGT[c4 * 4 + 0][j] = s.x;
        sGT[c4 * 4 + 1][j] = s.y;
        sGT[c4 * 4 + 2][j] = s.z;
        sGT[c4 * 4 + 3][j] = s.w;
    }
    __syncthreads();
    #pragma unroll
    for (int r = 0; r < 4; r++) {
        int idx = t + 256 * r;
        int il = idx >> 5, j4 = idx & 31;  // warp-aligned: one row per warp
        int i = islab * 32 + il;
        float4 f = make_float4(0.f, 0.f, 0.f, 0.f);
        #pragma unroll
        for (int ks = 0; ks < KS1; ks++) {
            size_t o = (((size_t)(b * KS1 + ks) * CC + i)) * CC + j4 * 4;
            float4 vf = *(const float4*)(g_epF + o);
            float4 vg = *(const float4*)(g_epG + o);
            f.x += vf.x + vg.x; f.y += vf.y + vg.y; f.z += vf.z + vg.z; f.w += vf.w + vg.w;
        }
        float4 gt = *(const float4*)&sGT[il][j4 * 4];
        float4 e = make_float4(f.x + gt.x, f.y + gt.y, f.z + gt.z, f.w + gt.w);
        *(float4*)(g_energy + ((size_t)(b * CC + i)) * CC + j4 * 4) = e;
        float mx = fmaxf(fmaxf(e.x, e.y), fmaxf(e.z, e.w));
        #pragma unroll
        for (int o = 16; o; o >>= 1) mx = fmaxf(mx, __shfl_xor_sync(0xffffffffu, mx, o));
        float e0 = mx - e.x, e1 = mx - e.y, e2 = mx - e.z, e3 = mx - e.w;
        float m2 = fmaxf(fmaxf(e0, e1), fmaxf(e2, e3));
        #pragma unroll
        for (int o = 16; o; o >>= 1) m2 = fmaxf(m2, __shfl_xor_sync(0xffffffffu, m2, o));
        float p0 = expf(e0 - m2), p1 = expf(e1 - m2), p2 = expf(e2 - m2), p3 = expf(e3 - m2);
        float s = (p0 + p1) + (p2 + p3);
        #pragma unroll
        for (int o = 16; o; o >>= 1) s += __shfl_xor_sync(0xffffffffu, s, o);
        float inv = 1.f / s;
        *(float4*)(g_attn + ((size_t)(b * CC + i)) * CC + j4 * 4) =
            make_float4(p0 * inv, p1 * inv, p2 * inv, p3 * inv);
    }
}

// ---- kernel 3: BN stats partials, grid (8 cslabs, BB) -----------------------
__global__ void __launch_bounds__(256) k_stats1() {
    int cs = blockIdx.x, b = blockIdx.y, t = threadIdx.x, lane = t & 31, w = t >> 5;
    extern __shared__ float sms[];
    float* sE = sms;                  // [k=128][j=128]
    float* sA = sms + 16384;          // [16][128]
    float* sR = sms + 16384 + 2048;   // [128]
    const float4* Eg = (const float4*)(g_energy + (size_t)b * CC * CC);
    for (int i = t; i < 4096; i += 256) ((float4*)sE)[i] = Eg[i];
    const float4* Ag = (const float4*)(g_attn + ((size_t)b * CC + cs * 16) * CC);
    for (int i = t; i < 512; i += 256) ((float4*)sA)[i] = Ag[i];
    if (t < 32) ((float4*)sR)[t] = ((const float4*)(g_rowsum + b * CC))[t];
    __syncthreads();

    // warp w handles channels cs*16 + w*2 + {0,1}
    float accT[2][4];
    #pragma unroll
    for (int c = 0; c < 2; c++)
        #pragma unroll
        for (int q = 0; q < 4; q++) accT[c][q] = 0.f;
    for (int k = 0; k < 128; k++) {
        float4 e = *(float4*)&sE[k * 128 + lane * 4];
        #pragma unroll
        for (int c = 0; c < 2; c++) {
            float a = sA[(w * 2 + c) * 128 + k];
            accT[c][0] += a * e.x; accT[c][1] += a * e.y;
            accT[c][2] += a * e.z; accT[c][3] += a * e.w;
        }
    }
    float4 r4 = *(float4*)&sR[lane * 4];
    #pragma unroll
    for (int c = 0; c < 2; c++) {
        float4 a4 = *(float4*)&sA[(w * 2 + c) * 128 + lane * 4];
        float l2 = accT[c][0] * a4.x + accT[c][1] * a4.y + accT[c][2] * a4.z + accT[c][3] * a4.w;
        float l1 = r4.x * a4.x + r4.y * a4.y + r4.z * a4.z + r4.w * a4.w;
        #pragma unroll
        for (int o = 16; o; o >>= 1) {
            l1 += __shfl_xor_sync(0xffffffffu, l1, o);
            l2 += __shfl_xor_sync(0xffffffffu, l2, o);
        }
        if (lane == 0) {
            g_part1[b * CC + cs * 16 + w * 2 + c] = l1;
            g_part2[b * CC + cs * 16 + w * 2 + c] = l2;
        }
    }
}

// ---- kernel 4: finalize scale/shift -----------------------------------------
__global__ void k_stats2(const float* __restrict__ gamma,
                         const float* __restrict__ bn_w,
                         const float* __restrict__ bn_b) {
    int c = threadIdx.x;
    float a1 = 0.f, a2 = 0.f;
    #pragma unroll
    for (int b = 0; b < BB; b++) { a1 += g_part1[b * CC + c]; a2 += g_part2[b * CC + c]; }
    float g = gamma[0];
    float invN = 1.f / (float)((size_t)BB * HW);
    float mean = g * a1 * invN;
    float ey2 = g * g * a2 * invN;
    float rstd = rsqrtf(ey2 - mean * mean + 1e-5f);
    float w = bn_w[c];
    g_scale[c] = g * rstd * w;
    g_shift[c] = bn_b[c] - mean * rstd * w;
}

// ---- kernel 5: attn limbs with scale folded ---------------------------------
__global__ void k_alimb() {
    int b = blockIdx.x, j = threadIdx.x;
    int half = j >> 6, jl = j & 63;
    for (int i = 0; i < 128; i++) {
        float v = g_attn[((size_t)(b * CC + i)) * CC + j] * g_scale[i];
        __nv_bfloat16 a0 = __float2bfloat16_rn(v);
        __nv_bfloat16 a1 = __float2bfloat16_rn(v - __bfloat162float(a0));
        g_al[(((size_t)(b * 2 + 0) * 2 + half) * CC + i) * 64 + jl] = a0;
        g_al[(((size_t)(b * 2 + 1) * 2 + half) * CC + i) * 64 + jl] = a1;
    }
}

// ---- kernel 6: out GEMM, persistent, x prefetched via cp.async --------------
// smem map (128B-aligned base): A 0..64K | B ring 64K..128K (2x32K)
//                              | X ring 128K..192K (2x32K) | stage 192K..226K
__global__ void __launch_bounds__(256) k_out_mma(const float* __restrict__ x,
                                                 float* __restrict__ out) {
    extern __shared__ char smraw[];
    char* sm = (char*)(((unsigned long long)smraw + 127) & ~127ULL);
    unsigned sb = smem_u32(sm);
    float* stage = (float*)(sm + 196608);  // 128 x 68 floats
    int t = threadIdx.x, lane = t & 31, wid = t >> 5;
    int nb = blockIdx.x, b = blockIdx.y;   // nb: 8 chunks of 2048 cols
    int wm = (wid >> 1) * 32, wn = (wid & 1) * 32;  // 4m x 2n warps
    size_t xrow = (size_t)b * CC * HW;

    // A limb tiles (iter-invariant): 4 x 16KB at sb
    #pragma unroll
    for (int i = 0; i < 16; i++) {
        int idx = t + 256 * i;
        int limb = idx >> 11, rem = idx & 2047, half = rem >> 10, r2 = rem & 1023;
        int row = r2 >> 3, part = r2 & 7;
        const void* src = g_al + (((size_t)(b * 2 + limb) * 2 + half) * CC + row) * 64 + part * 8;
        CPA(sb + (limb * 2 + half) * 16384 + swz((unsigned)(row * 128 + part * 16)), src);
    }

    // per-iter load: B limbs (2x16KB) + X fp32 tile (32KB), one commit group
    #define O_LOAD(it) do { \
        int _stg = (it) & 1; \
        size_t _nbase = (size_t)nb * 2048 + (it) * 64; \
        _Pragma("unroll") \
        for (int _i = 0; _i < 8; _i++) { \
            int _idx = t + 256 * _i; \
            int _limb = _idx >> 10, _rem = _idx & 1023, _row = _rem >> 3, _part = _rem & 7; \
            const __nv_bfloat16* _L = _limb ? g_q1 : g_q0; \
            const void* _src = _L + ((size_t)(b * CC + _row)) * HW + _nbase + _part * 8; \
            CPA(sb + 65536 + _stg * 32768 + _limb * 16384 + swz((unsigned)(_row * 128 + _part * 16)), _src); \
        } \
        _Pragma("unroll") \
        for (int _i = 0; _i < 8; _i++) { \
            int _idx = t + 256 * _i; \
            int _row = _idx >> 4, _c4 = _idx & 15; \
            const void* _src = x + xrow + (size_t)_row * HW + _nbase + _c4 * 4; \
            CPA(sb + 131072 + _stg * 32768 + _row * 256 + _c4 * 16, _src); \
        } \
        CPA_COMMIT(); \
    } while (0)

    O_LOAD(0);      // group 0 includes A tiles
    CPA_WAIT0();
    __syncthreads();

    // hoist all A fragments into registers
    unsigned A0h[8][2][4], A1h[8][2][4];
    #pragma unroll
    for (int ksp = 0; ksp < 8; ksp++) {
        int jhalf = ksp >> 2;
        unsigned kb = (unsigned)((ksp & 3) * 32 + (lane >> 4) * 16);
        #pragma unroll
        for (int mt = 0; mt < 2; mt++) {
            unsigned off = swz((unsigned)((wm + mt * 16 + (lane & 15)) * 128) + kb);
            ldsm4(sb + (0 * 2 + jhalf) * 16384 + off, A0h[ksp][mt]);
            ldsm4(sb + (1 * 2 + jhalf) * 16384 + off, A1h[ksp][mt]);
        }
    }

    for (int it = 0; it < 32; it++) {
        if (it + 1 < 32) O_LOAD(it + 1);  // into other buffer (safe: prior epilogue synced)

        float acc[2][4][4];
        #pragma unroll
        for (int mt = 0; mt < 2; mt++)
            #pragma unroll
            for (int nf = 0; nf < 4; nf++)
                #pragma unroll
                for (int c = 0; c < 4; c++) acc[mt][nf][c] = 0.f;

        unsigned Bt0 = sb + 65536 + (it & 1) * 32768;
        unsigned Bt1 = Bt0 + 16384;
        #pragma unroll
        for (int ksp = 0; ksp < 8; ksp++) {
            int jrow = ksp * 16 + ((lane >> 3) & 1) * 8 + (lane & 7);
            unsigned B0[2][4], B1[2][4];
            #pragma unroll
            for (int nt = 0; nt < 2; nt++) {
                int ncol = wn + nt * 16 + ((lane >> 4) & 1) * 8;
                unsigned offb = swz((unsigned)(jrow * 128 + ncol * 2));
                ldsm4t(Bt0 + offb, B0[nt]);
                ldsm4t(Bt1 + offb, B1[nt]);
            }
            #pragma unroll
            for (int mt = 0; mt < 2; mt++)
                #pragma unroll
                for (int nt = 0; nt < 2; nt++)
                    #pragma unroll
                    for (int s = 0; s < 2; s++) {
                        float* c = acc[mt][nt * 2 + s];
                        mma16816(c, A0h[ksp][mt], B0[nt][s * 2], B0[nt][s * 2 + 1]);
                        mma16816(c, A0h[ksp][mt], B1[nt][s * 2], B1[nt][s * 2 + 1]);
                        mma16816(c, A1h[ksp][mt], B0[nt][s * 2], B0[nt][s * 2 + 1]);
                    }
        }

        int g = lane >> 2, tg = lane & 3;
        #pragma unroll
        for (int mt = 0; mt < 2; mt++)
            #pragma unroll
            for (int nf = 0; nf < 4; nf++) {
                int i0 = wm + mt * 16 + g, col = wn + nf * 8 + tg * 2;
                *(float2*)&stage[i0 * 68 + col] = make_float2(acc[mt][nf][0], acc[mt][nf][1]);
                *(float2*)&stage[(i0 + 8) * 68 + col] = make_float2(acc[mt][nf][2], acc[mt][nf][3]);
            }
        __syncthreads();

        const float* sx = (const float*)(sm + 131072 + (it & 1) * 32768);
        size_t gbase = xrow + (size_t)nb * 2048 + it * 64;
        #pragma unroll
        for (int r = 0; r < 8; r++) {
            int idx = t + 256 * r;
            int i = idx >> 4, n4 = (idx & 15) * 4;
            float4 v = *(float4*)&stage[i * 68 + n4];
            float4 xv = *(const float4*)&sx[i * 64 + n4];
            float sh = g_shift[i];
            size_t o = gbase + (size_t)i * HW + n4;
            *(float4*)(out + o) = make_float4(v.x + sh + xv.x, v.y + sh + xv.y,
                                              v.z + sh + xv.z, v.w + sh + xv.w);
        }
        if (it + 1 < 32) CPA_WAIT0();
        __syncthreads();  // stage + buffers reusable; next chunk ready
    }
    #undef O_LOAD
}

extern "C" void kernel_launch(void* const* d_in, const int* in_sizes, int n_in,
                              void* d_out, int out_size) {
    const float* x = (const float*)d_in[0];
    const float* gamma = (const float*)d_in[1];
    const float* bn_w = (const float*)d_in[2];
    const float* bn_b = (const float*)d_in[3];
    float* out = (float*)d_out;

    int smE = 1024 + 2 * 32768;                       // 66.5 KB
    int smS = (16384 + 2048 + 128) * 4;               // 74.2 KB
    int smO = 196608 + 128 * 68 * 4 + 256;            // ~226 KB
    cudaFuncSetAttribute(k_energy_mma, cudaFuncAttributeMaxDynamicSharedMemorySize, smE);
    cudaFuncSetAttribute(k_stats1, cudaFuncAttributeMaxDynamicSharedMemorySize, smS);
    cudaFuncSetAttribute(k_out_mma, cudaFuncAttributeMaxDynamicSharedMemorySize, smO);

    k_limbs_rs<<<dim3(CC, BB), 256>>>(x);            // 0
    k_energy_mma<<<dim3(KS1, BB), 256, smE>>>();     // 1
    k_redsoft<<<dim3(4, BB), 256>>>();               // 2
    k_stats1<<<dim3(8, BB), 256, smS>>>();           // 3  (ncu capture slot)
    k_stats2<<<1, 128>>>(gamma, bn_w, bn_b);         // 4
    k_alimb<<<BB, 128>>>();                          // 5
    k_out_mma<<<dim3(8, BB), 256, smO>>>(x, out);    // 6
}

// round 10
// speedup vs baseline: 2.7255x; 1.1376x over previous
#include <cuda_runtime.h>
#include <cuda_bf16.h>
#include <math.h>

#define BB 16
#define CC 128
#define HW 16384
#define KS1 8
#define KSEG (HW / KS1)  // 2048

__device__ float g_energy[BB * CC * CC];
__device__ float g_epF[BB * KS1 * CC * CC];
__device__ float g_epG[BB * KS1 * CC * CC];
__device__ float g_attn[BB * CC * CC];
__device__ float g_rowsum[BB * CC];
__device__ float g_rspart[BB * KS1 * CC];
__device__ float g_part1[BB * CC];
__device__ float g_part2[BB * CC];
__device__ float g_scale[CC];
__device__ float g_shift[CC];
// attn limbs (scale folded), layout [b][limb][jhalf][i][64]
__device__ __nv_bfloat16 g_al[(size_t)BB * 2 * 2 * CC * 64];

__device__ __forceinline__ unsigned smem_u32(const void* p) {
    unsigned a;
    asm("{ .reg .u64 t; cvta.to.shared.u64 t, %1; cvt.u32.u64 %0, t; }" : "=r"(a) : "l"(p));
    return a;
}
__device__ __forceinline__ unsigned swz(unsigned o) { return o ^ ((o >> 3) & 0x70); }

#define CPA(dst, src) asm volatile("cp.async.ca.shared.global [%0], [%1], 16;" :: "r"(dst), "l"(src))
#define CPA_COMMIT()  asm volatile("cp.async.commit_group;" ::: "memory")
#define CPA_WAIT0()   asm volatile("cp.async.wait_group 0;" ::: "memory")
#define CPA_WAIT1()   asm volatile("cp.async.wait_group 1;" ::: "memory")

__device__ __forceinline__ void ldsm4(unsigned a, unsigned r[4]) {
    asm volatile("ldmatrix.sync.aligned.m8n8.x4.shared.b16 {%0,%1,%2,%3}, [%4];"
                 : "=r"(r[0]), "=r"(r[1]), "=r"(r[2]), "=r"(r[3]) : "r"(a));
}
__device__ __forceinline__ void ldsm4t(unsigned a, unsigned r[4]) {
    asm volatile("ldmatrix.sync.aligned.m8n8.x4.trans.shared.b16 {%0,%1,%2,%3}, [%4];"
                 : "=r"(r[0]), "=r"(r[1]), "=r"(r[2]), "=r"(r[3]) : "r"(a));
}
__device__ __forceinline__ void mma16816(float c[4], const unsigned a[4], unsigned b0, unsigned b1) {
    asm volatile("mma.sync.aligned.m16n8k16.row.col.f32.bf16.bf16.f32 "
                 "{%0,%1,%2,%3}, {%4,%5,%6,%7}, {%8,%9}, {%0,%1,%2,%3};"
                 : "+f"(c[0]), "+f"(c[1]), "+f"(c[2]), "+f"(c[3])
                 : "r"(a[0]), "r"(a[1]), "r"(a[2]), "r"(a[3]), "r"(b0), "r"(b1));
}

// convert 8 fp32 (32B at sp) into two 16B bf16 limb vectors; returns elem sum
__device__ __forceinline__ float conv8(const char* sp, char* d0, char* d1) {
    float4 a = ((const float4*)sp)[0];
    float4 b = ((const float4*)sp)[1];
    float f[8] = {a.x, a.y, a.z, a.w, b.x, b.y, b.z, b.w};
    unsigned u0[4], u1[4];
    #pragma unroll
    for (int k = 0; k < 4; k++) {
        __nv_bfloat16 p0 = __float2bfloat16_rn(f[2 * k]);
        __nv_bfloat16 p1 = __float2bfloat16_rn(f[2 * k + 1]);
        __nv_bfloat16 q0 = __float2bfloat16_rn(f[2 * k] - __bfloat162float(p0));
        __nv_bfloat16 q1 = __float2bfloat16_rn(f[2 * k + 1] - __bfloat162float(p1));
        __nv_bfloat162 v0(p0, p1), v1(q0, q1);
        u0[k] = *(unsigned*)&v0;
        u1[k] = *(unsigned*)&v1;
    }
    *(uint4*)d0 = make_uint4(u0[0], u0[1], u0[2], u0[3]);
    *(uint4*)d1 = make_uint4(u1[0], u1[1], u1[2], u1[3]);
    return ((f[0] + f[1]) + (f[2] + f[3])) + ((f[4] + f[5]) + (f[6] + f[7]));
}

__global__ void k_nop() {}

// ---- energy: fused fp32->limb conversion + F = q0 q0^T, G = q0 q1^T --------
// smem: X staging 2x32KB @0 | limb tiles 2x(16K l0+16K l1) @65536 | s_rs @131072
__global__ void __launch_bounds__(256) k_energy_mma(const float* __restrict__ x) {
    extern __shared__ char smraw[];
    char* sm = (char*)(((unsigned long long)smraw + 1023) & ~1023ULL);
    unsigned sb = smem_u32(sm);
    int t = threadIdx.x, lane = t & 31, wid = t >> 5;
    int ks = blockIdx.x, b = blockIdx.y;
    size_t rowbase = (size_t)b * CC * HW + (size_t)ks * KSEG;
    int wm = (wid >> 2) * 64, wn = (wid & 3) * 32;
    float* s_rs = (float*)(sm + 131072);
    float rsacc[4] = {0.f, 0.f, 0.f, 0.f};

    float accF[4][4][4], accG[4][4][4];
    #pragma unroll
    for (int mt = 0; mt < 4; mt++)
        #pragma unroll
        for (int nt = 0; nt < 4; nt++)
            #pragma unroll
            for (int c = 0; c < 4; c++) { accF[mt][nt][c] = 0.f; accG[mt][nt][c] = 0.f; }

    #define X_LOAD(ch) do { \
        unsigned _db = sb + ((ch) & 1) * 32768; \
        _Pragma("unroll") \
        for (int _i = 0; _i < 8; _i++) { \
            int _idx = t + 256 * _i; \
            int _row = _idx >> 4, _c4 = _idx & 15; \
            CPA(_db + _row * 256 + _c4 * 16, x + rowbase + (size_t)_row * HW + (ch) * 64 + _c4 * 4); \
        } \
        CPA_COMMIT(); \
    } while (0)

    #define X_CONV(ch) do { \
        char* _st = sm + ((ch) & 1) * 32768; \
        char* _lb = sm + 65536 + ((ch) & 1) * 32768; \
        _Pragma("unroll") \
        for (int _i = 0; _i < 4; _i++) { \
            int _idx = t + 256 * _i; \
            int _row = _idx >> 3, _part = _idx & 7; \
            unsigned _so = swz((unsigned)(_row * 128 + _part * 16)); \
            rsacc[_i] += conv8(_st + _row * 256 + _part * 32, _lb + _so, _lb + 16384 + _so); \
        } \
    } while (0)

    X_LOAD(0);
    X_LOAD(1);
    CPA_WAIT1();
    __syncthreads();
    X_CONV(0);
    __syncthreads();

    for (int ch = 0; ch < 32; ch++) {
        if (ch + 2 < 32) X_LOAD(ch + 2);
        if (ch + 1 < 32) {
            if (ch + 2 < 32) CPA_WAIT1(); else CPA_WAIT0();
        }
        __syncthreads();                 // staging(ch+1) visible
        if (ch + 1 < 32) X_CONV(ch + 1); // writes limb buf (ch+1)&1

        unsigned b0t = sb + 65536 + (ch & 1) * 32768;
        unsigned b1t = b0t + 16384;
        #pragma unroll
        for (int kk = 0; kk < 4; kk++) {
            int kbyte = kk * 32;
            unsigned A[4][4];
            #pragma unroll
            for (int mt = 0; mt < 4; mt++) {
                unsigned off = swz((unsigned)((wm + mt * 16 + (lane & 15)) * 128 + kbyte + (lane >> 4) * 16));
                ldsm4(b0t + off, A[mt]);
            }
            unsigned B0[2][4], B1[2][4];
            #pragma unroll
            for (int nt = 0; nt < 2; nt++) {
                int row = wn + nt * 16 + ((lane >> 4) & 1) * 8 + (lane & 7);
                int kb = kbyte + ((lane >> 3) & 1) * 16;
                unsigned off = swz((unsigned)(row * 128 + kb));
                ldsm4(b0t + off, B0[nt]);
                ldsm4(b1t + off, B1[nt]);
            }
            #pragma unroll
            for (int mt = 0; mt < 4; mt++)
                #pragma unroll
                for (int nt = 0; nt < 2; nt++)
                    #pragma unroll
                    for (int s = 0; s < 2; s++) {
                        mma16816(accF[mt][nt * 2 + s], A[mt], B0[nt][s * 2], B0[nt][s * 2 + 1]);
                        mma16816(accG[mt][nt * 2 + s], A[mt], B1[nt][s * 2], B1[nt][s * 2 + 1]);
                    }
        }
        __syncthreads();                 // limbs(ch+1) ready; staging reusable
    }
    #undef X_LOAD
    #undef X_CONV

    // rowsum partials (fixed-order reduce)
    #pragma unroll
    for (int i = 0; i < 4; i++) s_rs[((t + 256 * i) >> 3) * 8 + (t & 7)] = rsacc[i];
    __syncthreads();
    if (t < 128) {
        float s = 0.f;
        #pragma unroll
        for (int k = 0; k < 8; k++) s += s_rs[t * 8 + k];
        g_rspart[(b * KS1 + ks) * CC + t] = s;
    }

    size_t pbase = ((size_t)(b * KS1 + ks)) * CC * CC;
    int g = lane >> 2, tg = lane & 3;
    #pragma unroll
    for (int mt = 0; mt < 4; mt++)
        #pragma unroll
        for (int nt = 0; nt < 4; nt++) {
            int i0 = wm + mt * 16 + g, j = wn + nt * 8 + tg * 2;
            *(float2*)(g_epF + pbase + (size_t)i0 * CC + j) = make_float2(accF[mt][nt][0], accF[mt][nt][1]);
            *(float2*)(g_epF + pbase + (size_t)(i0 + 8) * CC + j) = make_float2(accF[mt][nt][2], accF[mt][nt][3]);
            *(float2*)(g_epG + pbase + (size_t)i0 * CC + j) = make_float2(accG[mt][nt][0], accG[mt][nt][1]);
            *(float2*)(g_epG + pbase + (size_t)(i0 + 8) * CC + j) = make_float2(accG[mt][nt][2], accG[mt][nt][3]);
        }
}

// ---- finish rowsum ----------------------------------------------------------
__global__ void k_rs2() {
    int b = blockIdx.x, j = threadIdx.x;
    float s = 0.f;
    #pragma unroll
    for (int ks = 0; ks < KS1; ks++) s += g_rspart[(b * KS1 + ks) * CC + j];
    g_rowsum[b * CC + j] = s;
}

// ---- fused E = F + G + G^T  AND softmax -------------------------------------
__global__ void k_redsoft() {  // grid (4, BB), block 256
    int islab = blockIdx.x, b = blockIdx.y, t = threadIdx.x;
    __shared__ float sGT[32][132];
    #pragma unroll
    for (int r = 0; r < 4; r++) {
        int idx = t + 256 * r;
        int j = idx >> 3, c4 = idx & 7;
        float4 s = make_float4(0.f, 0.f, 0.f, 0.f);
        #pragma unroll
        for (int ks = 0; ks < KS1; ks++) {
            float4 v = *(const float4*)(g_epG + (((size_t)(b * KS1 + ks) * CC + j)) * CC + islab * 32 + c4 * 4);
            s.x += v.x; s.y += v.y; s.z += v.z; s.w += v.w;
        }
        sGT[c4 * 4 + 0][j] = s.x;
        sGT[c4 * 4 + 1][j] = s.y;
        sGT[c4 * 4 + 2][j] = s.z;
        sGT[c4 * 4 + 3][j] = s.w;
    }
    __syncthreads();
    #pragma unroll
    for (int r = 0; r < 4; r++) {
        int idx = t + 256 * r;
        int il = idx >> 5, j4 = idx & 31;
        int i = islab * 32 + il;
        float4 f = make_float4(0.f, 0.f, 0.f, 0.f);
        #pragma unroll
        for (int ks = 0; ks < KS1; ks++) {
            size_t o = (((size_t)(b * KS1 + ks) * CC + i)) * CC + j4 * 4;
            float4 vf = *(const float4*)(g_epF + o);
            float4 vg = *(const float4*)(g_epG + o);
            f.x += vf.x + vg.x; f.y += vf.y + vg.y; f.z += vf.z + vg.z; f.w += vf.w + vg.w;
        }
        float4 gt = *(const float4*)&sGT[il][j4 * 4];
        float4 e = make_float4(f.x + gt.x, f.y + gt.y, f.z + gt.z, f.w + gt.w);
        *(float4*)(g_energy + ((size_t)(b * CC + i)) * CC + j4 * 4) = e;
        float mx = fmaxf(fmaxf(e.x, e.y), fmaxf(e.z, e.w));
        #pragma unroll
        for (int o = 16; o; o >>= 1) mx = fmaxf(mx, __shfl_xor_sync(0xffffffffu, mx, o));
        float e0 = mx - e.x, e1 = mx - e.y, e2 = mx - e.z, e3 = mx - e.w;
        float m2 = fmaxf(fmaxf(e0, e1), fmaxf(e2, e3));
        #pragma unroll
        for (int o = 16; o; o >>= 1) m2 = fmaxf(m2, __shfl_xor_sync(0xffffffffu, m2, o));
        float p0 = expf(e0 - m2), p1 = expf(e1 - m2), p2 = expf(e2 - m2), p3 = expf(e3 - m2);
        float s = (p0 + p1) + (p2 + p3);
        #pragma unroll
        for (int o = 16; o; o >>= 1) s += __shfl_xor_sync(0xffffffffu, s, o);
        float inv = 1.f / s;
        *(float4*)(g_attn + ((size_t)(b * CC + i)) * CC + j4 * 4) =
            make_float4(p0 * inv, p1 * inv, p2 * inv, p3 * inv);
    }
}

// ---- BN stats partials, grid (8 cslabs, BB) ---------------------------------
__global__ void __launch_bounds__(256) k_stats1() {
    int cs = blockIdx.x, b = blockIdx.y, t = threadIdx.x, lane = t & 31, w = t >> 5;
    extern __shared__ float sms[];
    float* sE = sms;
    float* sA = sms + 16384;
    float* sR = sms + 16384 + 2048;
    const float4* Eg = (const float4*)(g_energy + (size_t)b * CC * CC);
    for (int i = t; i < 4096; i += 256) ((float4*)sE)[i] = Eg[i];
    const float4* Ag = (const float4*)(g_attn + ((size_t)b * CC + cs * 16) * CC);
    for (int i = t; i < 512; i += 256) ((float4*)sA)[i] = Ag[i];
    if (t < 32) ((float4*)sR)[t] = ((const float4*)(g_rowsum + b * CC))[t];
    __syncthreads();

    float accT[2][4];
    #pragma unroll
    for (int c = 0; c < 2; c++)
        #pragma unroll
        for (int q = 0; q < 4; q++) accT[c][q] = 0.f;
    for (int k = 0; k < 128; k++) {
        float4 e = *(float4*)&sE[k * 128 + lane * 4];
        #pragma unroll
        for (int c = 0; c < 2; c++) {
            float a = sA[(w * 2 + c) * 128 + k];
            accT[c][0] += a * e.x; accT[c][1] += a * e.y;
            accT[c][2] += a * e.z; accT[c][3] += a * e.w;
        }
    }
    float4 r4 = *(float4*)&sR[lane * 4];
    #pragma unroll
    for (int c = 0; c < 2; c++) {
        float4 a4 = *(float4*)&sA[(w * 2 + c) * 128 + lane * 4];
        float l2 = accT[c][0] * a4.x + accT[c][1] * a4.y + accT[c][2] * a4.z + accT[c][3] * a4.w;
        float l1 = r4.x * a4.x + r4.y * a4.y + r4.z * a4.z + r4.w * a4.w;
        #pragma unroll
        for (int o = 16; o; o >>= 1) {
            l1 += __shfl_xor_sync(0xffffffffu, l1, o);
            l2 += __shfl_xor_sync(0xffffffffu, l2, o);
        }
        if (lane == 0) {
            g_part1[b * CC + cs * 16 + w * 2 + c] = l1;
            g_part2[b * CC + cs * 16 + w * 2 + c] = l2;
        }
    }
}

// ---- finalize scale/shift ---------------------------------------------------
__global__ void k_stats2(const float* __restrict__ gamma,
                         const float* __restrict__ bn_w,
                         const float* __restrict__ bn_b) {
    int c = threadIdx.x;
    float a1 = 0.f, a2 = 0.f;
    #pragma unroll
    for (int b = 0; b < BB; b++) { a1 += g_part1[b * CC + c]; a2 += g_part2[b * CC + c]; }
    float g = gamma[0];
    float invN = 1.f / (float)((size_t)BB * HW);
    float mean = g * a1 * invN;
    float ey2 = g * g * a2 * invN;
    float rstd = rsqrtf(ey2 - mean * mean + 1e-5f);
    float w = bn_w[c];
    g_scale[c] = g * rstd * w;
    g_shift[c] = bn_b[c] - mean * rstd * w;
}

// ---- attn limbs with scale folded -------------------------------------------
__global__ void k_alimb() {
    int b = blockIdx.x, j = threadIdx.x;
    int half = j >> 6, jl = j & 63;
    for (int i = 0; i < 128; i++) {
        float v = g_attn[((size_t)(b * CC + i)) * CC + j] * g_scale[i];
        __nv_bfloat16 a0 = __float2bfloat16_rn(v);
        __nv_bfloat16 a1 = __float2bfloat16_rn(v - __bfloat162float(a0));
        g_al[(((size_t)(b * 2 + 0) * 2 + half) * CC + i) * 64 + jl] = a0;
        g_al[(((size_t)(b * 2 + 1) * 2 + half) * CC + i) * 64 + jl] = a1;
    }
}

// ---- out GEMM: single fp32 X stream, in-kernel limb conversion --------------
// smem: A 0..64K | limb B 64K..128K (2 buf) | X ring 128K..192K (2x32K) | stage
__global__ void __launch_bounds__(256) k_out_mma(const float* __restrict__ x,
                                                 float* __restrict__ out) {
    extern __shared__ char smraw[];
    char* sm = (char*)(((unsigned long long)smraw + 127) & ~127ULL);
    unsigned sb = smem_u32(sm);
    float* stage = (float*)(sm + 196608);
    int t = threadIdx.x, lane = t & 31, wid = t >> 5;
    int nb = blockIdx.x, b = blockIdx.y;
    int wm = (wid >> 1) * 32, wn = (wid & 1) * 32;
    size_t xrow = (size_t)b * CC * HW;

    #define OX_LOAD(it) do { \
        unsigned _db = sb + 131072 + ((it) & 1) * 32768; \
        size_t _nbase = (size_t)nb * 2048 + (it) * 64; \
        _Pragma("unroll") \
        for (int _i = 0; _i < 8; _i++) { \
            int _idx = t + 256 * _i; \
            int _row = _idx >> 4, _c4 = _idx & 15; \
            CPA(_db + _row * 256 + _c4 * 16, x + xrow + (size_t)_row * HW + _nbase + _c4 * 4); \
        } \
        CPA_COMMIT(); \
    } while (0)

    #define OX_CONV(it) do { \
        char* _st = sm + 131072 + ((it) & 1) * 32768; \
        char* _lb = sm + 65536 + ((it) & 1) * 32768; \
        _Pragma("unroll") \
        for (int _i = 0; _i < 4; _i++) { \
            int _idx = t + 256 * _i; \
            int _row = _idx >> 3, _part = _idx & 7; \
            unsigned _so = swz((unsigned)(_row * 128 + _part * 16)); \
            conv8(_st + _row * 256 + _part * 32, _lb + _so, _lb + 16384 + _so); \
        } \
    } while (0)

    // group 0: A limb tiles + X chunk 0
    #pragma unroll
    for (int i = 0; i < 16; i++) {
        int idx = t + 256 * i;
        int limb = idx >> 11, rem = idx & 2047, half = rem >> 10, r2 = rem & 1023;
        int row = r2 >> 3, part = r2 & 7;
        const void* src = g_al + (((size_t)(b * 2 + limb) * 2 + half) * CC + row) * 64 + part * 8;
        CPA(sb + (limb * 2 + half) * 16384 + swz((unsigned)(row * 128 + part * 16)), src);
    }
    OX_LOAD(0);
    OX_LOAD(1);
    CPA_WAIT1();   // A + X0 ready
    __syncthreads();

    unsigned A0h[8][2][4], A1h[8][2][4];
    #pragma unroll
    for (int ksp = 0; ksp < 8; ksp++) {
        int jhalf = ksp >> 2;
        unsigned kb = (unsigned)((ksp & 3) * 32 + (lane >> 4) * 16);
        #pragma unroll
        for (int mt = 0; mt < 2; mt++) {
            unsigned off = swz((unsigned)((wm + mt * 16 + (lane & 15)) * 128) + kb);
            ldsm4(sb + (0 * 2 + jhalf) * 16384 + off, A0h[ksp][mt]);
            ldsm4(sb + (1 * 2 + jhalf) * 16384 + off, A1h[ksp][mt]);
        }
    }
    OX_CONV(0);
    __syncthreads();

    for (int it = 0; it < 32; it++) {
        float acc[2][4][4];
        #pragma unroll
        for (int mt = 0; mt < 2; mt++)
            #pragma unroll
            for (int nf = 0; nf < 4; nf++)
                #pragma unroll
                for (int c = 0; c < 4; c++) acc[mt][nf][c] = 0.f;

        unsigned Bt0 = sb + 65536 + (it & 1) * 32768;
        unsigned Bt1 = Bt0 + 16384;
        #pragma unroll
        for (int ksp = 0; ksp < 8; ksp++) {
            int jrow = ksp * 16 + ((lane >> 3) & 1) * 8 + (lane & 7);
            unsigned B0[2][4], B1[2][4];
            #pragma unroll
            for (int nt = 0; nt < 2; nt++) {
                int ncol = wn + nt * 16 + ((lane >> 4) & 1) * 8;
                unsigned offb = swz((unsigned)(jrow * 128 + ncol * 2));
                ldsm4t(Bt0 + offb, B0[nt]);
                ldsm4t(Bt1 + offb, B1[nt]);
            }
            #pragma unroll
            for (int mt = 0; mt < 2; mt++)
                #pragma unroll
                for (int nt = 0; nt < 2; nt++)
                    #pragma unroll
                    for (int s = 0; s < 2; s++) {
                        float* c = acc[mt][nt * 2 + s];
                        mma16816(c, A0h[ksp][mt], B0[nt][s * 2], B0[nt][s * 2 + 1]);
                        mma16816(c, A0h[ksp][mt], B1[nt][s * 2], B1[nt][s * 2 + 1]);
                        mma16816(c, A1h[ksp][mt], B0[nt][s * 2], B0[nt][s * 2 + 1]);
                    }
        }

        if (it + 1 < 32) CPA_WAIT0();  // X(it+1) arrived

        int g = lane >> 2, tg = lane & 3;
        #pragma unroll
        for (int mt = 0; mt < 2; mt++)
            #pragma unroll
            for (int nf = 0; nf < 4; nf++) {
                int i0 = wm + mt * 16 + g, col = wn + nf * 8 + tg * 2;
                *(float2*)&stage[i0 * 68 + col] = make_float2(acc[mt][nf][0], acc[mt][nf][1]);
                *(float2*)&stage[(i0 + 8) * 68 + col] = make_float2(acc[mt][nf][2], acc[mt][nf][3]);
            }
        __syncthreads();  // stage + X(it+1) visible to all

        if (it + 1 < 32) OX_CONV(it + 1);  // writes limb buf (it+1)&1

        const float* sx = (const float*)(sm + 131072 + (it & 1) * 32768);
        size_t gbase = xrow + (size_t)nb * 2048 + it * 64;
        #pragma unroll
        for (int r = 0; r < 8; r++) {
            int idx = t + 256 * r;
            int i = idx >> 4, n4 = (idx & 15) * 4;
            float4 v = *(float4*)&stage[i * 68 + n4];
            float4 xv = *(const float4*)&sx[i * 64 + n4];
            float sh = g_shift[i];
            size_t o = gbase + (size_t)i * HW + n4;
            *(float4*)(out + o) = make_float4(v.x + sh + xv.x, v.y + sh + xv.y,
                                              v.z + sh + xv.z, v.w + sh + xv.w);
        }
        __syncthreads();  // limbs(it+1) ready; X slot it&1 + stage reusable

        if (it + 2 < 32) OX_LOAD(it + 2);
    }
    #undef OX_LOAD
    #undef OX_CONV
}

extern "C" void kernel_launch(void* const* d_in, const int* in_sizes, int n_in,
                              void* d_out, int out_size) {
    const float* x = (const float*)d_in[0];
    const float* gamma = (const float*)d_in[1];
    const float* bn_w = (const float*)d_in[2];
    const float* bn_b = (const float*)d_in[3];
    float* out = (float*)d_out;

    int smE = 65536 + 65536 + 4096 + 1024;            // ~133 KB
    int smS = (16384 + 2048 + 128) * 4;               // 74.2 KB
    int smO = 196608 + 128 * 68 * 4 + 256;            // ~226 KB
    cudaFuncSetAttribute(k_energy_mma, cudaFuncAttributeMaxDynamicSharedMemorySize, smE);
    cudaFuncSetAttribute(k_stats1, cudaFuncAttributeMaxDynamicSharedMemorySize, smS);
    cudaFuncSetAttribute(k_out_mma, cudaFuncAttributeMaxDynamicSharedMemorySize, smO);

    k_nop<<<1, 1>>>();                                // 0
    k_nop<<<1, 1>>>();                                // 1
    k_nop<<<1, 1>>>();                                // 2
    k_energy_mma<<<dim3(KS1, BB), 256, smE>>>(x);     // 3 (ncu capture slot)
    k_rs2<<<BB, CC>>>();                              // 4
    k_redsoft<<<dim3(4, BB), 256>>>();                // 5
    k_stats1<<<dim3(8, BB), 256, smS>>>();            // 6
    k_stats2<<<1, 128>>>(gamma, bn_w, bn_b);          // 7
    k_alimb<<<BB, 128>>>();                           // 8
    k_out_mma<<<dim3(8, BB), 256, smO>>>(x, out);     // 9
}

// round 11
// speedup vs baseline: 3.1988x; 1.1737x over previous
#include <cuda_runtime.h>
#include <cuda_bf16.h>
#include <math.h>

#define BB 16
#define CC 128
#define HW 16384
#define KS1 8
#define KSEG (HW / KS1)  // 2048

__device__ float g_energy[BB * CC * CC];
__device__ float g_epF[BB * KS1 * CC * CC];
__device__ float g_epG[BB * KS1 * CC * CC];
__device__ float g_attn[BB * CC * CC];
__device__ float g_rowsum[BB * CC];
__device__ float g_rspart[BB * KS1 * CC];
__device__ float g_part1[BB * CC];
__device__ float g_part2[BB * CC];
__device__ float g_scale[CC];
__device__ float g_shift[CC];
// attn limbs (scale folded), layout [b][limb][jhalf][i][64]
__device__ __nv_bfloat16 g_al[(size_t)BB * 2 * 2 * CC * 64];

__device__ __forceinline__ unsigned smem_u32(const void* p) {
    unsigned a;
    asm("{ .reg .u64 t; cvta.to.shared.u64 t, %1; cvt.u32.u64 %0, t; }" : "=r"(a) : "l"(p));
    return a;
}
__device__ __forceinline__ unsigned swz(unsigned o) { return o ^ ((o >> 3) & 0x70); }

#define CPA(dst, src) asm volatile("cp.async.ca.shared.global [%0], [%1], 16;" :: "r"(dst), "l"(src))
#define CPA_COMMIT()  asm volatile("cp.async.commit_group;" ::: "memory")
#define CPA_WAIT0()   asm volatile("cp.async.wait_group 0;" ::: "memory")
#define CPA_WAIT1()   asm volatile("cp.async.wait_group 1;" ::: "memory")
#define NBAR_SYNC(id, n)   asm volatile("bar.sync %0, %1;"   :: "r"(id), "r"(n) : "memory")
#define NBAR_ARRIVE(id, n) asm volatile("bar.arrive %0, %1;" :: "r"(id), "r"(n) : "memory")

__device__ __forceinline__ void ldsm4(unsigned a, unsigned r[4]) {
    asm volatile("ldmatrix.sync.aligned.m8n8.x4.shared.b16 {%0,%1,%2,%3}, [%4];"
                 : "=r"(r[0]), "=r"(r[1]), "=r"(r[2]), "=r"(r[3]) : "r"(a));
}
__device__ __forceinline__ void ldsm4t(unsigned a, unsigned r[4]) {
    asm volatile("ldmatrix.sync.aligned.m8n8.x4.trans.shared.b16 {%0,%1,%2,%3}, [%4];"
                 : "=r"(r[0]), "=r"(r[1]), "=r"(r[2]), "=r"(r[3]) : "r"(a));
}
__device__ __forceinline__ void mma16816(float c[4], const unsigned a[4], unsigned b0, unsigned b1) {
    asm volatile("mma.sync.aligned.m16n8k16.row.col.f32.bf16.bf16.f32 "
                 "{%0,%1,%2,%3}, {%4,%5,%6,%7}, {%8,%9}, {%0,%1,%2,%3};"
                 : "+f"(c[0]), "+f"(c[1]), "+f"(c[2]), "+f"(c[3])
                 : "r"(a[0]), "r"(a[1]), "r"(a[2]), "r"(a[3]), "r"(b0), "r"(b1));
}

// convert 8 fp32 (32B at sp) into two 16B bf16 limb vectors; returns elem sum
__device__ __forceinline__ float conv8(const char* sp, char* d0, char* d1) {
    float4 a = ((const float4*)sp)[0];
    float4 b = ((const float4*)sp)[1];
    float f[8] = {a.x, a.y, a.z, a.w, b.x, b.y, b.z, b.w};
    unsigned u0[4], u1[4];
    #pragma unroll
    for (int k = 0; k < 4; k++) {
        __nv_bfloat16 p0 = __float2bfloat16_rn(f[2 * k]);
        __nv_bfloat16 p1 = __float2bfloat16_rn(f[2 * k + 1]);
        __nv_bfloat16 q0 = __float2bfloat16_rn(f[2 * k] - __bfloat162float(p0));
        __nv_bfloat16 q1 = __float2bfloat16_rn(f[2 * k + 1] - __bfloat162float(p1));
        __nv_bfloat162 v0(p0, p1), v1(q0, q1);
        u0[k] = *(unsigned*)&v0;
        u1[k] = *(unsigned*)&v1;
    }
    *(uint4*)d0 = make_uint4(u0[0], u0[1], u0[2], u0[3]);
    *(uint4*)d1 = make_uint4(u1[0], u1[1], u1[2], u1[3]);
    return ((f[0] + f[1]) + (f[2] + f[3])) + ((f[4] + f[5]) + (f[6] + f[7]));
}

// ---- energy: fused fp32->limb conversion + F = q0 q0^T, G = q0 q1^T --------
__global__ void __launch_bounds__(256) k_energy_mma(const float* __restrict__ x) {
    extern __shared__ char smraw[];
    char* sm = (char*)(((unsigned long long)smraw + 1023) & ~1023ULL);
    unsigned sb = smem_u32(sm);
    int t = threadIdx.x, lane = t & 31, wid = t >> 5;
    int ks = blockIdx.x, b = blockIdx.y;
    size_t rowbase = (size_t)b * CC * HW + (size_t)ks * KSEG;
    int wm = (wid >> 2) * 64, wn = (wid & 3) * 32;
    float* s_rs = (float*)(sm + 131072);
    float rsacc[4] = {0.f, 0.f, 0.f, 0.f};

    float accF[4][4][4], accG[4][4][4];
    #pragma unroll
    for (int mt = 0; mt < 4; mt++)
        #pragma unroll
        for (int nt = 0; nt < 4; nt++)
            #pragma unroll
            for (int c = 0; c < 4; c++) { accF[mt][nt][c] = 0.f; accG[mt][nt][c] = 0.f; }

    #define X_LOAD(ch) do { \
        unsigned _db = sb + ((ch) & 1) * 32768; \
        _Pragma("unroll") \
        for (int _i = 0; _i < 8; _i++) { \
            int _idx = t + 256 * _i; \
            int _row = _idx >> 4, _c4 = _idx & 15; \
            CPA(_db + _row * 256 + _c4 * 16, x + rowbase + (size_t)_row * HW + (ch) * 64 + _c4 * 4); \
        } \
        CPA_COMMIT(); \
    } while (0)

    #define X_CONV(ch) do { \
        char* _st = sm + ((ch) & 1) * 32768; \
        char* _lb = sm + 65536 + ((ch) & 1) * 32768; \
        _Pragma("unroll") \
        for (int _i = 0; _i < 4; _i++) { \
            int _idx = t + 256 * _i; \
            int _row = _idx >> 3, _part = _idx & 7; \
            unsigned _so = swz((unsigned)(_row * 128 + _part * 16)); \
            rsacc[_i] += conv8(_st + _row * 256 + _part * 32, _lb + _so, _lb + 16384 + _so); \
        } \
    } while (0)

    X_LOAD(0);
    X_LOAD(1);
    CPA_WAIT1();
    __syncthreads();
    X_CONV(0);
    __syncthreads();

    for (int ch = 0; ch < 32; ch++) {
        if (ch + 2 < 32) X_LOAD(ch + 2);
        if (ch + 1 < 32) {
            if (ch + 2 < 32) CPA_WAIT1(); else CPA_WAIT0();
        }
        __syncthreads();
        if (ch + 1 < 32) X_CONV(ch + 1);

        unsigned b0t = sb + 65536 + (ch & 1) * 32768;
        unsigned b1t = b0t + 16384;
        #pragma unroll
        for (int kk = 0; kk < 4; kk++) {
            int kbyte = kk * 32;
            unsigned A[4][4];
            #pragma unroll
            for (int mt = 0; mt < 4; mt++) {
                unsigned off = swz((unsigned)((wm + mt * 16 + (lane & 15)) * 128 + kbyte + (lane >> 4) * 16));
                ldsm4(b0t + off, A[mt]);
            }
            unsigned B0[2][4], B1[2][4];
            #pragma unroll
            for (int nt = 0; nt < 2; nt++) {
                int row = wn + nt * 16 + ((lane >> 4) & 1) * 8 + (lane & 7);
                int kb = kbyte + ((lane >> 3) & 1) * 16;
                unsigned off = swz((unsigned)(row * 128 + kb));
                ldsm4(b0t + off, B0[nt]);
                ldsm4(b1t + off, B1[nt]);
            }
            #pragma unroll
            for (int mt = 0; mt < 4; mt++)
                #pragma unroll
                for (int nt = 0; nt < 2; nt++)
                    #pragma unroll
                    for (int s = 0; s < 2; s++) {
                        mma16816(accF[mt][nt * 2 + s], A[mt], B0[nt][s * 2], B0[nt][s * 2 + 1]);
                        mma16816(accG[mt][nt * 2 + s], A[mt], B1[nt][s * 2], B1[nt][s * 2 + 1]);
                    }
        }
        __syncthreads();
    }
    #undef X_LOAD
    #undef X_CONV

    #pragma unroll
    for (int i = 0; i < 4; i++) s_rs[((t + 256 * i) >> 3) * 8 + (t & 7)] = rsacc[i];
    __syncthreads();
    if (t < 128) {
        float s = 0.f;
        #pragma unroll
        for (int k = 0; k < 8; k++) s += s_rs[t * 8 + k];
        g_rspart[(b * KS1 + ks) * CC + t] = s;
    }

    size_t pbase = ((size_t)(b * KS1 + ks)) * CC * CC;
    int g = lane >> 2, tg = lane & 3;
    #pragma unroll
    for (int mt = 0; mt < 4; mt++)
        #pragma unroll
        for (int nt = 0; nt < 4; nt++) {
            int i0 = wm + mt * 16 + g, j = wn + nt * 8 + tg * 2;
            *(float2*)(g_epF + pbase + (size_t)i0 * CC + j) = make_float2(accF[mt][nt][0], accF[mt][nt][1]);
            *(float2*)(g_epF + pbase + (size_t)(i0 + 8) * CC + j) = make_float2(accF[mt][nt][2], accF[mt][nt][3]);
            *(float2*)(g_epG + pbase + (size_t)i0 * CC + j) = make_float2(accG[mt][nt][0], accG[mt][nt][1]);
            *(float2*)(g_epG + pbase + (size_t)(i0 + 8) * CC + j) = make_float2(accG[mt][nt][2], accG[mt][nt][3]);
        }
}

// ---- finish rowsum ----------------------------------------------------------
__global__ void k_rs2() {
    int b = blockIdx.x, j = threadIdx.x;
    float s = 0.f;
    #pragma unroll
    for (int ks = 0; ks < KS1; ks++) s += g_rspart[(b * KS1 + ks) * CC + j];
    g_rowsum[b * CC + j] = s;
}

// ---- fused E = F + G + G^T  AND softmax -------------------------------------
__global__ void k_redsoft() {
    int islab = blockIdx.x, b = blockIdx.y, t = threadIdx.x;
    __shared__ float sGT[32][132];
    #pragma unroll
    for (int r = 0; r < 4; r++) {
        int idx = t + 256 * r;
        int j = idx >> 3, c4 = idx & 7;
        float4 s = make_float4(0.f, 0.f, 0.f, 0.f);
        #pragma unroll
        for (int ks = 0; ks < KS1; ks++) {
            float4 v = *(const float4*)(g_epG + (((size_t)(b * KS1 + ks) * CC + j)) * CC + islab * 32 + c4 * 4);
            s.x += v.x; s.y += v.y; s.z += v.z; s.w += v.w;
        }
        sGT[c4 * 4 + 0][j] = s.x;
        sGT[c4 * 4 + 1][j] = s.y;
        sGT[c4 * 4 + 2][j] = s.z;
        sGT[c4 * 4 + 3][j] = s.w;
    }
    __syncthreads();
    #pragma unroll
    for (int r = 0; r < 4; r++) {
        int idx = t + 256 * r;
        int il = idx >> 5, j4 = idx & 31;
        int i = islab * 32 + il;
        float4 f = make_float4(0.f, 0.f, 0.f, 0.f);
        #pragma unroll
        for (int ks = 0; ks < KS1; ks++) {
            size_t o = (((size_t)(b * KS1 + ks) * CC + i)) * CC + j4 * 4;
            float4 vf = *(const float4*)(g_epF + o);
            float4 vg = *(const float4*)(g_epG + o);
            f.x += vf.x + vg.x; f.y += vf.y + vg.y; f.z += vf.z + vg.z; f.w += vf.w + vg.w;
        }
        float4 gt = *(const float4*)&sGT[il][j4 * 4];
        float4 e = make_float4(f.x + gt.x, f.y + gt.y, f.z + gt.z, f.w + gt.w);
        *(float4*)(g_energy + ((size_t)(b * CC + i)) * CC + j4 * 4) = e;
        float mx = fmaxf(fmaxf(e.x, e.y), fmaxf(e.z, e.w));
        #pragma unroll
        for (int o = 16; o; o >>= 1) mx = fmaxf(mx, __shfl_xor_sync(0xffffffffu, mx, o));
        float e0 = mx - e.x, e1 = mx - e.y, e2 = mx - e.z, e3 = mx - e.w;
        float m2 = fmaxf(fmaxf(e0, e1), fmaxf(e2, e3));
        #pragma unroll
        for (int o = 16; o; o >>= 1) m2 = fmaxf(m2, __shfl_xor_sync(0xffffffffu, m2, o));
        float p0 = expf(e0 - m2), p1 = expf(e1 - m2), p2 = expf(e2 - m2), p3 = expf(e3 - m2);
        float s = (p0 + p1) + (p2 + p3);
        #pragma unroll
        for (int o = 16; o; o >>= 1) s += __shfl_xor_sync(0xffffffffu, s, o);
        float inv = 1.f / s;
        *(float4*)(g_attn + ((size_t)(b * CC + i)) * CC + j4 * 4) =
            make_float4(p0 * inv, p1 * inv, p2 * inv, p3 * inv);
    }
}

// ---- BN stats partials, grid (8 cslabs, BB) ---------------------------------
__global__ void __launch_bounds__(256) k_stats1() {
    int cs = blockIdx.x, b = blockIdx.y, t = threadIdx.x, lane = t & 31, w = t >> 5;
    extern __shared__ float sms[];
    float* sE = sms;
    float* sA = sms + 16384;
    float* sR = sms + 16384 + 2048;
    const float4* Eg = (const float4*)(g_energy + (size_t)b * CC * CC);
    for (int i = t; i < 4096; i += 256) ((float4*)sE)[i] = Eg[i];
    const float4* Ag = (const float4*)(g_attn + ((size_t)b * CC + cs * 16) * CC);
    for (int i = t; i < 512; i += 256) ((float4*)sA)[i] = Ag[i];
    if (t < 32) ((float4*)sR)[t] = ((const float4*)(g_rowsum + b * CC))[t];
    __syncthreads();

    float accT[2][4];
    #pragma unroll
    for (int c = 0; c < 2; c++)
        #pragma unroll
        for (int q = 0; q < 4; q++) accT[c][q] = 0.f;
    for (int k = 0; k < 128; k++) {
        float4 e = *(float4*)&sE[k * 128 + lane * 4];
        #pragma unroll
        for (int c = 0; c < 2; c++) {
            float a = sA[(w * 2 + c) * 128 + k];
            accT[c][0] += a * e.x; accT[c][1] += a * e.y;
            accT[c][2] += a * e.z; accT[c][3] += a * e.w;
        }
    }
    float4 r4 = *(float4*)&sR[lane * 4];
    #pragma unroll
    for (int c = 0; c < 2; c++) {
        float4 a4 = *(float4*)&sA[(w * 2 + c) * 128 + lane * 4];
        float l2 = accT[c][0] * a4.x + accT[c][1] * a4.y + accT[c][2] * a4.z + accT[c][3] * a4.w;
        float l1 = r4.x * a4.x + r4.y * a4.y + r4.z * a4.z + r4.w * a4.w;
        #pragma unroll
        for (int o = 16; o; o >>= 1) {
            l1 += __shfl_xor_sync(0xffffffffu, l1, o);
            l2 += __shfl_xor_sync(0xffffffffu, l2, o);
        }
        if (lane == 0) {
            g_part1[b * CC + cs * 16 + w * 2 + c] = l1;
            g_part2[b * CC + cs * 16 + w * 2 + c] = l2;
        }
    }
}

// ---- finalize scale/shift ---------------------------------------------------
__global__ void k_stats2(const float* __restrict__ gamma,
                         const float* __restrict__ bn_w,
                         const float* __restrict__ bn_b) {
    int c = threadIdx.x;
    float a1 = 0.f, a2 = 0.f;
    #pragma unroll
    for (int b = 0; b < BB; b++) { a1 += g_part1[b * CC + c]; a2 += g_part2[b * CC + c]; }
    float g = gamma[0];
    float invN = 1.f / (float)((size_t)BB * HW);
    float mean = g * a1 * invN;
    float ey2 = g * g * a2 * invN;
    float rstd = rsqrtf(ey2 - mean * mean + 1e-5f);
    float w = bn_w[c];
    g_scale[c] = g * rstd * w;
    g_shift[c] = bn_b[c] - mean * rstd * w;
}

// ---- attn limbs with scale folded -------------------------------------------
__global__ void k_alimb() {
    int b = blockIdx.x, j = threadIdx.x;
    int half = j >> 6, jl = j & 63;
    for (int i = 0; i < 128; i++) {
        float v = g_attn[((size_t)(b * CC + i)) * CC + j] * g_scale[i];
        __nv_bfloat16 a0 = __float2bfloat16_rn(v);
        __nv_bfloat16 a1 = __float2bfloat16_rn(v - __bfloat162float(a0));
        g_al[(((size_t)(b * 2 + 0) * 2 + half) * CC + i) * 64 + jl] = a0;
        g_al[(((size_t)(b * 2 + 1) * 2 + half) * CC + i) * 64 + jl] = a1;
    }
}

// ---- out GEMM: warp-specialized (4 MMA warps + 4 IO warps), direct stores ---
// smem: A 0..64K | limb ring 64K..128K (2x32K) | X ring 128K (2x34816, 272B rows)
//       | s_shift @200704
__global__ void __launch_bounds__(256) k_out_mma(const float* __restrict__ x,
                                                 float* __restrict__ out) {
    extern __shared__ char smraw[];
    char* sm = (char*)(((unsigned long long)smraw + 1023) & ~1023ULL);
    unsigned sb = smem_u32(sm);
    int t = threadIdx.x, lane = t & 31, wid = t >> 5;
    int nb = blockIdx.x, b = blockIdx.y;  // nb: 8 chunks of 2048 cols
    size_t xrow = (size_t)b * CC * HW;
    const unsigned XS = 34816;
    float* s_shift = (float*)(sm + 200704);

    if (wid < 4) {
        // ================= MMA warps =================
        int wm = wid * 32;
        #pragma unroll
        for (int i = 0; i < 32; i++) {
            int idx = t + 128 * i;
            int tile = idx >> 10, rem = idx & 1023, row = rem >> 3, part = rem & 7;
            int limb = tile >> 1, half = tile & 1;
            const void* src = g_al + (((size_t)(b * 2 + limb) * 2 + half) * CC + row) * 64 + part * 8;
            CPA(sb + tile * 16384 + swz((unsigned)(row * 128 + part * 16)), src);
        }
        CPA_COMMIT();
        s_shift[t] = g_shift[t];
        CPA_WAIT0();
        NBAR_SYNC(6, 128);

        unsigned A0h[8][2][4], A1h[8][2][4];
        #pragma unroll
        for (int ksp = 0; ksp < 8; ksp++) {
            int jhalf = ksp >> 2;
            unsigned kb = (unsigned)((ksp & 3) * 32 + (lane >> 4) * 16);
            #pragma unroll
            for (int mt = 0; mt < 2; mt++) {
                unsigned off = swz((unsigned)((wm + mt * 16 + (lane & 15)) * 128) + kb);
                ldsm4(sb + (0 + jhalf) * 16384 + off, A0h[ksp][mt]);  // limb0: tiles 0,1
                ldsm4(sb + (2 + jhalf) * 16384 + off, A1h[ksp][mt]);  // limb1: tiles 2,3
            }
        }

        int g = lane >> 2, tg = lane & 3;
        for (int it = 0; it < 32; it++) {
            int slot = it & 1;
            NBAR_SYNC(1 + slot, 256);  // limb+X slot ready

            float acc[2][8][4];
            #pragma unroll
            for (int mt = 0; mt < 2; mt++)
                #pragma unroll
                for (int nf = 0; nf < 8; nf++)
                    #pragma unroll
                    for (int c = 0; c < 4; c++) acc[mt][nf][c] = 0.f;

            unsigned Bt0 = sb + 65536 + slot * 32768;
            unsigned Bt1 = Bt0 + 16384;
            #pragma unroll
            for (int ksp = 0; ksp < 8; ksp++) {
                int jrow = ksp * 16 + ((lane >> 3) & 1) * 8 + (lane & 7);
                #pragma unroll
                for (int f = 0; f < 4; f++) {
                    int ncol = f * 16 + ((lane >> 4) & 1) * 8;
                    unsigned offb = swz((unsigned)(jrow * 128 + ncol * 2));
                    unsigned B0[4], B1[4];
                    ldsm4t(Bt0 + offb, B0);
                    ldsm4t(Bt1 + offb, B1);
                    #pragma unroll
                    for (int mt = 0; mt < 2; mt++)
                        #pragma unroll
                        for (int s = 0; s < 2; s++) {
                            float* c = acc[mt][f * 2 + s];
                            mma16816(c, A0h[ksp][mt], B0[s * 2], B0[s * 2 + 1]);
                            mma16816(c, A0h[ksp][mt], B1[s * 2], B1[s * 2 + 1]);
                            mma16816(c, A1h[ksp][mt], B0[s * 2], B0[s * 2 + 1]);
                        }
                }
            }

            // epilogue: direct stores + shift + x (from padded smem X ring)
            const char* xc = sm + 131072 + slot * XS;
            size_t gbase = xrow + (size_t)nb * 2048 + it * 64;
            #pragma unroll
            for (int mt = 0; mt < 2; mt++) {
                int i0 = wm + mt * 16 + g;
                float sh0 = s_shift[i0], sh1 = s_shift[i0 + 8];
                #pragma unroll
                for (int nf = 0; nf < 8; nf++) {
                    int col = nf * 8 + tg * 2;
                    float2 xv0 = *(const float2*)(xc + i0 * 272 + col * 4);
                    float2 xv1 = *(const float2*)(xc + (i0 + 8) * 272 + col * 4);
                    *(float2*)(out + gbase + (size_t)i0 * HW + col) =
                        make_float2(acc[mt][nf][0] + sh0 + xv0.x, acc[mt][nf][1] + sh0 + xv0.y);
                    *(float2*)(out + gbase + (size_t)(i0 + 8) * HW + col) =
                        make_float2(acc[mt][nf][2] + sh1 + xv1.x, acc[mt][nf][3] + sh1 + xv1.y);
                }
            }
            if (it + 2 < 32) NBAR_ARRIVE(3 + slot, 256);  // slot consumed
        }
    } else {
        // ================= IO warps =================
        int tio = t - 128;

        #define OX_LOAD(it) do { \
            unsigned _db = sb + 131072 + ((it) & 1) * XS; \
            size_t _nbase = (size_t)nb * 2048 + (it) * 64; \
            _Pragma("unroll") \
            for (int _i = 0; _i < 16; _i++) { \
                int _idx = tio + 128 * _i; \
                int _row = _idx >> 4, _c4 = _idx & 15; \
                CPA(_db + _row * 272 + _c4 * 16, x + xrow + (size_t)_row * HW + _nbase + _c4 * 4); \
            } \
            CPA_COMMIT(); \
        } while (0)

        #define OX_CONV(it) do { \
            const char* _st = sm + 131072 + ((it) & 1) * XS; \
            char* _lb = sm + 65536 + ((it) & 1) * 32768; \
            _Pragma("unroll") \
            for (int _i = 0; _i < 8; _i++) { \
                int _idx = tio + 128 * _i; \
                int _row = _idx >> 3, _part = _idx & 7; \
                unsigned _so = swz((unsigned)(_row * 128 + _part * 16)); \
                conv8(_st + _row * 272 + _part * 32, _lb + _so, _lb + 16384 + _so); \
            } \
        } while (0)

        OX_LOAD(0);
        OX_LOAD(1);
        CPA_WAIT1();
        NBAR_SYNC(5, 128);
        OX_CONV(0);
        NBAR_ARRIVE(1, 256);
        CPA_WAIT0();
        NBAR_SYNC(5, 128);
        OX_CONV(1);
        NBAR_ARRIVE(2, 256);

        for (int it = 0; it + 2 < 32; it++) {
            int slot = it & 1;
            NBAR_SYNC(3 + slot, 256);  // MMA done with slot
            OX_LOAD(it + 2);
            CPA_WAIT0();
            NBAR_SYNC(5, 128);
            OX_CONV(it + 2);
            NBAR_ARRIVE(1 + slot, 256);
        }
        #undef OX_LOAD
        #undef OX_CONV
    }
}

extern "C" void kernel_launch(void* const* d_in, const int* in_sizes, int n_in,
                              void* d_out, int out_size) {
    const float* x = (const float*)d_in[0];
    const float* gamma = (const float*)d_in[1];
    const float* bn_w = (const float*)d_in[2];
    const float* bn_b = (const float*)d_in[3];
    float* out = (float*)d_out;

    int smE = 65536 + 65536 + 4096 + 1024;            // ~133 KB
    int smS = (16384 + 2048 + 128) * 4;               // 74.2 KB
    int smO = 200704 + 512 + 1024;                    // ~197.5 KB
    cudaFuncSetAttribute(k_energy_mma, cudaFuncAttributeMaxDynamicSharedMemorySize, smE);
    cudaFuncSetAttribute(k_stats1, cudaFuncAttributeMaxDynamicSharedMemorySize, smS);
    cudaFuncSetAttribute(k_out_mma, cudaFuncAttributeMaxDynamicSharedMemorySize, smO);

    k_energy_mma<<<dim3(KS1, BB), 256, smE>>>(x);     // 0
    k_rs2<<<BB, CC>>>();                              // 1
    k_redsoft<<<dim3(4, BB), 256>>>();                // 2
    k_stats1<<<dim3(8, BB), 256, smS>>>();            // 3 (ncu capture slot)
    k_stats2<<<1, 128>>>(gamma, bn_w, bn_b);          // 4
    k_alimb<<<BB, 128>>>();                           // 5
    k_out_mma<<<dim3(8, BB), 256, smO>>>(x, out);     // 6
}

// round 12
// speedup vs baseline: 3.3489x; 1.0469x over previous
#include <cuda_runtime.h>
#include <cuda_bf16.h>
#include <math.h>

#define BB 16
#define CC 128
#define HW 16384
#define KS1 8
#define KSEG (HW / KS1)  // 2048

__device__ float g_energy[BB * CC * CC];
__device__ float g_epF[BB * KS1 * CC * CC];
__device__ float g_epG[BB * KS1 * CC * CC];
__device__ float g_attn[BB * CC * CC];
__device__ float g_rowsum[BB * CC];
__device__ float g_rspart[BB * KS1 * CC];
__device__ float g_part1[BB * CC];
__device__ float g_part2[BB * CC];
__device__ float g_scale[CC];
__device__ float g_shift[CC];
// attn limbs (scale folded), layout [b][limb][jhalf][i][64]
__device__ __nv_bfloat16 g_al[(size_t)BB * 2 * 2 * CC * 64];

__device__ __forceinline__ unsigned smem_u32(const void* p) {
    unsigned a;
    asm("{ .reg .u64 t; cvta.to.shared.u64 t, %1; cvt.u32.u64 %0, t; }" : "=r"(a) : "l"(p));
    return a;
}
__device__ __forceinline__ unsigned swz(unsigned o) { return o ^ ((o >> 3) & 0x70); }

#define CPA(dst, src) asm volatile("cp.async.ca.shared.global [%0], [%1], 16;" :: "r"(dst), "l"(src))
#define CPA_COMMIT()  asm volatile("cp.async.commit_group;" ::: "memory")
#define CPA_WAIT0()   asm volatile("cp.async.wait_group 0;" ::: "memory")
#define CPA_WAIT1()   asm volatile("cp.async.wait_group 1;" ::: "memory")
#define NBAR_SYNC(id, n)   asm volatile("bar.sync %0, %1;"   :: "r"(id), "r"(n) : "memory")
#define NBAR_ARRIVE(id, n) asm volatile("bar.arrive %0, %1;" :: "r"(id), "r"(n) : "memory")

__device__ __forceinline__ void ldsm4(unsigned a, unsigned r[4]) {
    asm volatile("ldmatrix.sync.aligned.m8n8.x4.shared.b16 {%0,%1,%2,%3}, [%4];"
                 : "=r"(r[0]), "=r"(r[1]), "=r"(r[2]), "=r"(r[3]) : "r"(a));
}
__device__ __forceinline__ void ldsm4t(unsigned a, unsigned r[4]) {
    asm volatile("ldmatrix.sync.aligned.m8n8.x4.trans.shared.b16 {%0,%1,%2,%3}, [%4];"
                 : "=r"(r[0]), "=r"(r[1]), "=r"(r[2]), "=r"(r[3]) : "r"(a));
}
__device__ __forceinline__ void mma16816(float c[4], const unsigned a[4], unsigned b0, unsigned b1) {
    asm volatile("mma.sync.aligned.m16n8k16.row.col.f32.bf16.bf16.f32 "
                 "{%0,%1,%2,%3}, {%4,%5,%6,%7}, {%8,%9}, {%0,%1,%2,%3};"
                 : "+f"(c[0]), "+f"(c[1]), "+f"(c[2]), "+f"(c[3])
                 : "r"(a[0]), "r"(a[1]), "r"(a[2]), "r"(a[3]), "r"(b0), "r"(b1));
}

// convert 8 fp32 (32B at sp) into two 16B bf16 limb vectors; returns elem sum.
// Packed cvt: bit-identical to per-scalar __float2bfloat16_rn version.
__device__ __forceinline__ float conv8(const char* sp, char* d0, char* d1) {
    float4 a = ((const float4*)sp)[0];
    float4 b = ((const float4*)sp)[1];
    float fl[8] = {a.x, a.y, a.z, a.w, b.x, b.y, b.z, b.w};
    unsigned p[4], q[4];
    #pragma unroll
    for (int k = 0; k < 4; k++) {
        float lo = fl[2 * k], hi = fl[2 * k + 1];
        unsigned pk;
        asm("cvt.rn.bf16x2.f32 %0, %1, %2;" : "=r"(pk) : "f"(hi), "f"(lo));
        float alo = __uint_as_float(pk << 16);
        float ahi = __uint_as_float(pk & 0xFFFF0000u);
        float rlo = lo - alo, rhi = hi - ahi;
        unsigned qk;
        asm("cvt.rn.bf16x2.f32 %0, %1, %2;" : "=r"(qk) : "f"(rhi), "f"(rlo));
        p[k] = pk; q[k] = qk;
    }
    *(uint4*)d0 = make_uint4(p[0], p[1], p[2], p[3]);
    *(uint4*)d1 = make_uint4(q[0], q[1], q[2], q[3]);
    return ((fl[0] + fl[1]) + (fl[2] + fl[3])) + ((fl[4] + fl[5]) + (fl[6] + fl[7]));
}

__global__ void k_nop() {}

// ---- energy: fused conversion + F = q0 q0^T, G = q0 q1^T --------------------
// self-mapped loads; mma issued BEFORE conv each iter (tensor pipe drains
// queued HMMAs while conv ALU work issues); one sync per iter.
__global__ void __launch_bounds__(256) k_energy_mma(const float* __restrict__ x) {
    extern __shared__ char smraw[];
    char* sm = (char*)(((unsigned long long)smraw + 1023) & ~1023ULL);
    unsigned sb = smem_u32(sm);
    int t = threadIdx.x, lane = t & 31, wid = t >> 5;
    int ks = blockIdx.x, b = blockIdx.y;
    size_t rowbase = (size_t)b * CC * HW + (size_t)ks * KSEG;
    int wm = (wid >> 2) * 64, wn = (wid & 3) * 32;
    float* s_rs = (float*)(sm + 131072);
    float rsacc[4] = {0.f, 0.f, 0.f, 0.f};

    float accF[4][4][4], accG[4][4][4];
    #pragma unroll
    for (int mt = 0; mt < 4; mt++)
        #pragma unroll
        for (int nt = 0; nt < 4; nt++)
            #pragma unroll
            for (int c = 0; c < 4; c++) { accF[mt][nt][c] = 0.f; accG[mt][nt][c] = 0.f; }

    #define X_LOAD(ch) do { \
        unsigned _db = sb + ((ch) & 1) * 32768; \
        _Pragma("unroll") \
        for (int _i = 0; _i < 4; _i++) { \
            int _seg = t + 256 * _i; \
            int _row = _seg >> 3, _part = _seg & 7; \
            const float* _s = x + rowbase + (size_t)_row * HW + (ch) * 64 + _part * 8; \
            CPA(_db + _row * 256 + _part * 32, _s); \
            CPA(_db + _row * 256 + _part * 32 + 16, _s + 4); \
        } \
        CPA_COMMIT(); \
    } while (0)

    #define X_CONV(ch) do { \
        char* _st = sm + ((ch) & 1) * 32768; \
        char* _lb = sm + 65536 + ((ch) & 1) * 32768; \
        _Pragma("unroll") \
        for (int _i = 0; _i < 4; _i++) { \
            int _seg = t + 256 * _i; \
            int _row = _seg >> 3, _part = _seg & 7; \
            unsigned _so = swz((unsigned)(_row * 128 + _part * 16)); \
            rsacc[_i] += conv8(_st + _row * 256 + _part * 32, _lb + _so, _lb + 16384 + _so); \
        } \
    } while (0)

    X_LOAD(0);
    X_LOAD(1);
    CPA_WAIT1();
    X_CONV(0);   // self-mapped: own async data after wait
    __syncthreads();

    for (int ch = 0; ch < 32; ch++) {
        if (ch + 2 < 32) X_LOAD(ch + 2);

        unsigned b0t = sb + 65536 + (ch & 1) * 32768;
        unsigned b1t = b0t + 16384;
        #pragma unroll
        for (int kk = 0; kk < 4; kk++) {
            int kbyte = kk * 32;
            unsigned A[4][4];
            #pragma unroll
            for (int mt = 0; mt < 4; mt++) {
                unsigned off = swz((unsigned)((wm + mt * 16 + (lane & 15)) * 128 + kbyte + (lane >> 4) * 16));
                ldsm4(b0t + off, A[mt]);
            }
            unsigned B0[2][4], B1[2][4];
            #pragma unroll
            for (int nt = 0; nt < 2; nt++) {
                int row = wn + nt * 16 + ((lane >> 4) & 1) * 8 + (lane & 7);
                int kb = kbyte + ((lane >> 3) & 1) * 16;
                unsigned off = swz((unsigned)(row * 128 + kb));
                ldsm4(b0t + off, B0[nt]);
                ldsm4(b1t + off, B1[nt]);
            }
            #pragma unroll
            for (int mt = 0; mt < 4; mt++)
                #pragma unroll
                for (int nt = 0; nt < 2; nt++)
                    #pragma unroll
                    for (int s = 0; s < 2; s++) {
                        mma16816(accF[mt][nt * 2 + s], A[mt], B0[nt][s * 2], B0[nt][s * 2 + 1]);
                        mma16816(accG[mt][nt * 2 + s], A[mt], B1[nt][s * 2], B1[nt][s * 2 + 1]);
                    }
        }

        if (ch + 1 < 32) {
            if (ch + 2 < 32) CPA_WAIT1(); else CPA_WAIT0();
            X_CONV(ch + 1);  // overlaps with in-flight HMMAs
        }
        __syncthreads();
    }
    #undef X_LOAD
    #undef X_CONV

    #pragma unroll
    for (int i = 0; i < 4; i++) s_rs[t + 256 * i] = rsacc[i];  // index = row*8+part
    __syncthreads();
    if (t < 128) {
        float s = 0.f;
        #pragma unroll
        for (int k = 0; k < 8; k++) s += s_rs[t * 8 + k];
        g_rspart[(b * KS1 + ks) * CC + t] = s;
    }

    size_t pbase = ((size_t)(b * KS1 + ks)) * CC * CC;
    int g = lane >> 2, tg = lane & 3;
    #pragma unroll
    for (int mt = 0; mt < 4; mt++)
        #pragma unroll
        for (int nt = 0; nt < 4; nt++) {
            int i0 = wm + mt * 16 + g, j = wn + nt * 8 + tg * 2;
            *(float2*)(g_epF + pbase + (size_t)i0 * CC + j) = make_float2(accF[mt][nt][0], accF[mt][nt][1]);
            *(float2*)(g_epF + pbase + (size_t)(i0 + 8) * CC + j) = make_float2(accF[mt][nt][2], accF[mt][nt][3]);
            *(float2*)(g_epG + pbase + (size_t)i0 * CC + j) = make_float2(accG[mt][nt][0], accG[mt][nt][1]);
            *(float2*)(g_epG + pbase + (size_t)(i0 + 8) * CC + j) = make_float2(accG[mt][nt][2], accG[mt][nt][3]);
        }
}

// ---- finish rowsum ----------------------------------------------------------
__global__ void k_rs2() {
    int b = blockIdx.x, j = threadIdx.x;
    float s = 0.f;
    #pragma unroll
    for (int ks = 0; ks < KS1; ks++) s += g_rspart[(b * KS1 + ks) * CC + j];
    g_rowsum[b * CC + j] = s;
}

// ---- fused E = F + G + G^T  AND softmax -------------------------------------
__global__ void k_redsoft() {
    int islab = blockIdx.x, b = blockIdx.y, t = threadIdx.x;
    __shared__ float sGT[32][132];
    #pragma unroll
    for (int r = 0; r < 4; r++) {
        int idx = t + 256 * r;
        int j = idx >> 3, c4 = idx & 7;
        float4 s = make_float4(0.f, 0.f, 0.f, 0.f);
        #pragma unroll
        for (int ks = 0; ks < KS1; ks++) {
            float4 v = *(const float4*)(g_epG + (((size_t)(b * KS1 + ks) * CC + j)) * CC + islab * 32 + c4 * 4);
            s.x += v.x; s.y += v.y; s.z += v.z; s.w += v.w;
        }
        sGT[c4 * 4 + 0][j] = s.x;
        sGT[c4 * 4 + 1][j] = s.y;
        sGT[c4 * 4 + 2][j] = s.z;
        sGT[c4 * 4 + 3][j] = s.w;
    }
    __syncthreads();
    #pragma unroll
    for (int r = 0; r < 4; r++) {
        int idx = t + 256 * r;
        int il = idx >> 5, j4 = idx & 31;
        int i = islab * 32 + il;
        float4 f = make_float4(0.f, 0.f, 0.f, 0.f);
        #pragma unroll
        for (int ks = 0; ks < KS1; ks++) {
            size_t o = (((size_t)(b * KS1 + ks) * CC + i)) * CC + j4 * 4;
            float4 vf = *(const float4*)(g_epF + o);
            float4 vg = *(const float4*)(g_epG + o);
            f.x += vf.x + vg.x; f.y += vf.y + vg.y; f.z += vf.z + vg.z; f.w += vf.w + vg.w;
        }
        float4 gt = *(const float4*)&sGT[il][j4 * 4];
        float4 e = make_float4(f.x + gt.x, f.y + gt.y, f.z + gt.z, f.w + gt.w);
        *(float4*)(g_energy + ((size_t)(b * CC + i)) * CC + j4 * 4) = e;
        float mx = fmaxf(fmaxf(e.x, e.y), fmaxf(e.z, e.w));
        #pragma unroll
        for (int o = 16; o; o >>= 1) mx = fmaxf(mx, __shfl_xor_sync(0xffffffffu, mx, o));
        float e0 = mx - e.x, e1 = mx - e.y, e2 = mx - e.z, e3 = mx - e.w;
        float m2 = fmaxf(fmaxf(e0, e1), fmaxf(e2, e3));
        #pragma unroll
        for (int o = 16; o; o >>= 1) m2 = fmaxf(m2, __shfl_xor_sync(0xffffffffu, m2, o));
        float p0 = expf(e0 - m2), p1 = expf(e1 - m2), p2 = expf(e2 - m2), p3 = expf(e3 - m2);
        float s = (p0 + p1) + (p2 + p3);
        #pragma unroll
        for (int o = 16; o; o >>= 1) s += __shfl_xor_sync(0xffffffffu, s, o);
        float inv = 1.f / s;
        *(float4*)(g_attn + ((size_t)(b * CC + i)) * CC + j4 * 4) =
            make_float4(p0 * inv, p1 * inv, p2 * inv, p3 * inv);
    }
}

// ---- BN stats partials, grid (16 cslabs, BB), warp = 1 channel --------------
__global__ void __launch_bounds__(256) k_stats1() {
    int cs = blockIdx.x, b = blockIdx.y, t = threadIdx.x, lane = t & 31, w = t >> 5;
    extern __shared__ float sms[];
    float* sE = sms;                 // [k=128][j=128]
    float* sA = sms + 16384;         // [8][128]
    float* sR = sms + 16384 + 1024;  // [128]
    const float4* Eg = (const float4*)(g_energy + (size_t)b * CC * CC);
    for (int i = t; i < 4096; i += 256) ((float4*)sE)[i] = Eg[i];
    const float4* Ag = (const float4*)(g_attn + ((size_t)b * CC + cs * 8) * CC);
    if (t < 256) ((float4*)sA)[t] = Ag[t];
    if (t < 32) ((float4*)sR)[t] = ((const float4*)(g_rowsum + b * CC))[t];
    __syncthreads();

    float accT[4] = {0.f, 0.f, 0.f, 0.f};
    for (int k = 0; k < 128; k++) {
        float4 e = *(float4*)&sE[k * 128 + lane * 4];
        float a = sA[w * 128 + k];
        accT[0] += a * e.x; accT[1] += a * e.y;
        accT[2] += a * e.z; accT[3] += a * e.w;
    }
    float4 r4 = *(float4*)&sR[lane * 4];
    float4 a4 = *(float4*)&sA[w * 128 + lane * 4];
    float l2 = accT[0] * a4.x + accT[1] * a4.y + accT[2] * a4.z + accT[3] * a4.w;
    float l1 = r4.x * a4.x + r4.y * a4.y + r4.z * a4.z + r4.w * a4.w;
    #pragma unroll
    for (int o = 16; o; o >>= 1) {
        l1 += __shfl_xor_sync(0xffffffffu, l1, o);
        l2 += __shfl_xor_sync(0xffffffffu, l2, o);
    }
    if (lane == 0) {
        g_part1[b * CC + cs * 8 + w] = l1;
        g_part2[b * CC + cs * 8 + w] = l2;
    }
}

// ---- finalize scale/shift ---------------------------------------------------
__global__ void k_stats2(const float* __restrict__ gamma,
                         const float* __restrict__ bn_w,
                         const float* __restrict__ bn_b) {
    int c = threadIdx.x;
    float a1 = 0.f, a2 = 0.f;
    #pragma unroll
    for (int b = 0; b < BB; b++) { a1 += g_part1[b * CC + c]; a2 += g_part2[b * CC + c]; }
    float g = gamma[0];
    float invN = 1.f / (float)((size_t)BB * HW);
    float mean = g * a1 * invN;
    float ey2 = g * g * a2 * invN;
    float rstd = rsqrtf(ey2 - mean * mean + 1e-5f);
    float w = bn_w[c];
    g_scale[c] = g * rstd * w;
    g_shift[c] = bn_b[c] - mean * rstd * w;
}

// ---- attn limbs with scale folded -------------------------------------------
__global__ void k_alimb() {
    int b = blockIdx.x, j = threadIdx.x;
    int half = j >> 6, jl = j & 63;
    for (int i = 0; i < 128; i++) {
        float v = g_attn[((size_t)(b * CC + i)) * CC + j] * g_scale[i];
        __nv_bfloat16 a0 = __float2bfloat16_rn(v);
        __nv_bfloat16 a1 = __float2bfloat16_rn(v - __bfloat162float(a0));
        g_al[(((size_t)(b * 2 + 0) * 2 + half) * CC + i) * 64 + jl] = a0;
        g_al[(((size_t)(b * 2 + 1) * 2 + half) * CC + i) * 64 + jl] = a1;
    }
}

// ---- out GEMM: warp-specialized, 3-deep ring (limb+X per slot) --------------
// slot s (s=0..2) at sb + s*67584: limb0 16K | limb1 16K | X 34816 (272B rows)
// A tiles staged in slot2 region during prologue then hoisted; s_shift @202752.
__global__ void __launch_bounds__(256) k_out_mma(const float* __restrict__ x,
                                                 float* __restrict__ out) {
    extern __shared__ char smraw[];
    char* sm = (char*)(((unsigned long long)smraw + 1023) & ~1023ULL);
    unsigned sb = smem_u32(sm);
    int t = threadIdx.x, lane = t & 31, wid = t >> 5;
    int nb = blockIdx.x, b = blockIdx.y;  // nb: 8 chunks of 2048 cols
    size_t xrow = (size_t)b * CC * HW;
    const unsigned SLOT = 67584;
    float* s_shift = (float*)(sm + 3 * SLOT);

    if (wid < 4) {
        // ================= MMA warps =================
        int wm = wid * 32;
        unsigned asmb = sb + 2 * SLOT;  // A staging region (slot 2)
        #pragma unroll
        for (int i = 0; i < 32; i++) {
            int idx = t + 128 * i;
            int tile = idx >> 10, rem = idx & 1023, row = rem >> 3, part = rem & 7;
            int limb = tile >> 1, half = tile & 1;
            const void* src = g_al + (((size_t)(b * 2 + limb) * 2 + half) * CC + row) * 64 + part * 8;
            CPA(asmb + tile * 16384 + swz((unsigned)(row * 128 + part * 16)), src);
        }
        CPA_COMMIT();
        s_shift[t] = g_shift[t];
        CPA_WAIT0();
        NBAR_SYNC(8, 128);  // all MMA warps' A data landed

        unsigned A0h[8][2][4], A1h[8][2][4];
        #pragma unroll
        for (int ksp = 0; ksp < 8; ksp++) {
            int jhalf = ksp >> 2;
            unsigned kb = (unsigned)((ksp & 3) * 32 + (lane >> 4) * 16);
            #pragma unroll
            for (int mt = 0; mt < 2; mt++) {
                unsigned off = swz((unsigned)((wm + mt * 16 + (lane & 15)) * 128) + kb);
                ldsm4(asmb + (0 + jhalf) * 16384 + off, A0h[ksp][mt]);
                ldsm4(asmb + (2 + jhalf) * 16384 + off, A1h[ksp][mt]);
            }
        }
        NBAR_ARRIVE(9, 256);  // slot 2 region free for IO

        int g = lane >> 2, tg = lane & 3;
        for (int it = 0; it < 32; it++) {
            int slot = it % 3;
            NBAR_SYNC(1 + slot, 256);  // limb+X slot ready

            float acc[2][8][4];
            #pragma unroll
            for (int mt = 0; mt < 2; mt++)
                #pragma unroll
                for (int nf = 0; nf < 8; nf++)
                    #pragma unroll
                    for (int c = 0; c < 4; c++) acc[mt][nf][c] = 0.f;

            unsigned Bt0 = sb + slot * SLOT;
            unsigned Bt1 = Bt0 + 16384;
            #pragma unroll
            for (int ksp = 0; ksp < 8; ksp++) {
                int jrow = ksp * 16 + ((lane >> 3) & 1) * 8 + (lane & 7);
                #pragma unroll
                for (int f = 0; f < 4; f++) {
                    int ncol = f * 16 + ((lane >> 4) & 1) * 8;
                    unsigned offb = swz((unsigned)(jrow * 128 + ncol * 2));
                    unsigned B0[4], B1[4];
                    ldsm4t(Bt0 + offb, B0);
                    ldsm4t(Bt1 + offb, B1);
                    #pragma unroll
                    for (int mt = 0; mt < 2; mt++)
                        #pragma unroll
                        for (int s = 0; s < 2; s++) {
                            float* c = acc[mt][f * 2 + s];
                            mma16816(c, A0h[ksp][mt], B0[s * 2], B0[s * 2 + 1]);
                            mma16816(c, A0h[ksp][mt], B1[s * 2], B1[s * 2 + 1]);
                            mma16816(c, A1h[ksp][mt], B0[s * 2], B0[s * 2 + 1]);
                        }
                }
            }

            const char* xc = sm + slot * SLOT + 32768;
            size_t gbase = xrow + (size_t)nb * 2048 + it * 64;
            #pragma unroll
            for (int mt = 0; mt < 2; mt++) {
                int i0 = wm + mt * 16 + g;
                float sh0 = s_shift[i0], sh1 = s_shift[i0 + 8];
                #pragma unroll
                for (int nf = 0; nf < 8; nf++) {
                    int col = nf * 8 + tg * 2;
                    float2 xv0 = *(const float2*)(xc + i0 * 272 + col * 4);
                    float2 xv1 = *(const float2*)(xc + (i0 + 8) * 272 + col * 4);
                    *(float2*)(out + gbase + (size_t)i0 * HW + col) =
                        make_float2(acc[mt][nf][0] + sh0 + xv0.x, acc[mt][nf][1] + sh0 + xv0.y);
                    *(float2*)(out + gbase + (size_t)(i0 + 8) * HW + col) =
                        make_float2(acc[mt][nf][2] + sh1 + xv1.x, acc[mt][nf][3] + sh1 + xv1.y);
                }
            }
            if (it + 3 < 32) NBAR_ARRIVE(4 + slot, 256);  // slot consumed
        }
    } else {
        // ================= IO warps =================
        int tio = t - 128;

        #define OX_LOAD(it) do { \
            unsigned _db = sb + ((it) % 3) * SLOT + 32768; \
            size_t _nbase = (size_t)nb * 2048 + (it) * 64; \
            _Pragma("unroll") \
            for (int _i = 0; _i < 8; _i++) { \
                int _seg = tio + 128 * _i; \
                int _row = _seg >> 3, _part = _seg & 7; \
                const float* _s = x + xrow + (size_t)_row * HW + _nbase + _part * 8; \
                CPA(_db + _row * 272 + _part * 32, _s); \
                CPA(_db + _row * 272 + _part * 32 + 16, _s + 4); \
            } \
            CPA_COMMIT(); \
        } while (0)

        #define OX_CONV(it) do { \
            const char* _st = sm + ((it) % 3) * SLOT + 32768; \
            char* _lb = sm + ((it) % 3) * SLOT; \
            _Pragma("unroll") \
            for (int _i = 0; _i < 8; _i++) { \
                int _seg = tio + 128 * _i; \
                int _row = _seg >> 3, _part = _seg & 7; \
                unsigned _so = swz((unsigned)(_row * 128 + _part * 16)); \
                conv8(_st + _row * 272 + _part * 32, _lb + _so, _lb + 16384 + _so); \
            } \
        } while (0)

        OX_LOAD(0);
        OX_LOAD(1);
        CPA_WAIT1();
        OX_CONV(0);
        NBAR_ARRIVE(1, 256);
        CPA_WAIT0();
        OX_CONV(1);
        NBAR_ARRIVE(2, 256);
        NBAR_SYNC(9, 256);   // MMA finished hoisting A from slot-2 region
        OX_LOAD(2);
        CPA_WAIT0();
        OX_CONV(2);
        NBAR_ARRIVE(3, 256);

        for (int it = 0; it + 3 < 32; it++) {
            int slot = it % 3;
            NBAR_SYNC(4 + slot, 256);  // MMA done with slot it
            OX_LOAD(it + 3);           // same slot (it+3)%3 == slot
            CPA_WAIT0();
            OX_CONV(it + 3);
            NBAR_ARRIVE(1 + slot, 256);
        }
        #undef OX_LOAD
        #undef OX_CONV
    }
}

extern "C" void kernel_launch(void* const* d_in, const int* in_sizes, int n_in,
                              void* d_out, int out_size) {
    const float* x = (const float*)d_in[0];
    const float* gamma = (const float*)d_in[1];
    const float* bn_w = (const float*)d_in[2];
    const float* bn_b = (const float*)d_in[3];
    float* out = (float*)d_out;

    int smE = 65536 + 65536 + 4096 + 1024;            // ~133 KB
    int smS = (16384 + 1024 + 128) * 4 + 256;         // ~68.8 KB
    int smO = 3 * 67584 + 512 + 1024;                 // ~204 KB
    cudaFuncSetAttribute(k_energy_mma, cudaFuncAttributeMaxDynamicSharedMemorySize, smE);
    cudaFuncSetAttribute(k_stats1, cudaFuncAttributeMaxDynamicSharedMemorySize, smS);
    cudaFuncSetAttribute(k_out_mma, cudaFuncAttributeMaxDynamicSharedMemorySize, smO);

    k_nop<<<1, 1>>>();                                // 0
    k_nop<<<1, 1>>>();                                // 1
    k_nop<<<1, 1>>>();                                // 2
    k_energy_mma<<<dim3(KS1, BB), 256, smE>>>(x);     // 3 (ncu capture slot)
    k_rs2<<<BB, CC>>>();                              // 4
    k_redsoft<<<dim3(4, BB), 256>>>();                // 5
    k_stats1<<<dim3(16, BB), 256, smS>>>();           // 6
    k_stats2<<<1, 128>>>(gamma, bn_w, bn_b);          // 7
    k_alimb<<<BB, 128>>>();                           // 8
    k_out_mma<<<dim3(8, BB), 256, smO>>>(x, out);     // 9
}

// round 13
// speedup vs baseline: 3.4595x; 1.0330x over previous
#include <cuda_runtime.h>
#include <cuda_bf16.h>
#include <math.h>

#define BB 16
#define CC 128
#define HW 16384
#define KS1 8
#define KSEG (HW / KS1)  // 2048

__device__ float g_energy[BB * CC * CC];
__device__ float g_epF[BB * KS1 * CC * CC];
__device__ float g_epG[BB * KS1 * CC * CC];
__device__ float g_attn[BB * CC * CC];
__device__ float g_rspart[BB * KS1 * CC];
__device__ float g_part1[BB * CC];
__device__ float g_part2[BB * CC];

__device__ __forceinline__ unsigned smem_u32(const void* p) {
    unsigned a;
    asm("{ .reg .u64 t; cvta.to.shared.u64 t, %1; cvt.u32.u64 %0, t; }" : "=r"(a) : "l"(p));
    return a;
}
__device__ __forceinline__ unsigned swz(unsigned o) { return o ^ ((o >> 3) & 0x70); }

#define CPA(dst, src) asm volatile("cp.async.ca.shared.global [%0], [%1], 16;" :: "r"(dst), "l"(src))
#define CPA_COMMIT()  asm volatile("cp.async.commit_group;" ::: "memory")
#define CPA_WAIT0()   asm volatile("cp.async.wait_group 0;" ::: "memory")
#define CPA_WAIT1()   asm volatile("cp.async.wait_group 1;" ::: "memory")
#define NBAR_SYNC(id, n)   asm volatile("bar.sync %0, %1;"   :: "r"(id), "r"(n) : "memory")
#define NBAR_ARRIVE(id, n) asm volatile("bar.arrive %0, %1;" :: "r"(id), "r"(n) : "memory")

__device__ __forceinline__ void ldsm4(unsigned a, unsigned r[4]) {
    asm volatile("ldmatrix.sync.aligned.m8n8.x4.shared.b16 {%0,%1,%2,%3}, [%4];"
                 : "=r"(r[0]), "=r"(r[1]), "=r"(r[2]), "=r"(r[3]) : "r"(a));
}
__device__ __forceinline__ void ldsm4t(unsigned a, unsigned r[4]) {
    asm volatile("ldmatrix.sync.aligned.m8n8.x4.trans.shared.b16 {%0,%1,%2,%3}, [%4];"
                 : "=r"(r[0]), "=r"(r[1]), "=r"(r[2]), "=r"(r[3]) : "r"(a));
}
__device__ __forceinline__ void mma16816(float c[4], const unsigned a[4], unsigned b0, unsigned b1) {
    asm volatile("mma.sync.aligned.m16n8k16.row.col.f32.bf16.bf16.f32 "
                 "{%0,%1,%2,%3}, {%4,%5,%6,%7}, {%8,%9}, {%0,%1,%2,%3};"
                 : "+f"(c[0]), "+f"(c[1]), "+f"(c[2]), "+f"(c[3])
                 : "r"(a[0]), "r"(a[1]), "r"(a[2]), "r"(a[3]), "r"(b0), "r"(b1));
}

// packed 2-limb bf16 split of 8 fp32 regs -> two 16B stores (bit-identical
// to per-scalar __float2bfloat16_rn)
__device__ __forceinline__ void conv8r(const float* fl, char* d0, char* d1) {
    unsigned p[4], q[4];
    #pragma unroll
    for (int k = 0; k < 4; k++) {
        float lo = fl[2 * k], hi = fl[2 * k + 1];
        unsigned pk;
        asm("cvt.rn.bf16x2.f32 %0, %1, %2;" : "=r"(pk) : "f"(hi), "f"(lo));
        float rlo = lo - __uint_as_float(pk << 16);
        float rhi = hi - __uint_as_float(pk & 0xFFFF0000u);
        unsigned qk;
        asm("cvt.rn.bf16x2.f32 %0, %1, %2;" : "=r"(qk) : "f"(rhi), "f"(rlo));
        p[k] = pk; q[k] = qk;
    }
    *(uint4*)d0 = make_uint4(p[0], p[1], p[2], p[3]);
    *(uint4*)d1 = make_uint4(q[0], q[1], q[2], q[3]);
}
__device__ __forceinline__ float conv8(const char* sp, char* d0, char* d1) {
    float4 a = ((const float4*)sp)[0];
    float4 b = ((const float4*)sp)[1];
    float fl[8] = {a.x, a.y, a.z, a.w, b.x, b.y, b.z, b.w};
    conv8r(fl, d0, d1);
    return ((fl[0] + fl[1]) + (fl[2] + fl[3])) + ((fl[4] + fl[5]) + (fl[6] + fl[7]));
}

// ---- kernel 0: energy (unchanged from R12) ----------------------------------
__global__ void __launch_bounds__(256) k_energy_mma(const float* __restrict__ x) {
    extern __shared__ char smraw[];
    char* sm = (char*)(((unsigned long long)smraw + 1023) & ~1023ULL);
    unsigned sb = smem_u32(sm);
    int t = threadIdx.x, lane = t & 31, wid = t >> 5;
    int ks = blockIdx.x, b = blockIdx.y;
    size_t rowbase = (size_t)b * CC * HW + (size_t)ks * KSEG;
    int wm = (wid >> 2) * 64, wn = (wid & 3) * 32;
    float* s_rs = (float*)(sm + 131072);
    float rsacc[4] = {0.f, 0.f, 0.f, 0.f};

    float accF[4][4][4], accG[4][4][4];
    #pragma unroll
    for (int mt = 0; mt < 4; mt++)
        #pragma unroll
        for (int nt = 0; nt < 4; nt++)
            #pragma unroll
            for (int c = 0; c < 4; c++) { accF[mt][nt][c] = 0.f; accG[mt][nt][c] = 0.f; }

    #define X_LOAD(ch) do { \
        unsigned _db = sb + ((ch) & 1) * 32768; \
        _Pragma("unroll") \
        for (int _i = 0; _i < 4; _i++) { \
            int _seg = t + 256 * _i; \
            int _row = _seg >> 3, _part = _seg & 7; \
            const float* _s = x + rowbase + (size_t)_row * HW + (ch) * 64 + _part * 8; \
            CPA(_db + _row * 256 + _part * 32, _s); \
            CPA(_db + _row * 256 + _part * 32 + 16, _s + 4); \
        } \
        CPA_COMMIT(); \
    } while (0)

    #define X_CONV(ch) do { \
        char* _st = sm + ((ch) & 1) * 32768; \
        char* _lb = sm + 65536 + ((ch) & 1) * 32768; \
        _Pragma("unroll") \
        for (int _i = 0; _i < 4; _i++) { \
            int _seg = t + 256 * _i; \
            int _row = _seg >> 3, _part = _seg & 7; \
            unsigned _so = swz((unsigned)(_row * 128 + _part * 16)); \
            rsacc[_i] += conv8(_st + _row * 256 + _part * 32, _lb + _so, _lb + 16384 + _so); \
        } \
    } while (0)

    X_LOAD(0);
    X_LOAD(1);
    CPA_WAIT1();
    X_CONV(0);
    __syncthreads();

    for (int ch = 0; ch < 32; ch++) {
        if (ch + 2 < 32) X_LOAD(ch + 2);

        unsigned b0t = sb + 65536 + (ch & 1) * 32768;
        unsigned b1t = b0t + 16384;
        #pragma unroll
        for (int kk = 0; kk < 4; kk++) {
            int kbyte = kk * 32;
            unsigned A[4][4];
            #pragma unroll
            for (int mt = 0; mt < 4; mt++) {
                unsigned off = swz((unsigned)((wm + mt * 16 + (lane & 15)) * 128 + kbyte + (lane >> 4) * 16));
                ldsm4(b0t + off, A[mt]);
            }
            unsigned B0[2][4], B1[2][4];
            #pragma unroll
            for (int nt = 0; nt < 2; nt++) {
                int row = wn + nt * 16 + ((lane >> 4) & 1) * 8 + (lane & 7);
                int kb = kbyte + ((lane >> 3) & 1) * 16;
                unsigned off = swz((unsigned)(row * 128 + kb));
                ldsm4(b0t + off, B0[nt]);
                ldsm4(b1t + off, B1[nt]);
            }
            #pragma unroll
            for (int mt = 0; mt < 4; mt++)
                #pragma unroll
                for (int nt = 0; nt < 2; nt++)
                    #pragma unroll
                    for (int s = 0; s < 2; s++) {
                        mma16816(accF[mt][nt * 2 + s], A[mt], B0[nt][s * 2], B0[nt][s * 2 + 1]);
                        mma16816(accG[mt][nt * 2 + s], A[mt], B1[nt][s * 2], B1[nt][s * 2 + 1]);
                    }
        }

        if (ch + 1 < 32) {
            if (ch + 2 < 32) CPA_WAIT1(); else CPA_WAIT0();
            X_CONV(ch + 1);
        }
        __syncthreads();
    }
    #undef X_LOAD
    #undef X_CONV

    #pragma unroll
    for (int i = 0; i < 4; i++) s_rs[t + 256 * i] = rsacc[i];
    __syncthreads();
    if (t < 128) {
        float s = 0.f;
        #pragma unroll
        for (int k = 0; k < 8; k++) s += s_rs[t * 8 + k];
        g_rspart[(b * KS1 + ks) * CC + t] = s;
    }

    size_t pbase = ((size_t)(b * KS1 + ks)) * CC * CC;
    int g = lane >> 2, tg = lane & 3;
    #pragma unroll
    for (int mt = 0; mt < 4; mt++)
        #pragma unroll
        for (int nt = 0; nt < 4; nt++) {
            int i0 = wm + mt * 16 + g, j = wn + nt * 8 + tg * 2;
            *(float2*)(g_epF + pbase + (size_t)i0 * CC + j) = make_float2(accF[mt][nt][0], accF[mt][nt][1]);
            *(float2*)(g_epF + pbase + (size_t)(i0 + 8) * CC + j) = make_float2(accF[mt][nt][2], accF[mt][nt][3]);
            *(float2*)(g_epG + pbase + (size_t)i0 * CC + j) = make_float2(accG[mt][nt][0], accG[mt][nt][1]);
            *(float2*)(g_epG + pbase + (size_t)(i0 + 8) * CC + j) = make_float2(accG[mt][nt][2], accG[mt][nt][3]);
        }
}

// ---- kernel 1: fused E = F + G + G^T  AND softmax ---------------------------
__global__ void k_redsoft() {
    int islab = blockIdx.x, b = blockIdx.y, t = threadIdx.x;
    __shared__ float sGT[32][132];
    #pragma unroll
    for (int r = 0; r < 4; r++) {
        int idx = t + 256 * r;
        int j = idx >> 3, c4 = idx & 7;
        float4 s = make_float4(0.f, 0.f, 0.f, 0.f);
        #pragma unroll
        for (int ks = 0; ks < KS1; ks++) {
            float4 v = *(const float4*)(g_epG + (((size_t)(b * KS1 + ks) * CC + j)) * CC + islab * 32 + c4 * 4);
            s.x += v.x; s.y += v.y; s.z += v.z; s.w += v.w;
        }
        sGT[c4 * 4 + 0][j] = s.x;
        sGT[c4 * 4 + 1][j] = s.y;
        sGT[c4 * 4 + 2][j] = s.z;
        sGT[c4 * 4 + 3][j] = s.w;
    }
    __syncthreads();
    #pragma unroll
    for (int r = 0; r < 4; r++) {
        int idx = t + 256 * r;
        int il = idx >> 5, j4 = idx & 31;
        int i = islab * 32 + il;
        float4 f = make_float4(0.f, 0.f, 0.f, 0.f);
        #pragma unroll
        for (int ks = 0; ks < KS1; ks++) {
            size_t o = (((size_t)(b * KS1 + ks) * CC + i)) * CC + j4 * 4;
            float4 vf = *(const float4*)(g_epF + o);
            float4 vg = *(const float4*)(g_epG + o);
            f.x += vf.x + vg.x; f.y += vf.y + vg.y; f.z += vf.z + vg.z; f.w += vf.w + vg.w;
        }
        float4 gt = *(const float4*)&sGT[il][j4 * 4];
        float4 e = make_float4(f.x + gt.x, f.y + gt.y, f.z + gt.z, f.w + gt.w);
        *(float4*)(g_energy + ((size_t)(b * CC + i)) * CC + j4 * 4) = e;
        float mx = fmaxf(fmaxf(e.x, e.y), fmaxf(e.z, e.w));
        #pragma unroll
        for (int o = 16; o; o >>= 1) mx = fmaxf(mx, __shfl_xor_sync(0xffffffffu, mx, o));
        float e0 = mx - e.x, e1 = mx - e.y, e2 = mx - e.z, e3 = mx - e.w;
        float m2 = fmaxf(fmaxf(e0, e1), fmaxf(e2, e3));
        #pragma unroll
        for (int o = 16; o; o >>= 1) m2 = fmaxf(m2, __shfl_xor_sync(0xffffffffu, m2, o));
        float p0 = expf(e0 - m2), p1 = expf(e1 - m2), p2 = expf(e2 - m2), p3 = expf(e3 - m2);
        float s = (p0 + p1) + (p2 + p3);
        #pragma unroll
        for (int o = 16; o; o >>= 1) s += __shfl_xor_sync(0xffffffffu, s, o);
        float inv = 1.f / s;
        *(float4*)(g_attn + ((size_t)(b * CC + i)) * CC + j4 * 4) =
            make_float4(p0 * inv, p1 * inv, p2 * inv, p3 * inv);
    }
}

// ---- kernel 2: BN stats partials (rowsum fused from rspart) -----------------
__global__ void __launch_bounds__(256) k_stats1() {
    int cs = blockIdx.x, b = blockIdx.y, t = threadIdx.x, lane = t & 31, w = t >> 5;
    extern __shared__ float sms[];
    float* sE = sms;                 // [k=128][j=128]
    float* sA = sms + 16384;         // [8][128]
    float* sR = sms + 16384 + 1024;  // [128]
    const float4* Eg = (const float4*)(g_energy + (size_t)b * CC * CC);
    for (int i = t; i < 4096; i += 256) ((float4*)sE)[i] = Eg[i];
    const float4* Ag = (const float4*)(g_attn + ((size_t)b * CC + cs * 8) * CC);
    if (t < 256) ((float4*)sA)[t] = Ag[t];
    if (t < 128) {
        float s = 0.f;
        #pragma unroll
        for (int ks = 0; ks < KS1; ks++) s += g_rspart[(b * KS1 + ks) * CC + t];
        sR[t] = s;
    }
    __syncthreads();

    float accT[4] = {0.f, 0.f, 0.f, 0.f};
    for (int k = 0; k < 128; k++) {
        float4 e = *(float4*)&sE[k * 128 + lane * 4];
        float a = sA[w * 128 + k];
        accT[0] += a * e.x; accT[1] += a * e.y;
        accT[2] += a * e.z; accT[3] += a * e.w;
    }
    float4 r4 = *(float4*)&sR[lane * 4];
    float4 a4 = *(float4*)&sA[w * 128 + lane * 4];
    float l2 = accT[0] * a4.x + accT[1] * a4.y + accT[2] * a4.z + accT[3] * a4.w;
    float l1 = r4.x * a4.x + r4.y * a4.y + r4.z * a4.z + r4.w * a4.w;
    #pragma unroll
    for (int o = 16; o; o >>= 1) {
        l1 += __shfl_xor_sync(0xffffffffu, l1, o);
        l2 += __shfl_xor_sync(0xffffffffu, l2, o);
    }
    if (lane == 0) {
        g_part1[b * CC + cs * 8 + w] = l1;
        g_part2[b * CC + cs * 8 + w] = l2;
    }
}

// ---- kernel 3: out GEMM — fused stats2/alimb prologue, 4-slot limb ring,
//      IO: LDG->regs->conv->STS; MMA: x reg-prefetch, early slot-free arrive --
// smem: A limbs 4x16K @0 | ring 4x32K @65536 | s_scale @196608 | s_shift @197120
__global__ void __launch_bounds__(256) k_out_mma(const float* __restrict__ x,
                                                 float* __restrict__ out,
                                                 const float* __restrict__ gamma,
                                                 const float* __restrict__ bn_w,
                                                 const float* __restrict__ bn_b) {
    extern __shared__ char smraw[];
    char* sm = (char*)(((unsigned long long)smraw + 1023) & ~1023ULL);
    unsigned sb = smem_u32(sm);
    int t = threadIdx.x, lane = t & 31, wid = t >> 5;
    int nb = blockIdx.x, b = blockIdx.y;  // nb: 8 chunks of 2048 cols
    size_t xrow = (size_t)b * CC * HW;
    float* s_scale = (float*)(sm + 196608);
    float* s_shift = (float*)(sm + 197120);

    // ---- prologue: scale/shift (fused stats2) ----
    if (t < 128) {
        float a1 = 0.f, a2 = 0.f;
        #pragma unroll
        for (int bb = 0; bb < BB; bb++) { a1 += g_part1[bb * CC + t]; a2 += g_part2[bb * CC + t]; }
        float gg = gamma[0];
        float invN = 1.f / (float)((size_t)BB * HW);
        float mean = gg * a1 * invN;
        float ey2 = gg * gg * a2 * invN;
        float rstd = rsqrtf(ey2 - mean * mean + 1e-5f);
        float w = bn_w[t];
        s_scale[t] = gg * rstd * w;
        s_shift[t] = bn_b[t] - mean * rstd * w;
    }
    __syncthreads();
    // ---- prologue: attn -> A limb tiles (fused alimb) ----
    #pragma unroll
    for (int i2 = 0; i2 < 8; i2++) {
        int seg = t + 256 * i2;           // 2048 segs: 128 rows x 16 jparts
        int row = seg >> 4, jp = seg & 15;
        int jhalf = jp >> 3, part = jp & 7;
        const float4* ap = (const float4*)(g_attn + ((size_t)(b * CC + row)) * CC + jp * 8);
        float4 v0 = ap[0], v1 = ap[1];
        float sc = s_scale[row];
        float fl[8] = {v0.x * sc, v0.y * sc, v0.z * sc, v0.w * sc,
                       v1.x * sc, v1.y * sc, v1.z * sc, v1.w * sc};
        unsigned so = swz((unsigned)(row * 128 + part * 16));
        conv8r(fl, sm + jhalf * 16384 + so, sm + (2 + jhalf) * 16384 + so);
    }
    __syncthreads();

    if (wid < 4) {
        // ================= MMA warps =================
        int wm = wid * 32;
        int g = lane >> 2, tg = lane & 3;

        unsigned A0h[8][2][4];
        #pragma unroll
        for (int ksp = 0; ksp < 8; ksp++) {
            int jhalf = ksp >> 2;
            unsigned kb = (unsigned)((ksp & 3) * 32 + (lane >> 4) * 16);
            #pragma unroll
            for (int mt = 0; mt < 2; mt++) {
                unsigned off = swz((unsigned)((wm + mt * 16 + (lane & 15)) * 128) + kb);
                ldsm4(sb + jhalf * 16384 + off, A0h[ksp][mt]);
            }
        }

        for (int it = 0; it < 32; it++) {
            int slot = it & 3;
            NBAR_SYNC(1 + slot, 256);  // limb slot ready

            // prefetch x for this iteration's epilogue (hidden under MMA)
            size_t gx = xrow + (size_t)nb * 2048 + it * 64;
            float2 xp0[2][8], xp1[2][8];
            #pragma unroll
            for (int mt = 0; mt < 2; mt++) {
                int i0 = wm + mt * 16 + g;
                #pragma unroll
                for (int nf = 0; nf < 8; nf++) {
                    int col = nf * 8 + tg * 2;
                    xp0[mt][nf] = *(const float2*)(x + gx + (size_t)i0 * HW + col);
                    xp1[mt][nf] = *(const float2*)(x + gx + (size_t)(i0 + 8) * HW + col);
                }
            }

            float acc[2][8][4];
            #pragma unroll
            for (int mt = 0; mt < 2; mt++)
                #pragma unroll
                for (int nf = 0; nf < 8; nf++)
                    #pragma unroll
                    for (int c = 0; c < 4; c++) acc[mt][nf][c] = 0.f;

            unsigned Bt0 = sb + 65536 + slot * 32768;
            unsigned Bt1 = Bt0 + 16384;
            #pragma unroll
            for (int ksp = 0; ksp < 8; ksp++) {
                // A limb1 fragments from smem (not hoisted; saves regs)
                unsigned A1t[2][4];
                {
                    int jhalf = ksp >> 2;
                    unsigned kb = (unsigned)((ksp & 3) * 32 + (lane >> 4) * 16);
                    #pragma unroll
                    for (int mt = 0; mt < 2; mt++) {
                        unsigned off = swz((unsigned)((wm + mt * 16 + (lane & 15)) * 128) + kb);
                        ldsm4(sb + (2 + jhalf) * 16384 + off, A1t[mt]);
                    }
                }
                int jrow = ksp * 16 + ((lane >> 3) & 1) * 8 + (lane & 7);
                #pragma unroll
                for (int f = 0; f < 4; f++) {
                    int ncol = f * 16 + ((lane >> 4) & 1) * 8;
                    unsigned offb = swz((unsigned)(jrow * 128 + ncol * 2));
                    unsigned B0[4], B1[4];
                    ldsm4t(Bt0 + offb, B0);
                    ldsm4t(Bt1 + offb, B1);
                    #pragma unroll
                    for (int mt = 0; mt < 2; mt++)
                        #pragma unroll
                        for (int s = 0; s < 2; s++) {
                            float* c = acc[mt][f * 2 + s];
                            mma16816(c, A0h[ksp][mt], B0[s * 2], B0[s * 2 + 1]);
                            mma16816(c, A0h[ksp][mt], B1[s * 2], B1[s * 2 + 1]);
                            mma16816(c, A1t[mt], B0[s * 2], B0[s * 2 + 1]);
                        }
                }
            }
            if (it + 4 < 32) NBAR_ARRIVE(5 + slot, 256);  // limbs consumed: slot free

            // epilogue: acc + shift + x (regs), direct stores
            #pragma unroll
            for (int mt = 0; mt < 2; mt++) {
                int i0 = wm + mt * 16 + g;
                float sh0 = s_shift[i0], sh1 = s_shift[i0 + 8];
                #pragma unroll
                for (int nf = 0; nf < 8; nf++) {
                    int col = nf * 8 + tg * 2;
                    *(float2*)(out + gx + (size_t)i0 * HW + col) =
                        make_float2(acc[mt][nf][0] + sh0 + xp0[mt][nf].x,
                                    acc[mt][nf][1] + sh0 + xp0[mt][nf].y);
                    *(float2*)(out + gx + (size_t)(i0 + 8) * HW + col) =
                        make_float2(acc[mt][nf][2] + sh1 + xp1[mt][nf].x,
                                    acc[mt][nf][3] + sh1 + xp1[mt][nf].y);
                }
            }
        }
    } else {
        // ================= IO warps =================
        int tio = t - 128;
        float4 bufA[16], bufB[16];

        #define OX_LDG(buf, it) do { \
            size_t _nbase = (size_t)nb * 2048 + (it) * 64; \
            _Pragma("unroll") \
            for (int _i = 0; _i < 8; _i++) { \
                int _seg = tio + 128 * _i; \
                int _row = _seg >> 3, _part = _seg & 7; \
                const float4* _p = (const float4*)(x + xrow + (size_t)_row * HW + _nbase + _part * 8); \
                buf[2 * _i] = _p[0]; \
                buf[2 * _i + 1] = _p[1]; \
            } \
        } while (0)

        #define OX_CST(buf, it) do { \
            char* _lb = sm + 65536 + ((it) & 3) * 32768; \
            _Pragma("unroll") \
            for (int _i = 0; _i < 8; _i++) { \
                int _seg = tio + 128 * _i; \
                int _row = _seg >> 3, _part = _seg & 7; \
                unsigned _so = swz((unsigned)(_row * 128 + _part * 16)); \
                float4 _a = buf[2 * _i], _b = buf[2 * _i + 1]; \
                float _fl[8] = {_a.x, _a.y, _a.z, _a.w, _b.x, _b.y, _b.z, _b.w}; \
                conv8r(_fl, _lb + _so, _lb + 16384 + _so); \
            } \
        } while (0)

        OX_LDG(bufA, 0);
        for (int it = 0; it < 32; it += 2) {
            OX_LDG(bufB, it + 1);
            if (it >= 4) NBAR_SYNC(5 + (it & 3), 256);
            OX_CST(bufA, it);
            NBAR_ARRIVE(1 + (it & 3), 256);
            if (it + 2 < 32) OX_LDG(bufA, it + 2);
            if (it + 1 >= 4) NBAR_SYNC(5 + ((it + 1) & 3), 256);
            OX_CST(bufB, it + 1);
            NBAR_ARRIVE(1 + ((it + 1) & 3), 256);
        }
        #undef OX_LDG
        #undef OX_CST
    }
}

extern "C" void kernel_launch(void* const* d_in, const int* in_sizes, int n_in,
                              void* d_out, int out_size) {
    const float* x = (const float*)d_in[0];
    const float* gamma = (const float*)d_in[1];
    const float* bn_w = (const float*)d_in[2];
    const float* bn_b = (const float*)d_in[3];
    float* out = (float*)d_out;

    int smE = 65536 + 65536 + 4096 + 1024;    // ~133 KB
    int smS = (16384 + 1024 + 128) * 4 + 256; // ~68.8 KB
    int smO = 197632 + 1024;                  // ~194 KB
    cudaFuncSetAttribute(k_energy_mma, cudaFuncAttributeMaxDynamicSharedMemorySize, smE);
    cudaFuncSetAttribute(k_stats1, cudaFuncAttributeMaxDynamicSharedMemorySize, smS);
    cudaFuncSetAttribute(k_out_mma, cudaFuncAttributeMaxDynamicSharedMemorySize, smO);

    k_energy_mma<<<dim3(KS1, BB), 256, smE>>>(x);                 // 0
    k_redsoft<<<dim3(4, BB), 256>>>();                            // 1
    k_stats1<<<dim3(16, BB), 256, smS>>>();                       // 2
    k_out_mma<<<dim3(8, BB), 256, smO>>>(x, out, gamma, bn_w, bn_b);  // 3 (profiled)
}

// round 14
// speedup vs baseline: 3.5972x; 1.0398x over previous
#include <cuda_runtime.h>
#include <cuda_bf16.h>
#include <math.h>

#define BB 16
#define CC 128
#define HW 16384
#define KS1 8
#define KSEG (HW / KS1)  // 2048

__device__ float g_energy[BB * CC * CC];
__device__ float g_epF[BB * KS1 * CC * CC];
__device__ float g_epG[BB * KS1 * CC * CC];
__device__ float g_attn[BB * CC * CC];
__device__ float g_rspart[BB * KS1 * CC];
__device__ float g_part1[BB * CC];
__device__ float g_part2[BB * CC];

__device__ __forceinline__ unsigned smem_u32(const void* p) {
    unsigned a;
    asm("{ .reg .u64 t; cvta.to.shared.u64 t, %1; cvt.u32.u64 %0, t; }" : "=r"(a) : "l"(p));
    return a;
}
__device__ __forceinline__ unsigned swz(unsigned o) { return o ^ ((o >> 3) & 0x70); }

#define CPA(dst, src) asm volatile("cp.async.ca.shared.global [%0], [%1], 16;" :: "r"(dst), "l"(src))
#define CPA_COMMIT()  asm volatile("cp.async.commit_group;" ::: "memory")
#define CPA_WAIT0()   asm volatile("cp.async.wait_group 0;" ::: "memory")
#define CPA_WAIT1()   asm volatile("cp.async.wait_group 1;" ::: "memory")

__device__ __forceinline__ void ldsm4(unsigned a, unsigned r[4]) {
    asm volatile("ldmatrix.sync.aligned.m8n8.x4.shared.b16 {%0,%1,%2,%3}, [%4];"
                 : "=r"(r[0]), "=r"(r[1]), "=r"(r[2]), "=r"(r[3]) : "r"(a));
}
__device__ __forceinline__ void ldsm4t(unsigned a, unsigned r[4]) {
    asm volatile("ldmatrix.sync.aligned.m8n8.x4.trans.shared.b16 {%0,%1,%2,%3}, [%4];"
                 : "=r"(r[0]), "=r"(r[1]), "=r"(r[2]), "=r"(r[3]) : "r"(a));
}
__device__ __forceinline__ void mma16816(float c[4], const unsigned a[4], unsigned b0, unsigned b1) {
    asm volatile("mma.sync.aligned.m16n8k16.row.col.f32.bf16.bf16.f32 "
                 "{%0,%1,%2,%3}, {%4,%5,%6,%7}, {%8,%9}, {%0,%1,%2,%3};"
                 : "+f"(c[0]), "+f"(c[1]), "+f"(c[2]), "+f"(c[3])
                 : "r"(a[0]), "r"(a[1]), "r"(a[2]), "r"(a[3]), "r"(b0), "r"(b1));
}

// packed 2-limb bf16 split of 8 fp32 regs -> two 16B stores (bit-identical
// to per-scalar __float2bfloat16_rn)
__device__ __forceinline__ void conv8r(const float* fl, char* d0, char* d1) {
    unsigned p[4], q[4];
    #pragma unroll
    for (int k = 0; k < 4; k++) {
        float lo = fl[2 * k], hi = fl[2 * k + 1];
        unsigned pk;
        asm("cvt.rn.bf16x2.f32 %0, %1, %2;" : "=r"(pk) : "f"(hi), "f"(lo));
        float rlo = lo - __uint_as_float(pk << 16);
        float rhi = hi - __uint_as_float(pk & 0xFFFF0000u);
        unsigned qk;
        asm("cvt.rn.bf16x2.f32 %0, %1, %2;" : "=r"(qk) : "f"(rhi), "f"(rlo));
        p[k] = pk; q[k] = qk;
    }
    *(uint4*)d0 = make_uint4(p[0], p[1], p[2], p[3]);
    *(uint4*)d1 = make_uint4(q[0], q[1], q[2], q[3]);
}
__device__ __forceinline__ float conv8(const char* sp, char* d0, char* d1) {
    float4 a = ((const float4*)sp)[0];
    float4 b = ((const float4*)sp)[1];
    float fl[8] = {a.x, a.y, a.z, a.w, b.x, b.y, b.z, b.w};
    conv8r(fl, d0, d1);
    return ((fl[0] + fl[1]) + (fl[2] + fl[3])) + ((fl[4] + fl[5]) + (fl[6] + fl[7]));
}

// ---- kernel 0: energy (unchanged) -------------------------------------------
__global__ void __launch_bounds__(256) k_energy_mma(const float* __restrict__ x) {
    extern __shared__ char smraw[];
    char* sm = (char*)(((unsigned long long)smraw + 1023) & ~1023ULL);
    unsigned sb = smem_u32(sm);
    int t = threadIdx.x, lane = t & 31, wid = t >> 5;
    int ks = blockIdx.x, b = blockIdx.y;
    size_t rowbase = (size_t)b * CC * HW + (size_t)ks * KSEG;
    int wm = (wid >> 2) * 64, wn = (wid & 3) * 32;
    float* s_rs = (float*)(sm + 131072);
    float rsacc[4] = {0.f, 0.f, 0.f, 0.f};

    float accF[4][4][4], accG[4][4][4];
    #pragma unroll
    for (int mt = 0; mt < 4; mt++)
        #pragma unroll
        for (int nt = 0; nt < 4; nt++)
            #pragma unroll
            for (int c = 0; c < 4; c++) { accF[mt][nt][c] = 0.f; accG[mt][nt][c] = 0.f; }

    #define X_LOAD(ch) do { \
        unsigned _db = sb + ((ch) & 1) * 32768; \
        _Pragma("unroll") \
        for (int _i = 0; _i < 4; _i++) { \
            int _seg = t + 256 * _i; \
            int _row = _seg >> 3, _part = _seg & 7; \
            const float* _s = x + rowbase + (size_t)_row * HW + (ch) * 64 + _part * 8; \
            CPA(_db + _row * 256 + _part * 32, _s); \
            CPA(_db + _row * 256 + _part * 32 + 16, _s + 4); \
        } \
        CPA_COMMIT(); \
    } while (0)

    #define X_CONV(ch) do { \
        char* _st = sm + ((ch) & 1) * 32768; \
        char* _lb = sm + 65536 + ((ch) & 1) * 32768; \
        _Pragma("unroll") \
        for (int _i = 0; _i < 4; _i++) { \
            int _seg = t + 256 * _i; \
            int _row = _seg >> 3, _part = _seg & 7; \
            unsigned _so = swz((unsigned)(_row * 128 + _part * 16)); \
            rsacc[_i] += conv8(_st + _row * 256 + _part * 32, _lb + _so, _lb + 16384 + _so); \
        } \
    } while (0)

    X_LOAD(0);
    X_LOAD(1);
    CPA_WAIT1();
    X_CONV(0);
    __syncthreads();

    for (int ch = 0; ch < 32; ch++) {
        if (ch + 2 < 32) X_LOAD(ch + 2);

        unsigned b0t = sb + 65536 + (ch & 1) * 32768;
        unsigned b1t = b0t + 16384;
        #pragma unroll
        for (int kk = 0; kk < 4; kk++) {
            int kbyte = kk * 32;
            unsigned A[4][4];
            #pragma unroll
            for (int mt = 0; mt < 4; mt++) {
                unsigned off = swz((unsigned)((wm + mt * 16 + (lane & 15)) * 128 + kbyte + (lane >> 4) * 16));
                ldsm4(b0t + off, A[mt]);
            }
            unsigned B0[2][4], B1[2][4];
            #pragma unroll
            for (int nt = 0; nt < 2; nt++) {
                int row = wn + nt * 16 + ((lane >> 4) & 1) * 8 + (lane & 7);
                int kb = kbyte + ((lane >> 3) & 1) * 16;
                unsigned off = swz((unsigned)(row * 128 + kb));
                ldsm4(b0t + off, B0[nt]);
                ldsm4(b1t + off, B1[nt]);
            }
            #pragma unroll
            for (int mt = 0; mt < 4; mt++)
                #pragma unroll
                for (int nt = 0; nt < 2; nt++)
                    #pragma unroll
                    for (int s = 0; s < 2; s++) {
                        mma16816(accF[mt][nt * 2 + s], A[mt], B0[nt][s * 2], B0[nt][s * 2 + 1]);
                        mma16816(accG[mt][nt * 2 + s], A[mt], B1[nt][s * 2], B1[nt][s * 2 + 1]);
                    }
        }

        if (ch + 1 < 32) {
            if (ch + 2 < 32) CPA_WAIT1(); else CPA_WAIT0();
            X_CONV(ch + 1);
        }
        __syncthreads();
    }
    #undef X_LOAD
    #undef X_CONV

    #pragma unroll
    for (int i = 0; i < 4; i++) s_rs[t + 256 * i] = rsacc[i];
    __syncthreads();
    if (t < 128) {
        float s = 0.f;
        #pragma unroll
        for (int k = 0; k < 8; k++) s += s_rs[t * 8 + k];
        g_rspart[(b * KS1 + ks) * CC + t] = s;
    }

    size_t pbase = ((size_t)(b * KS1 + ks)) * CC * CC;
    int g = lane >> 2, tg = lane & 3;
    #pragma unroll
    for (int mt = 0; mt < 4; mt++)
        #pragma unroll
        for (int nt = 0; nt < 4; nt++) {
            int i0 = wm + mt * 16 + g, j = wn + nt * 8 + tg * 2;
            *(float2*)(g_epF + pbase + (size_t)i0 * CC + j) = make_float2(accF[mt][nt][0], accF[mt][nt][1]);
            *(float2*)(g_epF + pbase + (size_t)(i0 + 8) * CC + j) = make_float2(accF[mt][nt][2], accF[mt][nt][3]);
            *(float2*)(g_epG + pbase + (size_t)i0 * CC + j) = make_float2(accG[mt][nt][0], accG[mt][nt][1]);
            *(float2*)(g_epG + pbase + (size_t)(i0 + 8) * CC + j) = make_float2(accG[mt][nt][2], accG[mt][nt][3]);
        }
}

// ---- kernel 1: fused E = F + G + G^T  AND softmax ---------------------------
__global__ void k_redsoft() {
    int islab = blockIdx.x, b = blockIdx.y, t = threadIdx.x;
    __shared__ float sGT[32][132];
    #pragma unroll
    for (int r = 0; r < 4; r++) {
        int idx = t + 256 * r;
        int j = idx >> 3, c4 = idx & 7;
        float4 s = make_float4(0.f, 0.f, 0.f, 0.f);
        #pragma unroll
        for (int ks = 0; ks < KS1; ks++) {
            float4 v = *(const float4*)(g_epG + (((size_t)(b * KS1 + ks) * CC + j)) * CC + islab * 32 + c4 * 4);
            s.x += v.x; s.y += v.y; s.z += v.z; s.w += v.w;
        }
        sGT[c4 * 4 + 0][j] = s.x;
        sGT[c4 * 4 + 1][j] = s.y;
        sGT[c4 * 4 + 2][j] = s.z;
        sGT[c4 * 4 + 3][j] = s.w;
    }
    __syncthreads();
    #pragma unroll
    for (int r = 0; r < 4; r++) {
        int idx = t + 256 * r;
        int il = idx >> 5, j4 = idx & 31;
        int i = islab * 32 + il;
        float4 f = make_float4(0.f, 0.f, 0.f, 0.f);
        #pragma unroll
        for (int ks = 0; ks < KS1; ks++) {
            size_t o = (((size_t)(b * KS1 + ks) * CC + i)) * CC + j4 * 4;
            float4 vf = *(const float4*)(g_epF + o);
            float4 vg = *(const float4*)(g_epG + o);
            f.x += vf.x + vg.x; f.y += vf.y + vg.y; f.z += vf.z + vg.z; f.w += vf.w + vg.w;
        }
        float4 gt = *(const float4*)&sGT[il][j4 * 4];
        float4 e = make_float4(f.x + gt.x, f.y + gt.y, f.z + gt.z, f.w + gt.w);
        *(float4*)(g_energy + ((size_t)(b * CC + i)) * CC + j4 * 4) = e;
        float mx = fmaxf(fmaxf(e.x, e.y), fmaxf(e.z, e.w));
        #pragma unroll
        for (int o = 16; o; o >>= 1) mx = fmaxf(mx, __shfl_xor_sync(0xffffffffu, mx, o));
        float e0 = mx - e.x, e1 = mx - e.y, e2 = mx - e.z, e3 = mx - e.w;
        float m2 = fmaxf(fmaxf(e0, e1), fmaxf(e2, e3));
        #pragma unroll
        for (int o = 16; o; o >>= 1) m2 = fmaxf(m2, __shfl_xor_sync(0xffffffffu, m2, o));
        float p0 = expf(e0 - m2), p1 = expf(e1 - m2), p2 = expf(e2 - m2), p3 = expf(e3 - m2);
        float s = (p0 + p1) + (p2 + p3);
        #pragma unroll
        for (int o = 16; o; o >>= 1) s += __shfl_xor_sync(0xffffffffu, s, o);
        float inv = 1.f / s;
        *(float4*)(g_attn + ((size_t)(b * CC + i)) * CC + j4 * 4) =
            make_float4(p0 * inv, p1 * inv, p2 * inv, p3 * inv);
    }
}

// ---- kernel 2: BN stats partials (rowsum fused from rspart) -----------------
__global__ void __launch_bounds__(256) k_stats1() {
    int cs = blockIdx.x, b = blockIdx.y, t = threadIdx.x, lane = t & 31, w = t >> 5;
    extern __shared__ float sms[];
    float* sE = sms;
    float* sA = sms + 16384;
    float* sR = sms + 16384 + 1024;
    const float4* Eg = (const float4*)(g_energy + (size_t)b * CC * CC);
    for (int i = t; i < 4096; i += 256) ((float4*)sE)[i] = Eg[i];
    const float4* Ag = (const float4*)(g_attn + ((size_t)b * CC + cs * 8) * CC);
    if (t < 256) ((float4*)sA)[t] = Ag[t];
    if (t < 128) {
        float s = 0.f;
        #pragma unroll
        for (int ks = 0; ks < KS1; ks++) s += g_rspart[(b * KS1 + ks) * CC + t];
        sR[t] = s;
    }
    __syncthreads();

    float accT[4] = {0.f, 0.f, 0.f, 0.f};
    for (int k = 0; k < 128; k++) {
        float4 e = *(float4*)&sE[k * 128 + lane * 4];
        float a = sA[w * 128 + k];
        accT[0] += a * e.x; accT[1] += a * e.y;
        accT[2] += a * e.z; accT[3] += a * e.w;
    }
    float4 r4 = *(float4*)&sR[lane * 4];
    float4 a4 = *(float4*)&sA[w * 128 + lane * 4];
    float l2 = accT[0] * a4.x + accT[1] * a4.y + accT[2] * a4.z + accT[3] * a4.w;
    float l1 = r4.x * a4.x + r4.y * a4.y + r4.z * a4.z + r4.w * a4.w;
    #pragma unroll
    for (int o = 16; o; o >>= 1) {
        l1 += __shfl_xor_sync(0xffffffffu, l1, o);
        l2 += __shfl_xor_sync(0xffffffffu, l2, o);
    }
    if (lane == 0) {
        g_part1[b * CC + cs * 8 + w] = l1;
        g_part2[b * CC + cs * 8 + w] = l2;
    }
}

// ---- kernel 3: out GEMM — uniform 8-warp schema (energy-style) --------------
// All warps MMA + convert. Warp tile 32x32 (4m x 2n). LDG->regs->conv->STS,
// conv issued after MMA batch; one __syncthreads per iter.
// smem: A limbs 4x16K @0 | limb ring 2x32K @65536 | s_scale @131072 | s_shift @131584
__global__ void __launch_bounds__(256) k_out_mma(const float* __restrict__ x,
                                                 float* __restrict__ out,
                                                 const float* __restrict__ gamma,
                                                 const float* __restrict__ bn_w,
                                                 const float* __restrict__ bn_b) {
    extern __shared__ char smraw[];
    char* sm = (char*)(((unsigned long long)smraw + 1023) & ~1023ULL);
    unsigned sb = smem_u32(sm);
    int t = threadIdx.x, lane = t & 31, wid = t >> 5;
    int nb = blockIdx.x, b = blockIdx.y;  // nb: 8 chunks of 2048 cols
    size_t xrow = (size_t)b * CC * HW;
    float* s_scale = (float*)(sm + 131072);
    float* s_shift = (float*)(sm + 131584);
    int wm = (wid >> 1) * 32, wn = (wid & 1) * 32;
    int g = lane >> 2, tg = lane & 3;

    // ---- prologue: scale/shift (fused stats2) ----
    if (t < 128) {
        float a1 = 0.f, a2 = 0.f;
        #pragma unroll
        for (int bb = 0; bb < BB; bb++) { a1 += g_part1[bb * CC + t]; a2 += g_part2[bb * CC + t]; }
        float gg = gamma[0];
        float invN = 1.f / (float)((size_t)BB * HW);
        float mean = gg * a1 * invN;
        float ey2 = gg * gg * a2 * invN;
        float rstd = rsqrtf(ey2 - mean * mean + 1e-5f);
        float w = bn_w[t];
        s_scale[t] = gg * rstd * w;
        s_shift[t] = bn_b[t] - mean * rstd * w;
    }
    __syncthreads();
    // ---- prologue: attn -> A limb tiles ----
    #pragma unroll
    for (int i2 = 0; i2 < 8; i2++) {
        int seg = t + 256 * i2;
        int row = seg >> 4, jp = seg & 15;
        int jhalf = jp >> 3, part = jp & 7;
        const float4* ap = (const float4*)(g_attn + ((size_t)(b * CC + row)) * CC + jp * 8);
        float4 v0 = ap[0], v1 = ap[1];
        float sc = s_scale[row];
        float fl[8] = {v0.x * sc, v0.y * sc, v0.z * sc, v0.w * sc,
                       v1.x * sc, v1.y * sc, v1.z * sc, v1.w * sc};
        unsigned so = swz((unsigned)(row * 128 + part * 16));
        conv8r(fl, sm + jhalf * 16384 + so, sm + (2 + jhalf) * 16384 + so);
    }
    __syncthreads();

    // hoist A limb0 fragments (64 regs)
    unsigned A0h[8][2][4];
    #pragma unroll
    for (int ksp = 0; ksp < 8; ksp++) {
        int jhalf = ksp >> 2;
        unsigned kb = (unsigned)((ksp & 3) * 32 + (lane >> 4) * 16);
        #pragma unroll
        for (int mt = 0; mt < 2; mt++) {
            unsigned off = swz((unsigned)((wm + mt * 16 + (lane & 15)) * 128) + kb);
            ldsm4(sb + jhalf * 16384 + off, A0h[ksp][mt]);
        }
    }

    // X chunk helpers: 128 rows x 64 cols fp32; thread handles 4 segs of 8 floats
    float4 buf[8];
    #define OX_LDG(it) do { \
        size_t _nbase = (size_t)nb * 2048 + (it) * 64; \
        _Pragma("unroll") \
        for (int _i = 0; _i < 4; _i++) { \
            int _seg = t + 256 * _i; \
            int _row = _seg >> 3, _part = _seg & 7; \
            const float4* _p = (const float4*)(x + xrow + (size_t)_row * HW + _nbase + _part * 8); \
            buf[2 * _i] = _p[0]; \
            buf[2 * _i + 1] = _p[1]; \
        } \
    } while (0)
    #define OX_CST(it) do { \
        char* _lb = sm + 65536 + ((it) & 1) * 32768; \
        _Pragma("unroll") \
        for (int _i = 0; _i < 4; _i++) { \
            int _seg = t + 256 * _i; \
            int _row = _seg >> 3, _part = _seg & 7; \
            unsigned _so = swz((unsigned)(_row * 128 + _part * 16)); \
            float4 _a = buf[2 * _i], _b = buf[2 * _i + 1]; \
            float _fl[8] = {_a.x, _a.y, _a.z, _a.w, _b.x, _b.y, _b.z, _b.w}; \
            conv8r(_fl, _lb + _so, _lb + 16384 + _so); \
        } \
    } while (0)

    OX_LDG(0);
    OX_CST(0);          // slot 0
    OX_LDG(1);          // chunk 1 in regs
    __syncthreads();    // slot 0 visible

    for (int it = 0; it < 32; it++) {
        int slot = it & 1;
        size_t gx = xrow + (size_t)nb * 2048 + it * 64;

        // prefetch x for epilogue (latency hidden under MMA)
        float2 xp0[2][4], xp1[2][4];
        #pragma unroll
        for (int mt = 0; mt < 2; mt++) {
            int i0 = wm + mt * 16 + g;
            #pragma unroll
            for (int nf = 0; nf < 4; nf++) {
                int col = wn + nf * 8 + tg * 2;
                xp0[mt][nf] = *(const float2*)(x + gx + (size_t)i0 * HW + col);
                xp1[mt][nf] = *(const float2*)(x + gx + (size_t)(i0 + 8) * HW + col);
            }
        }

        float acc[2][4][4];
        #pragma unroll
        for (int mt = 0; mt < 2; mt++)
            #pragma unroll
            for (int nf = 0; nf < 4; nf++)
                #pragma unroll
                for (int c = 0; c < 4; c++) acc[mt][nf][c] = 0.f;

        unsigned Bt0 = sb + 65536 + slot * 32768;
        unsigned Bt1 = Bt0 + 16384;
        #pragma unroll
        for (int ksp = 0; ksp < 8; ksp++) {
            unsigned A1t[2][4];
            {
                int jhalf = ksp >> 2;
                unsigned kb = (unsigned)((ksp & 3) * 32 + (lane >> 4) * 16);
                #pragma unroll
                for (int mt = 0; mt < 2; mt++) {
                    unsigned off = swz((unsigned)((wm + mt * 16 + (lane & 15)) * 128) + kb);
                    ldsm4(sb + (2 + jhalf) * 16384 + off, A1t[mt]);
                }
            }
            int jrow = ksp * 16 + ((lane >> 3) & 1) * 8 + (lane & 7);
            #pragma unroll
            for (int f = 0; f < 2; f++) {
                int ncol = wn + f * 16 + ((lane >> 4) & 1) * 8;
                unsigned offb = swz((unsigned)(jrow * 128 + ncol * 2));
                unsigned B0[4], B1[4];
                ldsm4t(Bt0 + offb, B0);
                ldsm4t(Bt1 + offb, B1);
                #pragma unroll
                for (int mt = 0; mt < 2; mt++)
                    #pragma unroll
                    for (int s = 0; s < 2; s++) {
                        float* c = acc[mt][f * 2 + s];
                        mma16816(c, A0h[ksp][mt], B0[s * 2], B0[s * 2 + 1]);
                        mma16816(c, A0h[ksp][mt], B1[s * 2], B1[s * 2 + 1]);
                        mma16816(c, A1t[mt], B0[s * 2], B0[s * 2 + 1]);
                    }
            }
        }

        // convert next chunk (overlaps in-flight HMMAs), then prefetch chunk it+2
        if (it + 1 < 32) OX_CST(it + 1);
        if (it + 2 < 32) OX_LDG(it + 2);

        // epilogue: acc + shift + x, direct stores
        #pragma unroll
        for (int mt = 0; mt < 2; mt++) {
            int i0 = wm + mt * 16 + g;
            float sh0 = s_shift[i0], sh1 = s_shift[i0 + 8];
            #pragma unroll
            for (int nf = 0; nf < 4; nf++) {
                int col = wn + nf * 8 + tg * 2;
                *(float2*)(out + gx + (size_t)i0 * HW + col) =
                    make_float2(acc[mt][nf][0] + sh0 + xp0[mt][nf].x,
                                acc[mt][nf][1] + sh0 + xp0[mt][nf].y);
                *(float2*)(out + gx + (size_t)(i0 + 8) * HW + col) =
                    make_float2(acc[mt][nf][2] + sh1 + xp1[mt][nf].x,
                                acc[mt][nf][3] + sh1 + xp1[mt][nf].y);
            }
        }
        __syncthreads();  // limbs(it+1) ready; slot `it&1` reusable next iter
    }
    #undef OX_LDG
    #undef OX_CST
}

extern "C" void kernel_launch(void* const* d_in, const int* in_sizes, int n_in,
                              void* d_out, int out_size) {
    const float* x = (const float*)d_in[0];
    const float* gamma = (const float*)d_in[1];
    const float* bn_w = (const float*)d_in[2];
    const float* bn_b = (const float*)d_in[3];
    float* out = (float*)d_out;

    int smE = 65536 + 65536 + 4096 + 1024;    // ~133 KB
    int smS = (16384 + 1024 + 128) * 4 + 256; // ~68.8 KB
    int smO = 131072 + 1024 + 1024;           // ~130 KB
    cudaFuncSetAttribute(k_energy_mma, cudaFuncAttributeMaxDynamicSharedMemorySize, smE);
    cudaFuncSetAttribute(k_stats1, cudaFuncAttributeMaxDynamicSharedMemorySize, smS);
    cudaFuncSetAttribute(k_out_mma, cudaFuncAttributeMaxDynamicSharedMemorySize, smO);

    k_energy_mma<<<dim3(KS1, BB), 256, smE>>>(x);                 // 0
    k_redsoft<<<dim3(4, BB), 256>>>();                            // 1
    k_stats1<<<dim3(16, BB), 256, smS>>>();                       // 2
    k_out_mma<<<dim3(8, BB), 256, smO>>>(x, out, gamma, bn_w, bn_b);  // 3 (profiled)
}